// round 12
// baseline (speedup 1.0000x reference)
#include <cuda_runtime.h>
#include <math.h>
#include <stddef.h>
#include <stdint.h>
#include <string.h>

// ---------------- static scratch (no allocations allowed) ----------------
__device__ float g_in  [(size_t)32*512*128];          // (n, t, c)
__device__ float g_c1  [(size_t)32*508*124*16];       // NHWC
__device__ float g_c2  [(size_t)32*504*120*32];       // NHWC
__device__ float g_c3  [(size_t)32*500*116*64];       // NHWC
__device__ float g_pool[(size_t)32*64*496*58];        // (n, c, s, w) raw reshape layout
__device__ float g_x1  [(size_t)32*496*64];
__device__ float g_gi  [(size_t)32*496*192];
__device__ float g_hs  [(size_t)32*496*64];           // E (n<16) / Tm (n>=16)
__device__ float g_Tp  [(size_t)16*496*64];
__device__ float g_wt2 [(size_t)5*80*32];             // conv2 weights [dy][k8][co][pos]
__device__ float g_wt3 [(size_t)5*160*64];            // conv3 weights [dy][k8][co][pos]
__device__ float g_mx  [16*512];                      // column softmax stats
__device__ float g_iv  [16*512];

__device__ __forceinline__ uint32_t f2tf32(float x)
{
    uint32_t u;
    asm("cvt.rna.tf32.f32 %0, %1;" : "=r"(u) : "f"(x));
    return u;
}

__device__ __forceinline__ unsigned long long fma2(unsigned long long a,
                                                   unsigned long long b,
                                                   unsigned long long c)
{
    unsigned long long d;
    asm("fma.rn.f32x2 %0, %1, %2, %3;" : "=l"(d) : "l"(a), "l"(b), "l"(c));
    return d;
}

__device__ __forceinline__ unsigned long long pack2(float x, float y)
{
    unsigned long long d;
    asm("mov.b64 %0, {%1, %2};" : "=l"(d) : "f"(x), "f"(y));
    return d;
}

__device__ __forceinline__ void unpack2(unsigned long long v, float& x, float& y)
{
    asm("mov.b64 {%0, %1}, %2;" : "=f"(x), "=f"(y) : "l"(v));
}

// ---------------- prep: transpose (z<32) + weight reorders (z==32) ----------------
// B layout (R9): [dy][k>>3][co][pos(k&7)], pos(j) = 2*(j&3) + (j>>2)
__global__ void prep_kernel(const float* __restrict__ ev, const float* __restrict__ tm,
                            const float* __restrict__ c2w, const float* __restrict__ c3w,
                            float* __restrict__ out, float* __restrict__ wt2,
                            float* __restrict__ wt3)
{
    if (blockIdx.z < 32) {
        __shared__ float tile[32][33];
        int n = blockIdx.z;
        const float* src = (n < 16) ? (ev + (size_t)n * 128 * 512)
                                    : (tm + (size_t)(n - 16) * 128 * 512);
        int x0 = blockIdx.x * 32;
        int y0 = blockIdx.y * 32;
        int lx = threadIdx.x, ly = threadIdx.y; // 32 x 8
        for (int r = ly; r < 32; r += 8)
            tile[r][lx] = src[(size_t)(x0 + r) * 512 + y0 + lx];
        __syncthreads();
        float* o = out + (size_t)n * 512 * 128;
        for (int r = ly; r < 32; r += 8)
            o[(size_t)(y0 + r) * 128 + x0 + lx] = tile[lx][r];
    } else {
        int pid = (blockIdx.y * 4 + blockIdx.x) * 256 + threadIdx.y * 32 + threadIdx.x;
        for (int idx = pid; idx < 12800; idx += 16384) {   // conv2: CIN=16, COUT=32
            int dx = idx % 5, dy = (idx / 5) % 5, ci = (idx / 25) % 16, co = idx / 400;
            int k = dx * 16 + ci;
            int j = k & 7;
            int pos = 2 * (j & 3) + (j >> 2);
            wt2[(size_t)dy * (80 * 32) + (k >> 3) * 256 + co * 8 + pos] =
                __uint_as_float(f2tf32(c2w[idx]));
        }
        for (int idx = pid; idx < 51200; idx += 16384) {   // conv3: CIN=32, COUT=64
            int dx = idx % 5, dy = (idx / 5) % 5, ci = (idx / 25) % 32, co = idx / 800;
            int k = dx * 32 + ci;
            int j = k & 7;
            int pos = 2 * (j & 3) + (j >> 2);
            wt3[(size_t)dy * (160 * 64) + (k >> 3) * 512 + co * 8 + pos] =
                __uint_as_float(f2tf32(c3w[idx]));
        }
    }
}

// ---------------- conv1: CIN=1, direct fp32, NHWC out ----------------
__global__ void conv1_nhwc(const float* __restrict__ in, const float* __restrict__ w,
                           const float* __restrict__ bias, float* __restrict__ out)
{
    __shared__ float srow[5][128];
    __shared__ float sw[16][25];
    __shared__ float sb[16];
    int y = blockIdx.x, n = blockIdx.y, tid = threadIdx.x;  // 128 threads
    const float* ip = in + ((size_t)n * 512 + y) * 128;
#pragma unroll
    for (int r = 0; r < 5; r++) srow[r][tid] = ip[(size_t)r * 128 + tid];
    if (tid < 16) sb[tid] = bias[tid];
    for (int e = tid; e < 400; e += 128) sw[e / 25][e % 25] = w[e];
    __syncthreads();
    if (tid >= 124) return;
    float acc[16];
#pragma unroll
    for (int co = 0; co < 16; co++) acc[co] = sb[co];
#pragma unroll
    for (int dy = 0; dy < 5; dy++) {
#pragma unroll
        for (int dx = 0; dx < 5; dx++) {
            float v = srow[dy][tid + dx];
#pragma unroll
            for (int co = 0; co < 16; co++) acc[co] += v * sw[co][dy * 5 + dx];
        }
    }
    float4* op = (float4*)(out + (((size_t)n * 508 + y) * 124 + tid) * 16);
#pragma unroll
    for (int q = 0; q < 4; q++) {
        float4 v; v.x = acc[q*4]; v.y = acc[q*4+1]; v.z = acc[q*4+2]; v.w = acc[q*4+3];
        op[q] = v;
    }
}

// ---------------- implicit-GEMM conv (R9): ldmatrix A-frags, paired-B LDS.64 ---------
template<int CIN, int COUT, int HIN, int WIN>
__global__ __launch_bounds__(512) void conv_mma2(const float* __restrict__ in,
                                                 const float* __restrict__ wt,
                                                 const float* __restrict__ bias,
                                                 float* __restrict__ out)
{
    constexpr int HOUT = HIN - 4, WOUT = WIN - 4;
    constexpr int ROWF = 132 * CIN;
    constexpr int KDY = 5 * CIN;
    constexpr int BSZ = KDY * COUT;
    constexpr int A_SHIFT = (CIN == 32) ? 5 : 4;
    constexpr int MI = (COUT == 64) ? 4 : 2;

    extern __shared__ float smem[];
    float* sA = smem;                 // 8 rows x ROWF
    float* sB = smem + 8 * ROWF;      // 2 x BSZ (double buffer, contiguous layout)
    uint32_t* sAu = (uint32_t*)sA;

    int tid = threadIdx.x;
    int lane = tid & 31, warp = tid >> 5;   // 16 warps
    int y0 = blockIdx.x * 4, n = blockIdx.y;
    int wy = warp >> 2;
    int wsub = warp & 3;
    int mrow, nbase;
    if (COUT == 64) { mrow = (wsub & 1) * 64; nbase = (wsub >> 1) * 32; }
    else            { mrow = wsub * 32;       nbase = 0; }

    int ra = lane >> 2;
    int kfrac = lane & 3;
    int cidx[4];
#pragma unroll
    for (int nj = 0; nj < 4; nj++)
        cidx[nj] = (nbase + nj * 8 + ra) * 4 + kfrac;

    int lrow = lane & 15;
    int lcol = (lane >> 4) * 4;
    int linv[MI];
#pragma unroll
    for (int mi = 0; mi < MI; mi++)
        linv[mi] = (mrow + mi * 16 + lrow) * CIN + lcol;

    uint32_t sA_sh = (uint32_t)__cvta_generic_to_shared(sAu);

    float acc[MI][4][4];
#pragma unroll
    for (int mi = 0; mi < MI; mi++)
#pragma unroll
        for (int nj = 0; nj < 4; nj++)
#pragma unroll
            for (int q = 0; q < 4; q++) acc[mi][nj][q] = 0.f;

    // ---- stage all 8 input rows once (tf32, per-row swizzle) ----
    const int WVALID = WIN * CIN;
    for (int l = tid * 4; l < 8 * ROWF; l += 2048) {
        int rr = l / ROWF, lo = l % ROWF;
        const float* inrow = in + ((size_t)(n * HIN + y0 + rr) * WIN) * CIN;
        float4 v;
        if (lo + 4 <= WVALID) v = *(const float4*)(inrow + lo);
        else { v.x = v.y = v.z = v.w = 0.f; }
        uint4 u;
        u.x = f2tf32(v.x); u.y = f2tf32(v.y); u.z = f2tf32(v.z); u.w = f2tf32(v.w);
        int p = lo ^ (((lo >> A_SHIFT) & 7) << 2);
        *(uint4*)(sAu + rr * ROWF + p) = u;
    }

    // ---- prefetch B[0] via cp.async ----
    for (int l = tid * 4; l < BSZ; l += 2048) {
        uint32_t da = (uint32_t)__cvta_generic_to_shared(sB + l);
        asm volatile("cp.async.ca.shared.global [%0], [%1], 16;\n"
                     :: "r"(da), "l"(wt + l));
    }
    asm volatile("cp.async.commit_group;\n");
    asm volatile("cp.async.wait_group 0;\n");
    __syncthreads();

#pragma unroll 1
    for (int dy = 0; dy < 5; dy++) {
        if (dy < 4) {
            const float* wrow = wt + (size_t)(dy + 1) * BSZ;
            float* dst = sB + ((dy + 1) & 1) * BSZ;
            for (int l = tid * 4; l < BSZ; l += 2048) {
                uint32_t da = (uint32_t)__cvta_generic_to_shared(dst + l);
                asm volatile("cp.async.ca.shared.global [%0], [%1], 16;\n"
                             :: "r"(da), "l"(wrow + l));
            }
            asm volatile("cp.async.commit_group;\n");
        }
        const float2* sB2 = (const float2*)(sB + (dy & 1) * BSZ);

        int abase = (wy + dy) * ROWF;
#pragma unroll
        for (int k8 = 0; k8 < KDY; k8 += 8) {
            uint32_t a[MI][4];
#pragma unroll
            for (int mi = 0; mi < MI; mi++) {
                int l0 = linv[mi] + k8;
                int p = l0 ^ (((l0 >> A_SHIFT) & 7) << 2);
                uint32_t addr = sA_sh + (uint32_t)(abase + p) * 4u;
                asm volatile(
                    "ldmatrix.sync.aligned.m8n8.x4.shared.b16 {%0,%1,%2,%3}, [%4];"
                    : "=r"(a[mi][0]), "=r"(a[mi][1]), "=r"(a[mi][2]), "=r"(a[mi][3])
                    : "r"(addr));
            }
            const float2* pb = sB2 + (k8 >> 3) * (4 * COUT);
#pragma unroll
            for (int nj = 0; nj < 4; nj++) {
                float2 bb = pb[cidx[nj]];
                uint32_t b0 = __float_as_uint(bb.x);
                uint32_t b1 = __float_as_uint(bb.y);
#pragma unroll
                for (int mi = 0; mi < MI; mi++) {
                    asm volatile(
                        "mma.sync.aligned.m16n8k8.row.col.f32.tf32.tf32.f32 "
                        "{%0,%1,%2,%3}, {%4,%5,%6,%7}, {%8,%9}, {%0,%1,%2,%3};"
                        : "+f"(acc[mi][nj][0]), "+f"(acc[mi][nj][1]),
                          "+f"(acc[mi][nj][2]), "+f"(acc[mi][nj][3])
                        : "r"(a[mi][0]), "r"(a[mi][1]), "r"(a[mi][2]), "r"(a[mi][3]),
                          "r"(b0), "r"(b1));
                }
            }
        }
        if (dy < 4) {
            asm volatile("cp.async.wait_group 0;\n");
            __syncthreads();
        }
    }

    int y = y0 + wy;
    size_t obase = ((size_t)(n * HOUT + y) * WOUT) * COUT;
#pragma unroll
    for (int mi = 0; mi < MI; mi++) {
#pragma unroll
        for (int nj = 0; nj < 4; nj++) {
            int x = mrow + mi * 16 + ra;
            int co = nbase + nj * 8 + kfrac * 2;
            float b0 = bias[co], b1 = bias[co + 1];
            if (x < WOUT) {
                float2 v; v.x = acc[mi][nj][0] + b0; v.y = acc[mi][nj][1] + b1;
                *(float2*)(out + obase + (size_t)x * COUT + co) = v;
            }
            if (x + 8 < WOUT) {
                float2 v; v.x = acc[mi][nj][2] + b0; v.y = acc[mi][nj][3] + b1;
                *(float2*)(out + obase + (size_t)(x + 8) * COUT + co) = v;
            }
        }
    }
}

// ---------------- maxpool ring: each conv3 row read once ----------------
__global__ void pool_ring(const float* __restrict__ in, float* __restrict__ out)
{
    extern __shared__ float ring[];   // 5 x (58*67)
    const int RP = 58 * 67;
    int strip = blockIdx.x, n = blockIdx.y, tid = threadIdx.x; // 256 threads
    int s0 = strip * 62;
    float* ob = out + (size_t)n * 64 * 496 * 58;
    for (int y = s0; y < s0 + 66; y++) {
        const float* ip = in + ((size_t)(n * 500 + y) * 116) * 64;
        int rr = (y - s0) % 5;
        for (int idx = tid; idx < 3712; idx += 256) {
            int wp = idx >> 6, c = idx & 63;
            float a = ip[(size_t)(2 * wp) * 64 + c];
            float b = ip[(size_t)(2 * wp) * 64 + 64 + c];
            ring[rr * RP + wp * 67 + c] = fmaxf(a, b);
        }
        __syncthreads();
        if (y - s0 >= 4) {
            int s = y - 4;
            for (int f = tid; f < 3712; f += 256) {
                int c = f / 58, wp = f % 58;
                int o = wp * 67 + c;
                float m = ring[o];
                m = fmaxf(m, ring[RP + o]);
                m = fmaxf(m, ring[2 * RP + o]);
                m = fmaxf(m, ring[3 * RP + o]);
                m = fmaxf(m, ring[4 * RP + o]);
                ob[(size_t)c * 496 * 58 + (size_t)s * 58 + wp] = m;
            }
        }
        __syncthreads();
    }
}

// ------- tiled SIMT GEMM, packed-A smem + f32x2 inner loop (exact fp32) -------
template<bool WT>
__global__ void gemm_bias(const float* __restrict__ A, const float* __restrict__ Bm,
                          const float* __restrict__ bias, float* __restrict__ C,
                          int M, int N, int K, long sA, long sB, long sC)
{
    A  += (long)blockIdx.z * sA;
    Bm += (long)blockIdx.z * sB;
    C  += (long)blockIdx.z * sC;
    __shared__ __align__(16) unsigned long long sAd[64][17];  // (a,a) duplicated
    __shared__ __align__(16) float sBi[16][68];
    int tid = threadIdx.x;          // 128
    int ttx = tid & 15, tty = tid >> 4;
    int m0 = blockIdx.x * 64, n0 = blockIdx.y * 64;
    unsigned long long acc2[8][2];
#pragma unroll
    for (int i = 0; i < 8; i++) { acc2[i][0] = 0ull; acc2[i][1] = 0ull; }

    for (int k0 = 0; k0 < K; k0 += 16) {
#pragma unroll
        for (int l = 0; l < 8; l++) {
            int e = tid + l * 128;
            int mm = e >> 4, kk = e & 15;
            int m = m0 + mm;
            float v = (m < M) ? A[(long)m * K + k0 + kk] : 0.f;
            sAd[mm][kk] = pack2(v, v);
        }
#pragma unroll
        for (int l = 0; l < 8; l++) {
            int e = tid + l * 128;
            if (WT) {
                int j = e >> 4, kk = e & 15;
                int jn = n0 + j;
                sBi[kk][j] = (jn < N) ? Bm[(long)jn * K + k0 + kk] : 0.f;
            } else {
                int kk = e >> 6, j = e & 63;
                int jn = n0 + j;
                sBi[kk][j] = (jn < N) ? Bm[(long)(k0 + kk) * N + jn] : 0.f;
            }
        }
        __syncthreads();
#pragma unroll
        for (int kk = 0; kk < 16; kk++) {
            unsigned long long b0 = *(const unsigned long long*)&sBi[kk][ttx * 4];
            unsigned long long b1 = *(const unsigned long long*)&sBi[kk][ttx * 4 + 2];
#pragma unroll
            for (int i = 0; i < 8; i++) {
                unsigned long long ap = sAd[tty * 8 + i][kk];
                acc2[i][0] = fma2(ap, b0, acc2[i][0]);
                acc2[i][1] = fma2(ap, b1, acc2[i][1]);
            }
        }
        __syncthreads();
    }
#pragma unroll
    for (int i = 0; i < 8; i++) {
        int m = m0 + tty * 8 + i;
        if (m < M) {
            int j0 = n0 + ttx * 4;
            float4 v;
            unpack2(acc2[i][0], v.x, v.y);
            unpack2(acc2[i][1], v.z, v.w);
            v.x += bias ? bias[j0 + 0] : 0.f;
            v.y += bias ? bias[j0 + 1] : 0.f;
            v.z += bias ? bias[j0 + 2] : 0.f;
            v.w += bias ? bias[j0 + 3] : 0.f;
            *(float4*)&C[(long)m * N + j0] = v;
        }
    }
}

// ------- GRU v4: 384 thr, split dot (lane pairs), fast activations, 2 barriers -------
// row = tid>>1 (0..191), half = tid&1 owns h[half*32 .. half*32+31].
__global__ __launch_bounds__(384) void gru_kernel(const float* __restrict__ gi,
                                                  const float* __restrict__ W_hh,
                                                  const float* __restrict__ b_hh,
                                                  float* __restrict__ hs)
{
    int branch = blockIdx.x;
    int tid = threadIdx.x;       // 0..383
    int row = tid >> 1;          // 0..191
    int half = tid & 1;
    const float* g = gi + (size_t)branch * (16 * 496 * 192);
    float* out = hs + (size_t)branch * (16 * 496 * 64);

    unsigned long long w2[16];
    const float2* wr = (const float2*)(W_hh + (size_t)row * 64 + half * 32);
#pragma unroll
    for (int k = 0; k < 16; k++) {
        float2 p = wr[k];
        memcpy(&w2[k], &p, 8);
    }
    float bh = b_hh[row];

    __shared__ __align__(16) float h_sh[64];
    __shared__ float r_sh[64], z_sh[64];
    if (tid < 64) h_sh[tid] = 0.f;
    __syncthreads();

    const int L = 16 * 496;
    float gcur = (half == 0) ? g[row] : 0.f;
    for (int t = 0; t < L; t++) {
        float gnext = (half == 0 && t + 1 < L) ? g[(size_t)(t + 1) * 192 + row] : 0.f;
        unsigned long long a0 = 0, a1 = 0, a2 = 0, a3 = 0;
        const ulonglong2* hp = ((const ulonglong2*)h_sh) + half * 4;
#pragma unroll
        for (int q = 0; q < 4; q++) {
            ulonglong2 hv = hp[q];
            if (q & 1) {
                a2 = fma2(w2[4 * q + 0], hv.x, a2);
                a3 = fma2(w2[4 * q + 1], hv.y, a3);
            } else {
                a0 = fma2(w2[4 * q + 0], hv.x, a0);
                a1 = fma2(w2[4 * q + 1], hv.y, a1);
            }
            // second ull pair of this 16B chunk handled below
            if (q & 1) {
                a0 = fma2(w2[4 * q + 2], ((const unsigned long long*)&hv)[0] * 0, a0); // placeholder removed
            }
        }
        // NOTE: rewritten cleanly below
        a0 = a1 = a2 = a3 = 0;
        const unsigned long long* hq = ((const unsigned long long*)h_sh) + half * 16;
#pragma unroll
        for (int q = 0; q < 16; q += 4) {
            a0 = fma2(w2[q + 0], hq[q + 0], a0);
            a1 = fma2(w2[q + 1], hq[q + 1], a1);
            a2 = fma2(w2[q + 2], hq[q + 2], a2);
            a3 = fma2(w2[q + 3], hq[q + 3], a3);
        }
        float s_half;
        {
            float x0, x1, y0, y1, u0, u1, v0, v1;
            unpack2(a0, x0, x1);
            unpack2(a1, y0, y1);
            unpack2(a2, u0, u1);
            unpack2(a3, v0, v1);
            s_half = ((x0 + x1) + (y0 + y1)) + ((u0 + u1) + (v0 + v1));
        }
        float other = __shfl_xor_sync(0xffffffffu, s_half, 1);
        float s = ((half == 0) ? (s_half + other) : (other + s_half)) + bh;
        if (half == 0) {
            if (row < 64) {
                r_sh[row] = __fdividef(1.f, 1.f + __expf(-(gcur + s)));
            } else if (row < 128) {
                z_sh[row - 64] = __fdividef(1.f, 1.f + __expf(-(gcur + s)));
            }
        }
        __syncthreads();
        if (half == 0 && row >= 128) {
            int j = row - 128;
            float x = gcur + r_sh[j] * s;
            float e = __expf(-2.f * fabsf(x));
            float nt = __fdividef(1.f - e, 1.f + e);
            nt = copysignf(nt, x);
            float z = z_sh[j];
            float hn = (1.f - z) * nt + z * h_sh[j];
            h_sh[j] = hn;
            out[(size_t)t * 64 + j] = hn;
        }
        __syncthreads();
        gcur = gnext;
    }
}

// ---------------- attention stats: column max & inv-sum of exp ----------------
__global__ void attn_stats(const float* __restrict__ hs, float* __restrict__ mxo,
                           float* __restrict__ ivo)
{
    int b = blockIdx.y;
    int n0 = blockIdx.x * 8;
    const float* E  = hs + (size_t)b * 496 * 64;
    const float* Tm = hs + (size_t)(16 + b) * 496 * 64;
    __shared__ float tm_sh[8][64];
    __shared__ float lg[496][9];
    int tid = threadIdx.x; // 256
    for (int e = tid; e < 8 * 64; e += 256)
        tm_sh[e >> 6][e & 63] = Tm[(size_t)(n0 + (e >> 6)) * 64 + (e & 63)];
    __syncthreads();
    for (int m = tid; m < 496; m += 256) {
        const float4* Er = (const float4*)(E + (size_t)m * 64);
        float acc[8];
#pragma unroll
        for (int nn = 0; nn < 8; nn++) acc[nn] = 0.f;
#pragma unroll
        for (int j4 = 0; j4 < 16; j4++) {
            float4 v = Er[j4];
#pragma unroll
            for (int nn = 0; nn < 8; nn++) {
                acc[nn] += v.x * tm_sh[nn][j4 * 4 + 0];
                acc[nn] += v.y * tm_sh[nn][j4 * 4 + 1];
                acc[nn] += v.z * tm_sh[nn][j4 * 4 + 2];
                acc[nn] += v.w * tm_sh[nn][j4 * 4 + 3];
            }
        }
#pragma unroll
        for (int nn = 0; nn < 8; nn++) lg[m][nn] = acc[nn];
    }
    __syncthreads();
    int wg = tid >> 5, lane = tid & 31;
    float mx = -INFINITY;
    for (int m = lane; m < 496; m += 32) mx = fmaxf(mx, lg[m][wg]);
#pragma unroll
    for (int o = 16; o; o >>= 1) mx = fmaxf(mx, __shfl_xor_sync(0xffffffffu, mx, o));
    float sum = 0.f;
    for (int m = lane; m < 496; m += 32) sum += __expf(lg[m][wg] - mx);
#pragma unroll
    for (int o = 16; o; o >>= 1) sum += __shfl_xor_sync(0xffffffffu, sum, o);
    if (lane == 0) {
        mxo[b * 512 + n0 + wg] = mx;
        ivo[b * 512 + n0 + wg] = 1.f / sum;
    }
}

// ---------------- fused Tp: recompute logits, exp, contract with Tm ----------------
__global__ __launch_bounds__(256) void tp_fused(const float* __restrict__ hs,
                                                const float* __restrict__ mxv,
                                                const float* __restrict__ ivv,
                                                float* __restrict__ Tp)
{
    extern __shared__ float sm[];
    float* sE  = sm;               // 64 x 68
    float* sTm = sm + 64 * 68;     // 64 x 68
    float* sP  = sm + 2 * 64 * 68; // 64 x 68
    int b = blockIdx.y;
    int m0 = blockIdx.x * 64;
    const float* E  = hs + (size_t)b * 496 * 64;
    const float* Tm = hs + (size_t)(16 + b) * 496 * 64;
    int tid = threadIdx.x;
    int tx = tid & 15, ty = tid >> 4;

    for (int e = tid; e < 64 * 16; e += 256) {
        int r = e >> 4, c4 = (e & 15) * 4;
        float4 v = (m0 + r < 496) ? *(const float4*)(E + (size_t)(m0 + r) * 64 + c4)
                                  : make_float4(0.f, 0.f, 0.f, 0.f);
        *(float4*)&sE[r * 68 + c4] = v;
    }

    float acc[4][4];
#pragma unroll
    for (int ii = 0; ii < 4; ii++)
#pragma unroll
        for (int dd = 0; dd < 4; dd++) acc[ii][dd] = 0.f;

    for (int n0 = 0; n0 < 496; n0 += 64) {
        for (int e = tid; e < 64 * 16; e += 256) {
            int r = e >> 4, c4 = (e & 15) * 4;
            float4 v = (n0 + r < 496) ? *(const float4*)(Tm + (size_t)(n0 + r) * 64 + c4)
                                      : make_float4(0.f, 0.f, 0.f, 0.f);
            *(float4*)&sTm[r * 68 + c4] = v;
        }
        __syncthreads();

        float s4[4][4];
#pragma unroll
        for (int ii = 0; ii < 4; ii++)
#pragma unroll
            for (int jj = 0; jj < 4; jj++) s4[ii][jj] = 0.f;
#pragma unroll
        for (int k4 = 0; k4 < 16; k4++) {
            float4 a[4], bb[4];
#pragma unroll
            for (int ii = 0; ii < 4; ii++)
                a[ii] = *(float4*)&sE[(ty * 4 + ii) * 68 + k4 * 4];
#pragma unroll
            for (int jj = 0; jj < 4; jj++)
                bb[jj] = *(float4*)&sTm[(tx * 4 + jj) * 68 + k4 * 4];
#pragma unroll
            for (int ii = 0; ii < 4; ii++)
#pragma unroll
                for (int jj = 0; jj < 4; jj++)
                    s4[ii][jj] += a[ii].x * bb[jj].x + a[ii].y * bb[jj].y
                                + a[ii].z * bb[jj].z + a[ii].w * bb[jj].w;
        }
#pragma unroll
        for (int jj = 0; jj < 4; jj++) {
            int nn = n0 + tx * 4 + jj;
            float mxn = (nn < 496) ? mxv[b * 512 + nn] : 0.f;
            float ivn = (nn < 496) ? ivv[b * 512 + nn] : 0.f;
#pragma unroll
            for (int ii = 0; ii < 4; ii++)
                sP[(ty * 4 + ii) * 68 + tx * 4 + jj] =
                    (nn < 496) ? __expf(s4[ii][jj] - mxn) * ivn : 0.f;
        }
        __syncthreads();
#pragma unroll 2
        for (int j = 0; j < 64; j++) {
            float4 bv = *(float4*)&sTm[j * 68 + tx * 4];
            float p0 = sP[(ty * 4 + 0) * 68 + j];
            float p1 = sP[(ty * 4 + 1) * 68 + j];
            float p2 = sP[(ty * 4 + 2) * 68 + j];
            float p3 = sP[(ty * 4 + 3) * 68 + j];
            acc[0][0] += p0 * bv.x; acc[0][1] += p0 * bv.y; acc[0][2] += p0 * bv.z; acc[0][3] += p0 * bv.w;
            acc[1][0] += p1 * bv.x; acc[1][1] += p1 * bv.y; acc[1][2] += p1 * bv.z; acc[1][3] += p1 * bv.w;
            acc[2][0] += p2 * bv.x; acc[2][1] += p2 * bv.y; acc[2][2] += p2 * bv.z; acc[2][3] += p2 * bv.w;
            acc[3][0] += p3 * bv.x; acc[3][1] += p3 * bv.y; acc[3][2] += p3 * bv.z; acc[3][3] += p3 * bv.w;
        }
        __syncthreads();
    }
#pragma unroll
    for (int ii = 0; ii < 4; ii++) {
        int m = m0 + ty * 4 + ii;
        if (m < 496) {
            float4 v; v.x = acc[ii][0]; v.y = acc[ii][1]; v.z = acc[ii][2]; v.w = acc[ii][3];
            *(float4*)&Tp[((size_t)b * 496 + m) * 64 + tx * 4] = v;
        }
    }
}

// ---------------- fused head ----------------
__global__ void final_kernel(const float* __restrict__ hs, const float* __restrict__ Tp,
                             const float* __restrict__ aw, const float* __restrict__ ab,
                             const float* __restrict__ l3w, const float* __restrict__ l3b,
                             const float* __restrict__ cw, const float* __restrict__ cb,
                             float* __restrict__ outp)
{
    int b = blockIdx.x;
    int tid = threadIdx.x; // 256
    const float* E   = hs + (size_t)b * 496 * 64;
    const float* Tpb = Tp + (size_t)b * 496 * 64;
    __shared__ float att[496];
    __shared__ float red[256];
    __shared__ float part[4][64];
    __shared__ float hrep[64];
    __shared__ float h2[128];
    __shared__ float aw_sh[64];
    if (tid < 64) aw_sh[tid] = aw[tid];
    __syncthreads();
    float lmax = -INFINITY;
    for (int s = tid; s < 496; s += 256) {
        const float* er = E + (size_t)s * 64;
        float acc = ab[0];
#pragma unroll
        for (int j = 0; j < 64; j++) acc += er[j] * aw_sh[j];
        att[s] = acc;
        lmax = fmaxf(lmax, acc);
    }
    red[tid] = lmax;
    __syncthreads();
    for (int o = 128; o; o >>= 1) {
        if (tid < o) red[tid] = fmaxf(red[tid], red[tid + o]);
        __syncthreads();
    }
    float mx = red[0];
    __syncthreads();
    float lsum = 0.f;
    for (int s = tid; s < 496; s += 256) {
        float e = __expf(att[s] - mx);
        att[s] = e;
        lsum += e;
    }
    red[tid] = lsum;
    __syncthreads();
    for (int o = 128; o; o >>= 1) {
        if (tid < o) red[tid] += red[tid + o];
        __syncthreads();
    }
    float inv = 1.f / red[0];
    int d = tid & 63, grp = tid >> 6;
    float acc = 0.f;
    for (int s = grp; s < 496; s += 4)
        acc += att[s] * fabsf(Tpb[(size_t)s * 64 + d] - E[(size_t)s * 64 + d]);
    part[grp][d] = acc;
    __syncthreads();
    if (tid < 64) {
        float r = (part[0][tid] + part[1][tid] + part[2][tid] + part[3][tid]) * inv;
        hrep[tid] = fmaxf(r, 0.f);
    }
    __syncthreads();
    if (tid < 128) {
        float a2 = l3b[tid];
#pragma unroll
        for (int j = 0; j < 64; j++) a2 += hrep[j] * l3w[(size_t)tid * 64 + j];
        h2[tid] = fmaxf(a2, 0.f);
    }
    __syncthreads();
    if (tid < 2) {
        float a3 = cb[tid];
#pragma unroll
        for (int j = 0; j < 128; j++) a3 += h2[j] * cw[(size_t)tid * 128 + j];
        outp[b * 2 + tid] = a3;
    }
}

// ---------------- launch ----------------
extern "C" void kernel_launch(void* const* d_in, const int* in_sizes, int n_in,
                              void* d_out, int out_size)
{
    const float* ev    = (const float*)d_in[0];
    const float* tmpl  = (const float*)d_in[1];
    const float* c1w   = (const float*)d_in[2];
    const float* c1b   = (const float*)d_in[3];
    const float* c2w   = (const float*)d_in[4];
    const float* c2b   = (const float*)d_in[5];
    const float* c3w   = (const float*)d_in[6];
    const float* c3b   = (const float*)d_in[7];
    const float* l1w   = (const float*)d_in[8];
    const float* l1b   = (const float*)d_in[9];
    const float* W_ih  = (const float*)d_in[10];
    const float* W_hh  = (const float*)d_in[11];
    const float* b_ih  = (const float*)d_in[12];
    const float* b_hh  = (const float*)d_in[13];
    const float* aw    = (const float*)d_in[14];
    const float* ab    = (const float*)d_in[15];
    const float* l3w   = (const float*)d_in[16];
    const float* l3b   = (const float*)d_in[17];
    const float* cw    = (const float*)d_in[18];
    const float* cb    = (const float*)d_in[19];
    float* outp = (float*)d_out;

    float *p_in, *p_c1, *p_c2, *p_c3, *p_pool, *p_x1, *p_gi, *p_hs, *p_Tp;
    float *p_wt2, *p_wt3, *p_mx, *p_iv;
    cudaGetSymbolAddress((void**)&p_in,   g_in);
    cudaGetSymbolAddress((void**)&p_c1,   g_c1);
    cudaGetSymbolAddress((void**)&p_c2,   g_c2);
    cudaGetSymbolAddress((void**)&p_c3,   g_c3);
    cudaGetSymbolAddress((void**)&p_pool, g_pool);
    cudaGetSymbolAddress((void**)&p_x1,   g_x1);
    cudaGetSymbolAddress((void**)&p_gi,   g_gi);
    cudaGetSymbolAddress((void**)&p_hs,   g_hs);
    cudaGetSymbolAddress((void**)&p_Tp,   g_Tp);
    cudaGetSymbolAddress((void**)&p_wt2,  g_wt2);
    cudaGetSymbolAddress((void**)&p_wt3,  g_wt3);
    cudaGetSymbolAddress((void**)&p_mx,   g_mx);
    cudaGetSymbolAddress((void**)&p_iv,   g_iv);

    const int smem2 = (8 * 2112 + 2 * 2560) * 4;    // 88,064 B
    const int smem3 = (8 * 4224 + 2 * 10240) * 4;   // 217,088 B
    const int smemp = 5 * 58 * 67 * 4;              // 77,720 B
    const int smemt = 3 * 64 * 68 * 4;              // 52,224 B
    cudaFuncSetAttribute(conv_mma2<16, 32, 508, 124>,
                         cudaFuncAttributeMaxDynamicSharedMemorySize, smem2);
    cudaFuncSetAttribute(conv_mma2<32, 64, 504, 120>,
                         cudaFuncAttributeMaxDynamicSharedMemorySize, smem3);
    cudaFuncSetAttribute(pool_ring,
                         cudaFuncAttributeMaxDynamicSharedMemorySize, smemp);
    cudaFuncSetAttribute(tp_fused,
                         cudaFuncAttributeMaxDynamicSharedMemorySize, smemt);

    prep_kernel<<<dim3(4, 16, 33), dim3(32, 8)>>>(ev, tmpl, c2w, c3w, p_in, p_wt2, p_wt3);
    conv1_nhwc<<<dim3(508, 32), 128>>>(p_in, c1w, c1b, p_c1);
    conv_mma2<16, 32, 508, 124><<<dim3(126, 32), 512, smem2>>>(p_c1, p_wt2, c2b, p_c2);
    conv_mma2<32, 64, 504, 120><<<dim3(125, 32), 512, smem3>>>(p_c2, p_wt3, c3b, p_c3);
    pool_ring<<<dim3(8, 32), 256, smemp>>>(p_c3, p_pool);
    gemm_bias<true><<<dim3(248, 1, 1), 128>>>(p_pool, l1w, l1b, p_x1,
                                              15872, 64, 3712, 0, 0, 0);
    gemm_bias<true><<<dim3(248, 3, 1), 128>>>(p_x1, W_ih, b_ih, p_gi,
                                              15872, 192, 64, 0, 0, 0);
    gru_kernel<<<2, 384>>>(p_gi, W_hh, b_hh, p_hs);
    attn_stats<<<dim3(62, 16), 256>>>(p_hs, p_mx, p_iv);
    tp_fused<<<dim3(8, 16), 256, smemt>>>(p_hs, p_mx, p_iv, p_Tp);
    final_kernel<<<16, 256>>>(p_hs, p_Tp, aw, ab, l3w, l3b, cw, cb, outp);
}

// round 13
// speedup vs baseline: 1.1053x; 1.1053x over previous
#include <cuda_runtime.h>
#include <math.h>
#include <stddef.h>
#include <stdint.h>
#include <string.h>

// ---------------- static scratch (no allocations allowed) ----------------
__device__ float g_in  [(size_t)32*512*128];          // (n, t, c)
__device__ float g_c1  [(size_t)32*508*124*16];       // NHWC
__device__ float g_c2  [(size_t)32*504*120*32];       // NHWC
__device__ float g_c3  [(size_t)32*500*116*64];       // NHWC
__device__ float g_pool[(size_t)32*64*496*58];        // (n, c, s, w) raw reshape layout
__device__ float g_x1  [(size_t)32*496*64];
__device__ float g_gi  [(size_t)32*496*192];
__device__ float g_hs  [(size_t)32*496*64];           // E (n<16) / Tm (n>=16)
__device__ float g_Tp  [(size_t)16*496*64];
__device__ float g_wt2 [(size_t)5*80*32];             // conv2 weights [dy][k8][co][pos]
__device__ float g_wt3 [(size_t)5*160*64];            // conv3 weights [dy][k8][co][pos]
__device__ float g_mx  [16*512];                      // column softmax stats
__device__ float g_iv  [16*512];

__device__ __forceinline__ uint32_t f2tf32(float x)
{
    uint32_t u;
    asm("cvt.rna.tf32.f32 %0, %1;" : "=r"(u) : "f"(x));
    return u;
}

__device__ __forceinline__ unsigned long long fma2(unsigned long long a,
                                                   unsigned long long b,
                                                   unsigned long long c)
{
    unsigned long long d;
    asm("fma.rn.f32x2 %0, %1, %2, %3;" : "=l"(d) : "l"(a), "l"(b), "l"(c));
    return d;
}

__device__ __forceinline__ unsigned long long pack2(float x, float y)
{
    unsigned long long d;
    asm("mov.b64 %0, {%1, %2};" : "=l"(d) : "f"(x), "f"(y));
    return d;
}

__device__ __forceinline__ void unpack2(unsigned long long v, float& x, float& y)
{
    asm("mov.b64 {%0, %1}, %2;" : "=f"(x), "=f"(y) : "l"(v));
}

__device__ __forceinline__ float dot_combine(unsigned long long a0, unsigned long long a1,
                                             unsigned long long a2, unsigned long long a3,
                                             float b)
{
    float x0, x1, y0, y1, u0, u1, v0, v1;
    unpack2(a0, x0, x1);
    unpack2(a1, y0, y1);
    unpack2(a2, u0, u1);
    unpack2(a3, v0, v1);
    return ((x0 + x1) + (y0 + y1)) + ((u0 + u1) + (v0 + v1)) + b;
}

// ---------------- prep: transpose (z<32) + weight reorders (z==32) ----------------
// B layout (R9): [dy][k>>3][co][pos(k&7)], pos(j) = 2*(j&3) + (j>>2)
__global__ void prep_kernel(const float* __restrict__ ev, const float* __restrict__ tm,
                            const float* __restrict__ c2w, const float* __restrict__ c3w,
                            float* __restrict__ out, float* __restrict__ wt2,
                            float* __restrict__ wt3)
{
    if (blockIdx.z < 32) {
        __shared__ float tile[32][33];
        int n = blockIdx.z;
        const float* src = (n < 16) ? (ev + (size_t)n * 128 * 512)
                                    : (tm + (size_t)(n - 16) * 128 * 512);
        int x0 = blockIdx.x * 32;
        int y0 = blockIdx.y * 32;
        int lx = threadIdx.x, ly = threadIdx.y; // 32 x 8
        for (int r = ly; r < 32; r += 8)
            tile[r][lx] = src[(size_t)(x0 + r) * 512 + y0 + lx];
        __syncthreads();
        float* o = out + (size_t)n * 512 * 128;
        for (int r = ly; r < 32; r += 8)
            o[(size_t)(y0 + r) * 128 + x0 + lx] = tile[lx][r];
    } else {
        int pid = (blockIdx.y * 4 + blockIdx.x) * 256 + threadIdx.y * 32 + threadIdx.x;
        for (int idx = pid; idx < 12800; idx += 16384) {   // conv2: CIN=16, COUT=32
            int dx = idx % 5, dy = (idx / 5) % 5, ci = (idx / 25) % 16, co = idx / 400;
            int k = dx * 16 + ci;
            int j = k & 7;
            int pos = 2 * (j & 3) + (j >> 2);
            wt2[(size_t)dy * (80 * 32) + (k >> 3) * 256 + co * 8 + pos] =
                __uint_as_float(f2tf32(c2w[idx]));
        }
        for (int idx = pid; idx < 51200; idx += 16384) {   // conv3: CIN=32, COUT=64
            int dx = idx % 5, dy = (idx / 5) % 5, ci = (idx / 25) % 32, co = idx / 800;
            int k = dx * 32 + ci;
            int j = k & 7;
            int pos = 2 * (j & 3) + (j >> 2);
            wt3[(size_t)dy * (160 * 64) + (k >> 3) * 512 + co * 8 + pos] =
                __uint_as_float(f2tf32(c3w[idx]));
        }
    }
}

// ---------------- conv1: CIN=1, direct fp32, NHWC out ----------------
__global__ void conv1_nhwc(const float* __restrict__ in, const float* __restrict__ w,
                           const float* __restrict__ bias, float* __restrict__ out)
{
    __shared__ float srow[5][128];
    __shared__ float sw[16][25];
    __shared__ float sb[16];
    int y = blockIdx.x, n = blockIdx.y, tid = threadIdx.x;  // 128 threads
    const float* ip = in + ((size_t)n * 512 + y) * 128;
#pragma unroll
    for (int r = 0; r < 5; r++) srow[r][tid] = ip[(size_t)r * 128 + tid];
    if (tid < 16) sb[tid] = bias[tid];
    for (int e = tid; e < 400; e += 128) sw[e / 25][e % 25] = w[e];
    __syncthreads();
    if (tid >= 124) return;
    float acc[16];
#pragma unroll
    for (int co = 0; co < 16; co++) acc[co] = sb[co];
#pragma unroll
    for (int dy = 0; dy < 5; dy++) {
#pragma unroll
        for (int dx = 0; dx < 5; dx++) {
            float v = srow[dy][tid + dx];
#pragma unroll
            for (int co = 0; co < 16; co++) acc[co] += v * sw[co][dy * 5 + dx];
        }
    }
    float4* op = (float4*)(out + (((size_t)n * 508 + y) * 124 + tid) * 16);
#pragma unroll
    for (int q = 0; q < 4; q++) {
        float4 v; v.x = acc[q*4]; v.y = acc[q*4+1]; v.z = acc[q*4+2]; v.w = acc[q*4+3];
        op[q] = v;
    }
}

// ---------------- implicit-GEMM conv (R9): ldmatrix A-frags, paired-B LDS.64 ---------
template<int CIN, int COUT, int HIN, int WIN>
__global__ __launch_bounds__(512) void conv_mma2(const float* __restrict__ in,
                                                 const float* __restrict__ wt,
                                                 const float* __restrict__ bias,
                                                 float* __restrict__ out)
{
    constexpr int HOUT = HIN - 4, WOUT = WIN - 4;
    constexpr int ROWF = 132 * CIN;
    constexpr int KDY = 5 * CIN;
    constexpr int BSZ = KDY * COUT;
    constexpr int A_SHIFT = (CIN == 32) ? 5 : 4;
    constexpr int MI = (COUT == 64) ? 4 : 2;

    extern __shared__ float smem[];
    float* sA = smem;                 // 8 rows x ROWF
    float* sB = smem + 8 * ROWF;      // 2 x BSZ (double buffer, contiguous layout)
    uint32_t* sAu = (uint32_t*)sA;

    int tid = threadIdx.x;
    int lane = tid & 31, warp = tid >> 5;   // 16 warps
    int y0 = blockIdx.x * 4, n = blockIdx.y;
    int wy = warp >> 2;
    int wsub = warp & 3;
    int mrow, nbase;
    if (COUT == 64) { mrow = (wsub & 1) * 64; nbase = (wsub >> 1) * 32; }
    else            { mrow = wsub * 32;       nbase = 0; }

    int ra = lane >> 2;
    int kfrac = lane & 3;
    int cidx[4];
#pragma unroll
    for (int nj = 0; nj < 4; nj++)
        cidx[nj] = (nbase + nj * 8 + ra) * 4 + kfrac;

    int lrow = lane & 15;
    int lcol = (lane >> 4) * 4;
    int linv[MI];
#pragma unroll
    for (int mi = 0; mi < MI; mi++)
        linv[mi] = (mrow + mi * 16 + lrow) * CIN + lcol;

    uint32_t sA_sh = (uint32_t)__cvta_generic_to_shared(sAu);

    float acc[MI][4][4];
#pragma unroll
    for (int mi = 0; mi < MI; mi++)
#pragma unroll
        for (int nj = 0; nj < 4; nj++)
#pragma unroll
            for (int q = 0; q < 4; q++) acc[mi][nj][q] = 0.f;

    // ---- stage all 8 input rows once (tf32, per-row swizzle) ----
    const int WVALID = WIN * CIN;
    for (int l = tid * 4; l < 8 * ROWF; l += 2048) {
        int rr = l / ROWF, lo = l % ROWF;
        const float* inrow = in + ((size_t)(n * HIN + y0 + rr) * WIN) * CIN;
        float4 v;
        if (lo + 4 <= WVALID) v = *(const float4*)(inrow + lo);
        else { v.x = v.y = v.z = v.w = 0.f; }
        uint4 u;
        u.x = f2tf32(v.x); u.y = f2tf32(v.y); u.z = f2tf32(v.z); u.w = f2tf32(v.w);
        int p = lo ^ (((lo >> A_SHIFT) & 7) << 2);
        *(uint4*)(sAu + rr * ROWF + p) = u;
    }

    // ---- prefetch B[0] via cp.async ----
    for (int l = tid * 4; l < BSZ; l += 2048) {
        uint32_t da = (uint32_t)__cvta_generic_to_shared(sB + l);
        asm volatile("cp.async.ca.shared.global [%0], [%1], 16;\n"
                     :: "r"(da), "l"(wt + l));
    }
    asm volatile("cp.async.commit_group;\n");
    asm volatile("cp.async.wait_group 0;\n");
    __syncthreads();

#pragma unroll 1
    for (int dy = 0; dy < 5; dy++) {
        if (dy < 4) {
            const float* wrow = wt + (size_t)(dy + 1) * BSZ;
            float* dst = sB + ((dy + 1) & 1) * BSZ;
            for (int l = tid * 4; l < BSZ; l += 2048) {
                uint32_t da = (uint32_t)__cvta_generic_to_shared(dst + l);
                asm volatile("cp.async.ca.shared.global [%0], [%1], 16;\n"
                             :: "r"(da), "l"(wrow + l));
            }
            asm volatile("cp.async.commit_group;\n");
        }
        const float2* sB2 = (const float2*)(sB + (dy & 1) * BSZ);

        int abase = (wy + dy) * ROWF;
#pragma unroll
        for (int k8 = 0; k8 < KDY; k8 += 8) {
            uint32_t a[MI][4];
#pragma unroll
            for (int mi = 0; mi < MI; mi++) {
                int l0 = linv[mi] + k8;
                int p = l0 ^ (((l0 >> A_SHIFT) & 7) << 2);
                uint32_t addr = sA_sh + (uint32_t)(abase + p) * 4u;
                asm volatile(
                    "ldmatrix.sync.aligned.m8n8.x4.shared.b16 {%0,%1,%2,%3}, [%4];"
                    : "=r"(a[mi][0]), "=r"(a[mi][1]), "=r"(a[mi][2]), "=r"(a[mi][3])
                    : "r"(addr));
            }
            const float2* pb = sB2 + (k8 >> 3) * (4 * COUT);
#pragma unroll
            for (int nj = 0; nj < 4; nj++) {
                float2 bb = pb[cidx[nj]];
                uint32_t b0 = __float_as_uint(bb.x);
                uint32_t b1 = __float_as_uint(bb.y);
#pragma unroll
                for (int mi = 0; mi < MI; mi++) {
                    asm volatile(
                        "mma.sync.aligned.m16n8k8.row.col.f32.tf32.tf32.f32 "
                        "{%0,%1,%2,%3}, {%4,%5,%6,%7}, {%8,%9}, {%0,%1,%2,%3};"
                        : "+f"(acc[mi][nj][0]), "+f"(acc[mi][nj][1]),
                          "+f"(acc[mi][nj][2]), "+f"(acc[mi][nj][3])
                        : "r"(a[mi][0]), "r"(a[mi][1]), "r"(a[mi][2]), "r"(a[mi][3]),
                          "r"(b0), "r"(b1));
                }
            }
        }
        if (dy < 4) {
            asm volatile("cp.async.wait_group 0;\n");
            __syncthreads();
        }
    }

    int y = y0 + wy;
    size_t obase = ((size_t)(n * HOUT + y) * WOUT) * COUT;
#pragma unroll
    for (int mi = 0; mi < MI; mi++) {
#pragma unroll
        for (int nj = 0; nj < 4; nj++) {
            int x = mrow + mi * 16 + ra;
            int co = nbase + nj * 8 + kfrac * 2;
            float b0 = bias[co], b1 = bias[co + 1];
            if (x < WOUT) {
                float2 v; v.x = acc[mi][nj][0] + b0; v.y = acc[mi][nj][1] + b1;
                *(float2*)(out + obase + (size_t)x * COUT + co) = v;
            }
            if (x + 8 < WOUT) {
                float2 v; v.x = acc[mi][nj][2] + b0; v.y = acc[mi][nj][3] + b1;
                *(float2*)(out + obase + (size_t)(x + 8) * COUT + co) = v;
            }
        }
    }
}

// ---------------- maxpool ring: each conv3 row read once ----------------
__global__ void pool_ring(const float* __restrict__ in, float* __restrict__ out)
{
    extern __shared__ float ring[];   // 5 x (58*67)
    const int RP = 58 * 67;
    int strip = blockIdx.x, n = blockIdx.y, tid = threadIdx.x; // 256 threads
    int s0 = strip * 62;
    float* ob = out + (size_t)n * 64 * 496 * 58;
    for (int y = s0; y < s0 + 66; y++) {
        const float* ip = in + ((size_t)(n * 500 + y) * 116) * 64;
        int rr = (y - s0) % 5;
        for (int idx = tid; idx < 3712; idx += 256) {
            int wp = idx >> 6, c = idx & 63;
            float a = ip[(size_t)(2 * wp) * 64 + c];
            float b = ip[(size_t)(2 * wp) * 64 + 64 + c];
            ring[rr * RP + wp * 67 + c] = fmaxf(a, b);
        }
        __syncthreads();
        if (y - s0 >= 4) {
            int s = y - 4;
            for (int f = tid; f < 3712; f += 256) {
                int c = f / 58, wp = f % 58;
                int o = wp * 67 + c;
                float m = ring[o];
                m = fmaxf(m, ring[RP + o]);
                m = fmaxf(m, ring[2 * RP + o]);
                m = fmaxf(m, ring[3 * RP + o]);
                m = fmaxf(m, ring[4 * RP + o]);
                ob[(size_t)c * 496 * 58 + (size_t)s * 58 + wp] = m;
            }
        }
        __syncthreads();
    }
}

// ------- tiled SIMT GEMM, packed-A smem + f32x2 inner loop (exact fp32) -------
template<bool WT>
__global__ void gemm_bias(const float* __restrict__ A, const float* __restrict__ Bm,
                          const float* __restrict__ bias, float* __restrict__ C,
                          int M, int N, int K, long sA, long sB, long sC)
{
    A  += (long)blockIdx.z * sA;
    Bm += (long)blockIdx.z * sB;
    C  += (long)blockIdx.z * sC;
    __shared__ __align__(16) unsigned long long sAd[64][17];  // (a,a) duplicated
    __shared__ __align__(16) float sBi[16][68];
    int tid = threadIdx.x;          // 128
    int ttx = tid & 15, tty = tid >> 4;
    int m0 = blockIdx.x * 64, n0 = blockIdx.y * 64;
    unsigned long long acc2[8][2];
#pragma unroll
    for (int i = 0; i < 8; i++) { acc2[i][0] = 0ull; acc2[i][1] = 0ull; }

    for (int k0 = 0; k0 < K; k0 += 16) {
#pragma unroll
        for (int l = 0; l < 8; l++) {
            int e = tid + l * 128;
            int mm = e >> 4, kk = e & 15;
            int m = m0 + mm;
            float v = (m < M) ? A[(long)m * K + k0 + kk] : 0.f;
            sAd[mm][kk] = pack2(v, v);
        }
#pragma unroll
        for (int l = 0; l < 8; l++) {
            int e = tid + l * 128;
            if (WT) {
                int j = e >> 4, kk = e & 15;
                int jn = n0 + j;
                sBi[kk][j] = (jn < N) ? Bm[(long)jn * K + k0 + kk] : 0.f;
            } else {
                int kk = e >> 6, j = e & 63;
                int jn = n0 + j;
                sBi[kk][j] = (jn < N) ? Bm[(long)(k0 + kk) * N + jn] : 0.f;
            }
        }
        __syncthreads();
#pragma unroll
        for (int kk = 0; kk < 16; kk++) {
            unsigned long long b0 = *(const unsigned long long*)&sBi[kk][ttx * 4];
            unsigned long long b1 = *(const unsigned long long*)&sBi[kk][ttx * 4 + 2];
#pragma unroll
            for (int i = 0; i < 8; i++) {
                unsigned long long ap = sAd[tty * 8 + i][kk];
                acc2[i][0] = fma2(ap, b0, acc2[i][0]);
                acc2[i][1] = fma2(ap, b1, acc2[i][1]);
            }
        }
        __syncthreads();
    }
#pragma unroll
    for (int i = 0; i < 8; i++) {
        int m = m0 + tty * 8 + i;
        if (m < M) {
            int j0 = n0 + ttx * 4;
            float4 v;
            unpack2(acc2[i][0], v.x, v.y);
            unpack2(acc2[i][1], v.z, v.w);
            v.x += bias ? bias[j0 + 0] : 0.f;
            v.y += bias ? bias[j0 + 1] : 0.f;
            v.z += bias ? bias[j0 + 2] : 0.f;
            v.w += bias ? bias[j0 + 3] : 0.f;
            *(float4*)&C[(long)m * N + j0] = v;
        }
    }
}

// ------ GRU v5: 64 threads, thread j owns rows r=j, z=64+j, n=128+j ------
// Double-buffered h -> ONE barrier per step. fma2 sequence per row identical to R9.
__global__ __launch_bounds__(64) void gru_kernel(const float* __restrict__ gi,
                                                 const float* __restrict__ W_hh,
                                                 const float* __restrict__ b_hh,
                                                 float* __restrict__ hs)
{
    int branch = blockIdx.x;
    int j = threadIdx.x;   // 0..63
    const float* g = gi + (size_t)branch * (16 * 496 * 192);
    float* out = hs + (size_t)branch * (16 * 496 * 64);

    unsigned long long wr_[16], wz_[16], wn_[16];
    {
        const float2* p0 = (const float2*)(W_hh + (size_t)j * 64);
        const float2* p1 = (const float2*)(W_hh + (size_t)(64 + j) * 64);
        const float2* p2 = (const float2*)(W_hh + (size_t)(128 + j) * 64);
#pragma unroll
        for (int k = 0; k < 16; k++) {
            float2 a = p0[k]; memcpy(&wr_[k], &a, 8);
            float2 b = p1[k]; memcpy(&wz_[k], &b, 8);
            float2 c = p2[k]; memcpy(&wn_[k], &c, 8);
        }
        // NOTE: R9 used 32 u64 words per row (stride-2 float2). Here each row's
        // 64 floats = 32 u64; we keep 32 by splitting into two 16-chunks below.
    }
    unsigned long long wr2[32], wz2[32], wn2[32];
    {
        const float2* p0 = (const float2*)(W_hh + (size_t)j * 64);
        const float2* p1 = (const float2*)(W_hh + (size_t)(64 + j) * 64);
        const float2* p2 = (const float2*)(W_hh + (size_t)(128 + j) * 64);
#pragma unroll
        for (int k = 0; k < 32; k++) {
            float2 a = p0[k]; memcpy(&wr2[k], &a, 8);
            float2 b = p1[k]; memcpy(&wz2[k], &b, 8);
            float2 c = p2[k]; memcpy(&wn2[k], &c, 8);
        }
    }
    (void)wr_; (void)wz_; (void)wn_;
    float br = b_hh[j], bz = b_hh[64 + j], bn = b_hh[128 + j];

    __shared__ __align__(16) float h_sh[2][64];
    h_sh[0][j] = 0.f;
    __syncthreads();

    const int L = 16 * 496;
    float gr = g[j], gz = g[64 + j], gn = g[128 + j];
    int cur = 0;
    for (int t = 0; t < L; t++) {
        float gr_n = 0.f, gz_n = 0.f, gn_n = 0.f;
        if (t + 1 < L) {
            const float* gp = g + (size_t)(t + 1) * 192;
            gr_n = gp[j]; gz_n = gp[64 + j]; gn_n = gp[128 + j];
        }
        unsigned long long r0 = 0, r1 = 0, r2 = 0, r3 = 0;
        unsigned long long z0 = 0, z1 = 0, z2 = 0, z3 = 0;
        unsigned long long n0 = 0, n1 = 0, n2 = 0, n3 = 0;
        const ulonglong2* hp = (const ulonglong2*)h_sh[cur];
#pragma unroll
        for (int q = 0; q < 16; q += 2) {
            ulonglong2 hA = hp[q];
            ulonglong2 hB = hp[q + 1];
            r0 = fma2(wr2[2 * q + 0], hA.x, r0);
            r1 = fma2(wr2[2 * q + 1], hA.y, r1);
            r2 = fma2(wr2[2 * q + 2], hB.x, r2);
            r3 = fma2(wr2[2 * q + 3], hB.y, r3);
            z0 = fma2(wz2[2 * q + 0], hA.x, z0);
            z1 = fma2(wz2[2 * q + 1], hA.y, z1);
            z2 = fma2(wz2[2 * q + 2], hB.x, z2);
            z3 = fma2(wz2[2 * q + 3], hB.y, z3);
            n0 = fma2(wn2[2 * q + 0], hA.x, n0);
            n1 = fma2(wn2[2 * q + 1], hA.y, n1);
            n2 = fma2(wn2[2 * q + 2], hB.x, n2);
            n3 = fma2(wn2[2 * q + 3], hB.y, n3);
        }
        float sr = dot_combine(r0, r1, r2, r3, br);
        float sz = dot_combine(z0, z1, z2, z3, bz);
        float sn = dot_combine(n0, n1, n2, n3, bn);
        float r = __fdividef(1.f, 1.f + __expf(-(gr + sr)));
        float z = __fdividef(1.f, 1.f + __expf(-(gz + sz)));
        float x = gn + r * sn;
        float e = __expf(-2.f * fabsf(x));
        float nt = __fdividef(1.f - e, 1.f + e);
        nt = copysignf(nt, x);
        float hn = (1.f - z) * nt + z * h_sh[cur][j];
        h_sh[cur ^ 1][j] = hn;
        out[(size_t)t * 64 + j] = hn;
        __syncthreads();
        cur ^= 1;
        gr = gr_n; gz = gz_n; gn = gn_n;
    }
}

// ---------------- attention stats: column max & inv-sum of exp ----------------
__global__ void attn_stats(const float* __restrict__ hs, float* __restrict__ mxo,
                           float* __restrict__ ivo)
{
    int b = blockIdx.y;
    int n0 = blockIdx.x * 8;
    const float* E  = hs + (size_t)b * 496 * 64;
    const float* Tm = hs + (size_t)(16 + b) * 496 * 64;
    __shared__ float tm_sh[8][64];
    __shared__ float lg[496][9];
    int tid = threadIdx.x; // 256
    for (int e = tid; e < 8 * 64; e += 256)
        tm_sh[e >> 6][e & 63] = Tm[(size_t)(n0 + (e >> 6)) * 64 + (e & 63)];
    __syncthreads();
    for (int m = tid; m < 496; m += 256) {
        const float4* Er = (const float4*)(E + (size_t)m * 64);
        float acc[8];
#pragma unroll
        for (int nn = 0; nn < 8; nn++) acc[nn] = 0.f;
#pragma unroll
        for (int j4 = 0; j4 < 16; j4++) {
            float4 v = Er[j4];
#pragma unroll
            for (int nn = 0; nn < 8; nn++) {
                acc[nn] += v.x * tm_sh[nn][j4 * 4 + 0];
                acc[nn] += v.y * tm_sh[nn][j4 * 4 + 1];
                acc[nn] += v.z * tm_sh[nn][j4 * 4 + 2];
                acc[nn] += v.w * tm_sh[nn][j4 * 4 + 3];
            }
        }
#pragma unroll
        for (int nn = 0; nn < 8; nn++) lg[m][nn] = acc[nn];
    }
    __syncthreads();
    int wg = tid >> 5, lane = tid & 31;
    float mx = -INFINITY;
    for (int m = lane; m < 496; m += 32) mx = fmaxf(mx, lg[m][wg]);
#pragma unroll
    for (int o = 16; o; o >>= 1) mx = fmaxf(mx, __shfl_xor_sync(0xffffffffu, mx, o));
    float sum = 0.f;
    for (int m = lane; m < 496; m += 32) sum += __expf(lg[m][wg] - mx);
#pragma unroll
    for (int o = 16; o; o >>= 1) sum += __shfl_xor_sync(0xffffffffu, sum, o);
    if (lane == 0) {
        mxo[b * 512 + n0 + wg] = mx;
        ivo[b * 512 + n0 + wg] = 1.f / sum;
    }
}

// ---------------- fused Tp: recompute logits, exp, contract with Tm ----------------
__global__ __launch_bounds__(256) void tp_fused(const float* __restrict__ hs,
                                                const float* __restrict__ mxv,
                                                const float* __restrict__ ivv,
                                                float* __restrict__ Tp)
{
    extern __shared__ float sm[];
    float* sE  = sm;               // 64 x 68
    float* sTm = sm + 64 * 68;     // 64 x 68
    float* sP  = sm + 2 * 64 * 68; // 64 x 68
    int b = blockIdx.y;
    int m0 = blockIdx.x * 64;
    const float* E  = hs + (size_t)b * 496 * 64;
    const float* Tm = hs + (size_t)(16 + b) * 496 * 64;
    int tid = threadIdx.x;
    int tx = tid & 15, ty = tid >> 4;

    for (int e = tid; e < 64 * 16; e += 256) {
        int r = e >> 4, c4 = (e & 15) * 4;
        float4 v = (m0 + r < 496) ? *(const float4*)(E + (size_t)(m0 + r) * 64 + c4)
                                  : make_float4(0.f, 0.f, 0.f, 0.f);
        *(float4*)&sE[r * 68 + c4] = v;
    }

    float acc[4][4];
#pragma unroll
    for (int ii = 0; ii < 4; ii++)
#pragma unroll
        for (int dd = 0; dd < 4; dd++) acc[ii][dd] = 0.f;

    for (int n0 = 0; n0 < 496; n0 += 64) {
        for (int e = tid; e < 64 * 16; e += 256) {
            int r = e >> 4, c4 = (e & 15) * 4;
            float4 v = (n0 + r < 496) ? *(const float4*)(Tm + (size_t)(n0 + r) * 64 + c4)
                                      : make_float4(0.f, 0.f, 0.f, 0.f);
            *(float4*)&sTm[r * 68 + c4] = v;
        }
        __syncthreads();

        float s4[4][4];
#pragma unroll
        for (int ii = 0; ii < 4; ii++)
#pragma unroll
            for (int jj = 0; jj < 4; jj++) s4[ii][jj] = 0.f;
#pragma unroll
        for (int k4 = 0; k4 < 16; k4++) {
            float4 a[4], bb[4];
#pragma unroll
            for (int ii = 0; ii < 4; ii++)
                a[ii] = *(float4*)&sE[(ty * 4 + ii) * 68 + k4 * 4];
#pragma unroll
            for (int jj = 0; jj < 4; jj++)
                bb[jj] = *(float4*)&sTm[(tx * 4 + jj) * 68 + k4 * 4];
#pragma unroll
            for (int ii = 0; ii < 4; ii++)
#pragma unroll
                for (int jj = 0; jj < 4; jj++)
                    s4[ii][jj] += a[ii].x * bb[jj].x + a[ii].y * bb[jj].y
                                + a[ii].z * bb[jj].z + a[ii].w * bb[jj].w;
        }
#pragma unroll
        for (int jj = 0; jj < 4; jj++) {
            int nn = n0 + tx * 4 + jj;
            float mxn = (nn < 496) ? mxv[b * 512 + nn] : 0.f;
            float ivn = (nn < 496) ? ivv[b * 512 + nn] : 0.f;
#pragma unroll
            for (int ii = 0; ii < 4; ii++)
                sP[(ty * 4 + ii) * 68 + tx * 4 + jj] =
                    (nn < 496) ? __expf(s4[ii][jj] - mxn) * ivn : 0.f;
        }
        __syncthreads();
#pragma unroll 2
        for (int j = 0; j < 64; j++) {
            float4 bv = *(float4*)&sTm[j * 68 + tx * 4];
            float p0 = sP[(ty * 4 + 0) * 68 + j];
            float p1 = sP[(ty * 4 + 1) * 68 + j];
            float p2 = sP[(ty * 4 + 2) * 68 + j];
            float p3 = sP[(ty * 4 + 3) * 68 + j];
            acc[0][0] += p0 * bv.x; acc[0][1] += p0 * bv.y; acc[0][2] += p0 * bv.z; acc[0][3] += p0 * bv.w;
            acc[1][0] += p1 * bv.x; acc[1][1] += p1 * bv.y; acc[1][2] += p1 * bv.z; acc[1][3] += p1 * bv.w;
            acc[2][0] += p2 * bv.x; acc[2][1] += p2 * bv.y; acc[2][2] += p2 * bv.z; acc[2][3] += p2 * bv.w;
            acc[3][0] += p3 * bv.x; acc[3][1] += p3 * bv.y; acc[3][2] += p3 * bv.z; acc[3][3] += p3 * bv.w;
        }
        __syncthreads();
    }
#pragma unroll
    for (int ii = 0; ii < 4; ii++) {
        int m = m0 + ty * 4 + ii;
        if (m < 496) {
            float4 v; v.x = acc[ii][0]; v.y = acc[ii][1]; v.z = acc[ii][2]; v.w = acc[ii][3];
            *(float4*)&Tp[((size_t)b * 496 + m) * 64 + tx * 4] = v;
        }
    }
}

// ---------------- fused head ----------------
__global__ void final_kernel(const float* __restrict__ hs, const float* __restrict__ Tp,
                             const float* __restrict__ aw, const float* __restrict__ ab,
                             const float* __restrict__ l3w, const float* __restrict__ l3b,
                             const float* __restrict__ cw, const float* __restrict__ cb,
                             float* __restrict__ outp)
{
    int b = blockIdx.x;
    int tid = threadIdx.x; // 256
    const float* E   = hs + (size_t)b * 496 * 64;
    const float* Tpb = Tp + (size_t)b * 496 * 64;
    __shared__ float att[496];
    __shared__ float red[256];
    __shared__ float part[4][64];
    __shared__ float hrep[64];
    __shared__ float h2[128];
    __shared__ float aw_sh[64];
    if (tid < 64) aw_sh[tid] = aw[tid];
    __syncthreads();
    float lmax = -INFINITY;
    for (int s = tid; s < 496; s += 256) {
        const float* er = E + (size_t)s * 64;
        float acc = ab[0];
#pragma unroll
        for (int j = 0; j < 64; j++) acc += er[j] * aw_sh[j];
        att[s] = acc;
        lmax = fmaxf(lmax, acc);
    }
    red[tid] = lmax;
    __syncthreads();
    for (int o = 128; o; o >>= 1) {
        if (tid < o) red[tid] = fmaxf(red[tid], red[tid + o]);
        __syncthreads();
    }
    float mx = red[0];
    __syncthreads();
    float lsum = 0.f;
    for (int s = tid; s < 496; s += 256) {
        float e = __expf(att[s] - mx);
        att[s] = e;
        lsum += e;
    }
    red[tid] = lsum;
    __syncthreads();
    for (int o = 128; o; o >>= 1) {
        if (tid < o) red[tid] += red[tid + o];
        __syncthreads();
    }
    float inv = 1.f / red[0];
    int d = tid & 63, grp = tid >> 6;
    float acc = 0.f;
    for (int s = grp; s < 496; s += 4)
        acc += att[s] * fabsf(Tpb[(size_t)s * 64 + d] - E[(size_t)s * 64 + d]);
    part[grp][d] = acc;
    __syncthreads();
    if (tid < 64) {
        float r = (part[0][tid] + part[1][tid] + part[2][tid] + part[3][tid]) * inv;
        hrep[tid] = fmaxf(r, 0.f);
    }
    __syncthreads();
    if (tid < 128) {
        float a2 = l3b[tid];
#pragma unroll
        for (int j = 0; j < 64; j++) a2 += hrep[j] * l3w[(size_t)tid * 64 + j];
        h2[tid] = fmaxf(a2, 0.f);
    }
    __syncthreads();
    if (tid < 2) {
        float a3 = cb[tid];
#pragma unroll
        for (int j = 0; j < 128; j++) a3 += h2[j] * cw[(size_t)tid * 128 + j];
        outp[b * 2 + tid] = a3;
    }
}

// ---------------- launch ----------------
extern "C" void kernel_launch(void* const* d_in, const int* in_sizes, int n_in,
                              void* d_out, int out_size)
{
    const float* ev    = (const float*)d_in[0];
    const float* tmpl  = (const float*)d_in[1];
    const float* c1w   = (const float*)d_in[2];
    const float* c1b   = (const float*)d_in[3];
    const float* c2w   = (const float*)d_in[4];
    const float* c2b   = (const float*)d_in[5];
    const float* c3w   = (const float*)d_in[6];
    const float* c3b   = (const float*)d_in[7];
    const float* l1w   = (const float*)d_in[8];
    const float* l1b   = (const float*)d_in[9];
    const float* W_ih  = (const float*)d_in[10];
    const float* W_hh  = (const float*)d_in[11];
    const float* b_ih  = (const float*)d_in[12];
    const float* b_hh  = (const float*)d_in[13];
    const float* aw    = (const float*)d_in[14];
    const float* ab    = (const float*)d_in[15];
    const float* l3w   = (const float*)d_in[16];
    const float* l3b   = (const float*)d_in[17];
    const float* cw    = (const float*)d_in[18];
    const float* cb    = (const float*)d_in[19];
    float* outp = (float*)d_out;

    float *p_in, *p_c1, *p_c2, *p_c3, *p_pool, *p_x1, *p_gi, *p_hs, *p_Tp;
    float *p_wt2, *p_wt3, *p_mx, *p_iv;
    cudaGetSymbolAddress((void**)&p_in,   g_in);
    cudaGetSymbolAddress((void**)&p_c1,   g_c1);
    cudaGetSymbolAddress((void**)&p_c2,   g_c2);
    cudaGetSymbolAddress((void**)&p_c3,   g_c3);
    cudaGetSymbolAddress((void**)&p_pool, g_pool);
    cudaGetSymbolAddress((void**)&p_x1,   g_x1);
    cudaGetSymbolAddress((void**)&p_gi,   g_gi);
    cudaGetSymbolAddress((void**)&p_hs,   g_hs);
    cudaGetSymbolAddress((void**)&p_Tp,   g_Tp);
    cudaGetSymbolAddress((void**)&p_wt2,  g_wt2);
    cudaGetSymbolAddress((void**)&p_wt3,  g_wt3);
    cudaGetSymbolAddress((void**)&p_mx,   g_mx);
    cudaGetSymbolAddress((void**)&p_iv,   g_iv);

    const int smem2 = (8 * 2112 + 2 * 2560) * 4;    // 88,064 B
    const int smem3 = (8 * 4224 + 2 * 10240) * 4;   // 217,088 B
    const int smemp = 5 * 58 * 67 * 4;              // 77,720 B
    const int smemt = 3 * 64 * 68 * 4;              // 52,224 B
    cudaFuncSetAttribute(conv_mma2<16, 32, 508, 124>,
                         cudaFuncAttributeMaxDynamicSharedMemorySize, smem2);
    cudaFuncSetAttribute(conv_mma2<32, 64, 504, 120>,
                         cudaFuncAttributeMaxDynamicSharedMemorySize, smem3);
    cudaFuncSetAttribute(pool_ring,
                         cudaFuncAttributeMaxDynamicSharedMemorySize, smemp);
    cudaFuncSetAttribute(tp_fused,
                         cudaFuncAttributeMaxDynamicSharedMemorySize, smemt);

    prep_kernel<<<dim3(4, 16, 33), dim3(32, 8)>>>(ev, tmpl, c2w, c3w, p_in, p_wt2, p_wt3);
    conv1_nhwc<<<dim3(508, 32), 128>>>(p_in, c1w, c1b, p_c1);
    conv_mma2<16, 32, 508, 124><<<dim3(126, 32), 512, smem2>>>(p_c1, p_wt2, c2b, p_c2);
    conv_mma2<32, 64, 504, 120><<<dim3(125, 32), 512, smem3>>>(p_c2, p_wt3, c3b, p_c3);
    pool_ring<<<dim3(8, 32), 256, smemp>>>(p_c3, p_pool);
    gemm_bias<true><<<dim3(248, 1, 1), 128>>>(p_pool, l1w, l1b, p_x1,
                                              15872, 64, 3712, 0, 0, 0);
    gemm_bias<true><<<dim3(248, 3, 1), 128>>>(p_x1, W_ih, b_ih, p_gi,
                                              15872, 192, 64, 0, 0, 0);
    gru_kernel<<<2, 64>>>(p_gi, W_hh, b_hh, p_hs);
    attn_stats<<<dim3(62, 16), 256>>>(p_hs, p_mx, p_iv);
    tp_fused<<<dim3(8, 16), 256, smemt>>>(p_hs, p_mx, p_iv, p_Tp);
    final_kernel<<<16, 256>>>(p_hs, p_Tp, aw, ab, l3w, l3b, cw, cb, outp);
}

// round 14
// speedup vs baseline: 1.1517x; 1.0420x over previous
#include <cuda_runtime.h>
#include <math.h>
#include <stddef.h>
#include <stdint.h>
#include <string.h>

// ---------------- static scratch (no allocations allowed) ----------------
__device__ float g_in  [(size_t)32*512*128];          // (n, t, c)
__device__ float g_c1  [(size_t)32*508*124*16];       // NHWC
__device__ float g_c2  [(size_t)32*504*120*32];       // NHWC
__device__ float g_c3  [(size_t)32*500*116*64];       // NHWC
__device__ float g_pool[(size_t)32*64*496*58];        // (n, c, s, w) raw reshape layout
__device__ float g_x1  [(size_t)32*496*64];
__device__ float g_gi  [(size_t)32*496*192];
__device__ float g_hs  [(size_t)32*496*64];           // E (n<16) / Tm (n>=16)
__device__ float g_Tp  [(size_t)16*496*64];
__device__ float g_wt2 [(size_t)5*80*32];             // conv2 weights [dy][k8][co][pos]
__device__ float g_wt3 [(size_t)5*160*64];            // conv3 weights [dy][k8][co][pos]
__device__ float g_mx  [16*512];                      // column softmax stats
__device__ float g_iv  [16*512];

__device__ __forceinline__ uint32_t f2tf32(float x)
{
    uint32_t u;
    asm("cvt.rna.tf32.f32 %0, %1;" : "=r"(u) : "f"(x));
    return u;
}

__device__ __forceinline__ unsigned long long fma2(unsigned long long a,
                                                   unsigned long long b,
                                                   unsigned long long c)
{
    unsigned long long d;
    asm("fma.rn.f32x2 %0, %1, %2, %3;" : "=l"(d) : "l"(a), "l"(b), "l"(c));
    return d;
}

__device__ __forceinline__ unsigned long long pack2(float x, float y)
{
    unsigned long long d;
    asm("mov.b64 %0, {%1, %2};" : "=l"(d) : "f"(x), "f"(y));
    return d;
}

__device__ __forceinline__ void unpack2(unsigned long long v, float& x, float& y)
{
    asm("mov.b64 {%0, %1}, %2;" : "=f"(x), "=f"(y) : "l"(v));
}

// ---------------- prep: transpose (z<32) + weight reorders (z==32) ----------------
// B layout (R9): [dy][k>>3][co][pos(k&7)], pos(j) = 2*(j&3) + (j>>2)
__global__ void prep_kernel(const float* __restrict__ ev, const float* __restrict__ tm,
                            const float* __restrict__ c2w, const float* __restrict__ c3w,
                            float* __restrict__ out, float* __restrict__ wt2,
                            float* __restrict__ wt3)
{
    if (blockIdx.z < 32) {
        __shared__ float tile[32][33];
        int n = blockIdx.z;
        const float* src = (n < 16) ? (ev + (size_t)n * 128 * 512)
                                    : (tm + (size_t)(n - 16) * 128 * 512);
        int x0 = blockIdx.x * 32;
        int y0 = blockIdx.y * 32;
        int lx = threadIdx.x, ly = threadIdx.y; // 32 x 8
        for (int r = ly; r < 32; r += 8)
            tile[r][lx] = src[(size_t)(x0 + r) * 512 + y0 + lx];
        __syncthreads();
        float* o = out + (size_t)n * 512 * 128;
        for (int r = ly; r < 32; r += 8)
            o[(size_t)(y0 + r) * 128 + x0 + lx] = tile[lx][r];
    } else {
        int pid = (blockIdx.y * 4 + blockIdx.x) * 256 + threadIdx.y * 32 + threadIdx.x;
        for (int idx = pid; idx < 12800; idx += 16384) {   // conv2: CIN=16, COUT=32
            int dx = idx % 5, dy = (idx / 5) % 5, ci = (idx / 25) % 16, co = idx / 400;
            int k = dx * 16 + ci;
            int j = k & 7;
            int pos = 2 * (j & 3) + (j >> 2);
            wt2[(size_t)dy * (80 * 32) + (k >> 3) * 256 + co * 8 + pos] =
                __uint_as_float(f2tf32(c2w[idx]));
        }
        for (int idx = pid; idx < 51200; idx += 16384) {   // conv3: CIN=32, COUT=64
            int dx = idx % 5, dy = (idx / 5) % 5, ci = (idx / 25) % 32, co = idx / 800;
            int k = dx * 32 + ci;
            int j = k & 7;
            int pos = 2 * (j & 3) + (j >> 2);
            wt3[(size_t)dy * (160 * 64) + (k >> 3) * 512 + co * 8 + pos] =
                __uint_as_float(f2tf32(c3w[idx]));
        }
    }
}

// ---------------- conv1: CIN=1, direct fp32, NHWC out ----------------
__global__ void conv1_nhwc(const float* __restrict__ in, const float* __restrict__ w,
                           const float* __restrict__ bias, float* __restrict__ out)
{
    __shared__ float srow[5][128];
    __shared__ float sw[16][25];
    __shared__ float sb[16];
    int y = blockIdx.x, n = blockIdx.y, tid = threadIdx.x;  // 128 threads
    const float* ip = in + ((size_t)n * 512 + y) * 128;
#pragma unroll
    for (int r = 0; r < 5; r++) srow[r][tid] = ip[(size_t)r * 128 + tid];
    if (tid < 16) sb[tid] = bias[tid];
    for (int e = tid; e < 400; e += 128) sw[e / 25][e % 25] = w[e];
    __syncthreads();
    if (tid >= 124) return;
    float acc[16];
#pragma unroll
    for (int co = 0; co < 16; co++) acc[co] = sb[co];
#pragma unroll
    for (int dy = 0; dy < 5; dy++) {
#pragma unroll
        for (int dx = 0; dx < 5; dx++) {
            float v = srow[dy][tid + dx];
#pragma unroll
            for (int co = 0; co < 16; co++) acc[co] += v * sw[co][dy * 5 + dx];
        }
    }
    float4* op = (float4*)(out + (((size_t)n * 508 + y) * 124 + tid) * 16);
#pragma unroll
    for (int q = 0; q < 4; q++) {
        float4 v; v.x = acc[q*4]; v.y = acc[q*4+1]; v.z = acc[q*4+2]; v.w = acc[q*4+3];
        op[q] = v;
    }
}

// ---------------- implicit-GEMM conv (R9): ldmatrix A-frags, paired-B LDS.64 ---------
template<int CIN, int COUT, int HIN, int WIN>
__global__ __launch_bounds__(512) void conv_mma2(const float* __restrict__ in,
                                                 const float* __restrict__ wt,
                                                 const float* __restrict__ bias,
                                                 float* __restrict__ out)
{
    constexpr int HOUT = HIN - 4, WOUT = WIN - 4;
    constexpr int ROWF = 132 * CIN;
    constexpr int KDY = 5 * CIN;
    constexpr int BSZ = KDY * COUT;
    constexpr int A_SHIFT = (CIN == 32) ? 5 : 4;
    constexpr int MI = (COUT == 64) ? 4 : 2;

    extern __shared__ float smem[];
    float* sA = smem;                 // 8 rows x ROWF
    float* sB = smem + 8 * ROWF;      // 2 x BSZ (double buffer, contiguous layout)
    uint32_t* sAu = (uint32_t*)sA;

    int tid = threadIdx.x;
    int lane = tid & 31, warp = tid >> 5;   // 16 warps
    int y0 = blockIdx.x * 4, n = blockIdx.y;
    int wy = warp >> 2;
    int wsub = warp & 3;
    int mrow, nbase;
    if (COUT == 64) { mrow = (wsub & 1) * 64; nbase = (wsub >> 1) * 32; }
    else            { mrow = wsub * 32;       nbase = 0; }

    int ra = lane >> 2;
    int kfrac = lane & 3;
    int cidx[4];
#pragma unroll
    for (int nj = 0; nj < 4; nj++)
        cidx[nj] = (nbase + nj * 8 + ra) * 4 + kfrac;

    int lrow = lane & 15;
    int lcol = (lane >> 4) * 4;
    int linv[MI];
#pragma unroll
    for (int mi = 0; mi < MI; mi++)
        linv[mi] = (mrow + mi * 16 + lrow) * CIN + lcol;

    uint32_t sA_sh = (uint32_t)__cvta_generic_to_shared(sAu);

    float acc[MI][4][4];
#pragma unroll
    for (int mi = 0; mi < MI; mi++)
#pragma unroll
        for (int nj = 0; nj < 4; nj++)
#pragma unroll
            for (int q = 0; q < 4; q++) acc[mi][nj][q] = 0.f;

    // ---- stage all 8 input rows once (tf32, per-row swizzle) ----
    const int WVALID = WIN * CIN;
    for (int l = tid * 4; l < 8 * ROWF; l += 2048) {
        int rr = l / ROWF, lo = l % ROWF;
        const float* inrow = in + ((size_t)(n * HIN + y0 + rr) * WIN) * CIN;
        float4 v;
        if (lo + 4 <= WVALID) v = *(const float4*)(inrow + lo);
        else { v.x = v.y = v.z = v.w = 0.f; }
        uint4 u;
        u.x = f2tf32(v.x); u.y = f2tf32(v.y); u.z = f2tf32(v.z); u.w = f2tf32(v.w);
        int p = lo ^ (((lo >> A_SHIFT) & 7) << 2);
        *(uint4*)(sAu + rr * ROWF + p) = u;
    }

    // ---- prefetch B[0] via cp.async ----
    for (int l = tid * 4; l < BSZ; l += 2048) {
        uint32_t da = (uint32_t)__cvta_generic_to_shared(sB + l);
        asm volatile("cp.async.ca.shared.global [%0], [%1], 16;\n"
                     :: "r"(da), "l"(wt + l));
    }
    asm volatile("cp.async.commit_group;\n");
    asm volatile("cp.async.wait_group 0;\n");
    __syncthreads();

#pragma unroll 1
    for (int dy = 0; dy < 5; dy++) {
        if (dy < 4) {
            const float* wrow = wt + (size_t)(dy + 1) * BSZ;
            float* dst = sB + ((dy + 1) & 1) * BSZ;
            for (int l = tid * 4; l < BSZ; l += 2048) {
                uint32_t da = (uint32_t)__cvta_generic_to_shared(dst + l);
                asm volatile("cp.async.ca.shared.global [%0], [%1], 16;\n"
                             :: "r"(da), "l"(wrow + l));
            }
            asm volatile("cp.async.commit_group;\n");
        }
        const float2* sB2 = (const float2*)(sB + (dy & 1) * BSZ);

        int abase = (wy + dy) * ROWF;
#pragma unroll
        for (int k8 = 0; k8 < KDY; k8 += 8) {
            uint32_t a[MI][4];
#pragma unroll
            for (int mi = 0; mi < MI; mi++) {
                int l0 = linv[mi] + k8;
                int p = l0 ^ (((l0 >> A_SHIFT) & 7) << 2);
                uint32_t addr = sA_sh + (uint32_t)(abase + p) * 4u;
                asm volatile(
                    "ldmatrix.sync.aligned.m8n8.x4.shared.b16 {%0,%1,%2,%3}, [%4];"
                    : "=r"(a[mi][0]), "=r"(a[mi][1]), "=r"(a[mi][2]), "=r"(a[mi][3])
                    : "r"(addr));
            }
            const float2* pb = sB2 + (k8 >> 3) * (4 * COUT);
#pragma unroll
            for (int nj = 0; nj < 4; nj++) {
                float2 bb = pb[cidx[nj]];
                uint32_t b0 = __float_as_uint(bb.x);
                uint32_t b1 = __float_as_uint(bb.y);
#pragma unroll
                for (int mi = 0; mi < MI; mi++) {
                    asm volatile(
                        "mma.sync.aligned.m16n8k8.row.col.f32.tf32.tf32.f32 "
                        "{%0,%1,%2,%3}, {%4,%5,%6,%7}, {%8,%9}, {%0,%1,%2,%3};"
                        : "+f"(acc[mi][nj][0]), "+f"(acc[mi][nj][1]),
                          "+f"(acc[mi][nj][2]), "+f"(acc[mi][nj][3])
                        : "r"(a[mi][0]), "r"(a[mi][1]), "r"(a[mi][2]), "r"(a[mi][3]),
                          "r"(b0), "r"(b1));
                }
            }
        }
        if (dy < 4) {
            asm volatile("cp.async.wait_group 0;\n");
            __syncthreads();
        }
    }

    int y = y0 + wy;
    size_t obase = ((size_t)(n * HOUT + y) * WOUT) * COUT;
#pragma unroll
    for (int mi = 0; mi < MI; mi++) {
#pragma unroll
        for (int nj = 0; nj < 4; nj++) {
            int x = mrow + mi * 16 + ra;
            int co = nbase + nj * 8 + kfrac * 2;
            float b0 = bias[co], b1 = bias[co + 1];
            if (x < WOUT) {
                float2 v; v.x = acc[mi][nj][0] + b0; v.y = acc[mi][nj][1] + b1;
                *(float2*)(out + obase + (size_t)x * COUT + co) = v;
            }
            if (x + 8 < WOUT) {
                float2 v; v.x = acc[mi][nj][2] + b0; v.y = acc[mi][nj][3] + b1;
                *(float2*)(out + obase + (size_t)(x + 8) * COUT + co) = v;
            }
        }
    }
}

// ---------------- maxpool ring: each conv3 row read once ----------------
__global__ void pool_ring(const float* __restrict__ in, float* __restrict__ out)
{
    extern __shared__ float ring[];   // 5 x (58*67)
    const int RP = 58 * 67;
    int strip = blockIdx.x, n = blockIdx.y, tid = threadIdx.x; // 256 threads
    int s0 = strip * 62;
    float* ob = out + (size_t)n * 64 * 496 * 58;
    for (int y = s0; y < s0 + 66; y++) {
        const float* ip = in + ((size_t)(n * 500 + y) * 116) * 64;
        int rr = (y - s0) % 5;
        for (int idx = tid; idx < 3712; idx += 256) {
            int wp = idx >> 6, c = idx & 63;
            float a = ip[(size_t)(2 * wp) * 64 + c];
            float b = ip[(size_t)(2 * wp) * 64 + 64 + c];
            ring[rr * RP + wp * 67 + c] = fmaxf(a, b);
        }
        __syncthreads();
        if (y - s0 >= 4) {
            int s = y - 4;
            for (int f = tid; f < 3712; f += 256) {
                int c = f / 58, wp = f % 58;
                int o = wp * 67 + c;
                float m = ring[o];
                m = fmaxf(m, ring[RP + o]);
                m = fmaxf(m, ring[2 * RP + o]);
                m = fmaxf(m, ring[3 * RP + o]);
                m = fmaxf(m, ring[4 * RP + o]);
                ob[(size_t)c * 496 * 58 + (size_t)s * 58 + wp] = m;
            }
        }
        __syncthreads();
    }
}

// ---------------- lin1: split-tf32 MMA GEMM, M=15872 K=3712 N=64 (R7) ----------------
__global__ __launch_bounds__(256) void lin1_mma(const float* __restrict__ A,
                                                const float* __restrict__ W,
                                                const float* __restrict__ bias,
                                                float* __restrict__ C)
{
    const int K = 3712;
    __shared__ float sAhi[128 * 20], sAlo[128 * 20];
    __shared__ float sBhi[16 * 72], sBlo[16 * 72];
    int tid = threadIdx.x;
    int lane = tid & 31, warp = tid >> 5;      // 8 warps
    int m0 = blockIdx.x * 128;
    int mrow = (warp & 3) * 32;
    int nbase = (warp >> 2) * 32;

    float acc[2][4][4];
#pragma unroll
    for (int mi = 0; mi < 2; mi++)
#pragma unroll
        for (int nj = 0; nj < 4; nj++)
#pragma unroll
            for (int q = 0; q < 4; q++) acc[mi][nj][q] = 0.f;

    for (int k0 = 0; k0 < K; k0 += 16) {
#pragma unroll
        for (int pass = 0; pass < 2; pass++) {
            int l = tid * 4 + pass * 1024;
            int row = l >> 4, kk = l & 15;
            float4 v = *(const float4*)(A + (size_t)(m0 + row) * K + k0 + kk);
            float hx = __uint_as_float(f2tf32(v.x));
            float hy = __uint_as_float(f2tf32(v.y));
            float hz = __uint_as_float(f2tf32(v.z));
            float hw = __uint_as_float(f2tf32(v.w));
            float* ph = sAhi + row * 20 + kk;
            float* pl = sAlo + row * 20 + kk;
            ph[0] = hx; ph[1] = hy; ph[2] = hz; ph[3] = hw;
            pl[0] = __uint_as_float(f2tf32(v.x - hx));
            pl[1] = __uint_as_float(f2tf32(v.y - hy));
            pl[2] = __uint_as_float(f2tf32(v.z - hz));
            pl[3] = __uint_as_float(f2tf32(v.w - hw));
        }
        {
            int l = tid * 4;
            int jn = l >> 4, kk = l & 15;
            float4 v = *(const float4*)(W + (size_t)jn * K + k0 + kk);
            float h0 = __uint_as_float(f2tf32(v.x));
            float h1 = __uint_as_float(f2tf32(v.y));
            float h2 = __uint_as_float(f2tf32(v.z));
            float h3 = __uint_as_float(f2tf32(v.w));
            sBhi[(kk + 0) * 72 + jn] = h0;
            sBhi[(kk + 1) * 72 + jn] = h1;
            sBhi[(kk + 2) * 72 + jn] = h2;
            sBhi[(kk + 3) * 72 + jn] = h3;
            sBlo[(kk + 0) * 72 + jn] = __uint_as_float(f2tf32(v.x - h0));
            sBlo[(kk + 1) * 72 + jn] = __uint_as_float(f2tf32(v.y - h1));
            sBlo[(kk + 2) * 72 + jn] = __uint_as_float(f2tf32(v.z - h2));
            sBlo[(kk + 3) * 72 + jn] = __uint_as_float(f2tf32(v.w - h3));
        }
        __syncthreads();

#pragma unroll
        for (int k8 = 0; k8 < 16; k8 += 8) {
            int ra = lane >> 2, ca = k8 + (lane & 3);
            uint32_t ah[2][4], al[2][4];
#pragma unroll
            for (int mi = 0; mi < 2; mi++) {
                int r0 = mrow + mi * 16 + ra;
                ah[mi][0] = __float_as_uint(sAhi[r0 * 20 + ca]);
                ah[mi][1] = __float_as_uint(sAhi[(r0 + 8) * 20 + ca]);
                ah[mi][2] = __float_as_uint(sAhi[r0 * 20 + ca + 4]);
                ah[mi][3] = __float_as_uint(sAhi[(r0 + 8) * 20 + ca + 4]);
                al[mi][0] = __float_as_uint(sAlo[r0 * 20 + ca]);
                al[mi][1] = __float_as_uint(sAlo[(r0 + 8) * 20 + ca]);
                al[mi][2] = __float_as_uint(sAlo[r0 * 20 + ca + 4]);
                al[mi][3] = __float_as_uint(sAlo[(r0 + 8) * 20 + ca + 4]);
            }
            int kb = k8 + (lane & 3);
#pragma unroll
            for (int nj = 0; nj < 4; nj++) {
                int cn = nbase + nj * 8 + (lane >> 2);
                uint32_t bh0 = __float_as_uint(sBhi[kb * 72 + cn]);
                uint32_t bh1 = __float_as_uint(sBhi[(kb + 4) * 72 + cn]);
                uint32_t bl0 = __float_as_uint(sBlo[kb * 72 + cn]);
                uint32_t bl1 = __float_as_uint(sBlo[(kb + 4) * 72 + cn]);
#pragma unroll
                for (int mi = 0; mi < 2; mi++) {
#define LIN1_MMA(AV0,AV1,AV2,AV3,BV0,BV1) \
    asm volatile("mma.sync.aligned.m16n8k8.row.col.f32.tf32.tf32.f32 " \
                 "{%0,%1,%2,%3}, {%4,%5,%6,%7}, {%8,%9}, {%0,%1,%2,%3};" \
                 : "+f"(acc[mi][nj][0]), "+f"(acc[mi][nj][1]), \
                   "+f"(acc[mi][nj][2]), "+f"(acc[mi][nj][3]) \
                 : "r"(AV0), "r"(AV1), "r"(AV2), "r"(AV3), "r"(BV0), "r"(BV1))
                    LIN1_MMA(ah[mi][0], ah[mi][1], ah[mi][2], ah[mi][3], bh0, bh1);
                    LIN1_MMA(ah[mi][0], ah[mi][1], ah[mi][2], ah[mi][3], bl0, bl1);
                    LIN1_MMA(al[mi][0], al[mi][1], al[mi][2], al[mi][3], bh0, bh1);
#undef LIN1_MMA
                }
            }
        }
        __syncthreads();
    }

#pragma unroll
    for (int mi = 0; mi < 2; mi++) {
#pragma unroll
        for (int nj = 0; nj < 4; nj++) {
            int x = mrow + mi * 16 + (lane >> 2);
            int co = nbase + nj * 8 + (lane & 3) * 2;
            float b0 = bias[co], b1 = bias[co + 1];
            float2 v0; v0.x = acc[mi][nj][0] + b0; v0.y = acc[mi][nj][1] + b1;
            *(float2*)(C + (size_t)(m0 + x) * 64 + co) = v0;
            float2 v1; v1.x = acc[mi][nj][2] + b0; v1.y = acc[mi][nj][3] + b1;
            *(float2*)(C + (size_t)(m0 + x + 8) * 64 + co) = v1;
        }
    }
}

// ---------------- tiled SIMT GEMM (gi): pack-at-use f32x2 (R9) ----------------
template<bool WT>
__global__ void gemm_bias(const float* __restrict__ A, const float* __restrict__ Bm,
                          const float* __restrict__ bias, float* __restrict__ C,
                          int M, int N, int K, long sA, long sB, long sC)
{
    A  += (long)blockIdx.z * sA;
    Bm += (long)blockIdx.z * sB;
    C  += (long)blockIdx.z * sC;
    __shared__ __align__(16) float sAi[64][17];
    __shared__ __align__(16) float sBi[16][68];
    int tid = threadIdx.x;          // 128
    int ttx = tid & 15, tty = tid >> 4;
    int m0 = blockIdx.x * 64, n0 = blockIdx.y * 64;
    unsigned long long acc2[8][2];
#pragma unroll
    for (int i = 0; i < 8; i++) { acc2[i][0] = 0ull; acc2[i][1] = 0ull; }

    for (int k0 = 0; k0 < K; k0 += 16) {
#pragma unroll
        for (int l = 0; l < 8; l++) {
            int e = tid + l * 128;
            int mm = e >> 4, kk = e & 15;
            int m = m0 + mm;
            sAi[mm][kk] = (m < M) ? A[(long)m * K + k0 + kk] : 0.f;
        }
#pragma unroll
        for (int l = 0; l < 8; l++) {
            int e = tid + l * 128;
            if (WT) {
                int j = e >> 4, kk = e & 15;
                int jn = n0 + j;
                sBi[kk][j] = (jn < N) ? Bm[(long)jn * K + k0 + kk] : 0.f;
            } else {
                int kk = e >> 6, j = e & 63;
                int jn = n0 + j;
                sBi[kk][j] = (jn < N) ? Bm[(long)(k0 + kk) * N + jn] : 0.f;
            }
        }
        __syncthreads();
#pragma unroll
        for (int kk = 0; kk < 16; kk++) {
            unsigned long long b0 = *(const unsigned long long*)&sBi[kk][ttx * 4];
            unsigned long long b1 = *(const unsigned long long*)&sBi[kk][ttx * 4 + 2];
#pragma unroll
            for (int i = 0; i < 8; i++) {
                float as = sAi[tty * 8 + i][kk];
                unsigned long long ap = pack2(as, as);
                acc2[i][0] = fma2(ap, b0, acc2[i][0]);
                acc2[i][1] = fma2(ap, b1, acc2[i][1]);
            }
        }
        __syncthreads();
    }
#pragma unroll
    for (int i = 0; i < 8; i++) {
        int m = m0 + tty * 8 + i;
        if (m < M) {
            int j0 = n0 + ttx * 4;
            float4 v;
            unpack2(acc2[i][0], v.x, v.y);
            unpack2(acc2[i][1], v.z, v.w);
            v.x += bias ? bias[j0 + 0] : 0.f;
            v.y += bias ? bias[j0 + 1] : 0.f;
            v.z += bias ? bias[j0 + 2] : 0.f;
            v.w += bias ? bias[j0 + 3] : 0.f;
            *(float4*)&C[(long)m * N + j0] = v;
        }
    }
}

// ---------------- GRU (R9): 192 thr, packed f32x2 dot, fast activations --------------
__global__ void gru_kernel(const float* __restrict__ gi, const float* __restrict__ W_hh,
                           const float* __restrict__ b_hh, float* __restrict__ hs)
{
    int branch = blockIdx.x;
    int i = threadIdx.x; // 0..191
    const float* g = gi + (size_t)branch * (16 * 496 * 192);
    float* out = hs + (size_t)branch * (16 * 496 * 64);

    unsigned long long w2[32];
    const float2* wr = (const float2*)(W_hh + (size_t)i * 64);
#pragma unroll
    for (int k = 0; k < 32; k++) {
        float2 p = wr[k];
        memcpy(&w2[k], &p, 8);
    }
    float bh = b_hh[i];

    __shared__ __align__(16) float h_sh[64];
    __shared__ float r_sh[64], z_sh[64];
    if (i < 64) h_sh[i] = 0.f;
    __syncthreads();

    const int L = 16 * 496;
    float gcur = g[i];
    for (int t = 0; t < L; t++) {
        float gnext = (t + 1 < L) ? g[(size_t)(t + 1) * 192 + i] : 0.f;
        unsigned long long a0 = 0, a1 = 0, a2 = 0, a3 = 0;
        const ulonglong2* hp = (const ulonglong2*)h_sh;
#pragma unroll
        for (int q = 0; q < 16; q += 2) {
            ulonglong2 hA = hp[q];
            ulonglong2 hB = hp[q + 1];
            a0 = fma2(w2[2 * q + 0], hA.x, a0);
            a1 = fma2(w2[2 * q + 1], hA.y, a1);
            a2 = fma2(w2[2 * q + 2], hB.x, a2);
            a3 = fma2(w2[2 * q + 3], hB.y, a3);
        }
        float s;
        {
            float x0, x1, y0, y1, u0, u1, v0, v1;
            unpack2(a0, x0, x1);
            unpack2(a1, y0, y1);
            unpack2(a2, u0, u1);
            unpack2(a3, v0, v1);
            s = ((x0 + x1) + (y0 + y1)) + ((u0 + u1) + (v0 + v1)) + bh;
        }
        if (i < 64) {
            r_sh[i] = __fdividef(1.f, 1.f + __expf(-(gcur + s)));
        } else if (i < 128) {
            z_sh[i - 64] = __fdividef(1.f, 1.f + __expf(-(gcur + s)));
        }
        __syncthreads();
        if (i >= 128) {
            int j = i - 128;
            float x = gcur + r_sh[j] * s;
            float e = __expf(-2.f * fabsf(x));
            float nt = __fdividef(1.f - e, 1.f + e);
            nt = copysignf(nt, x);
            float z = z_sh[j];
            float hn = (1.f - z) * nt + z * h_sh[j];
            h_sh[j] = hn;
            out[(size_t)t * 64 + j] = hn;
        }
        __syncthreads();
        gcur = gnext;
    }
}

// ---------------- attention stats: column max & inv-sum of exp ----------------
__global__ void attn_stats(const float* __restrict__ hs, float* __restrict__ mxo,
                           float* __restrict__ ivo)
{
    int b = blockIdx.y;
    int n0 = blockIdx.x * 8;
    const float* E  = hs + (size_t)b * 496 * 64;
    const float* Tm = hs + (size_t)(16 + b) * 496 * 64;
    __shared__ float tm_sh[8][64];
    __shared__ float lg[496][9];
    int tid = threadIdx.x; // 256
    for (int e = tid; e < 8 * 64; e += 256)
        tm_sh[e >> 6][e & 63] = Tm[(size_t)(n0 + (e >> 6)) * 64 + (e & 63)];
    __syncthreads();
    for (int m = tid; m < 496; m += 256) {
        const float4* Er = (const float4*)(E + (size_t)m * 64);
        float acc[8];
#pragma unroll
        for (int nn = 0; nn < 8; nn++) acc[nn] = 0.f;
#pragma unroll
        for (int j4 = 0; j4 < 16; j4++) {
            float4 v = Er[j4];
#pragma unroll
            for (int nn = 0; nn < 8; nn++) {
                acc[nn] += v.x * tm_sh[nn][j4 * 4 + 0];
                acc[nn] += v.y * tm_sh[nn][j4 * 4 + 1];
                acc[nn] += v.z * tm_sh[nn][j4 * 4 + 2];
                acc[nn] += v.w * tm_sh[nn][j4 * 4 + 3];
            }
        }
#pragma unroll
        for (int nn = 0; nn < 8; nn++) lg[m][nn] = acc[nn];
    }
    __syncthreads();
    int wg = tid >> 5, lane = tid & 31;
    float mx = -INFINITY;
    for (int m = lane; m < 496; m += 32) mx = fmaxf(mx, lg[m][wg]);
#pragma unroll
    for (int o = 16; o; o >>= 1) mx = fmaxf(mx, __shfl_xor_sync(0xffffffffu, mx, o));
    float sum = 0.f;
    for (int m = lane; m < 496; m += 32) sum += __expf(lg[m][wg] - mx);
#pragma unroll
    for (int o = 16; o; o >>= 1) sum += __shfl_xor_sync(0xffffffffu, sum, o);
    if (lane == 0) {
        mxo[b * 512 + n0 + wg] = mx;
        ivo[b * 512 + n0 + wg] = 1.f / sum;
    }
}

// ---------------- fused Tp: recompute logits, exp, contract with Tm ----------------
__global__ __launch_bounds__(256) void tp_fused(const float* __restrict__ hs,
                                                const float* __restrict__ mxv,
                                                const float* __restrict__ ivv,
                                                float* __restrict__ Tp)
{
    extern __shared__ float sm[];
    float* sE  = sm;               // 64 x 68
    float* sTm = sm + 64 * 68;     // 64 x 68
    float* sP  = sm + 2 * 64 * 68; // 64 x 68
    int b = blockIdx.y;
    int m0 = blockIdx.x * 64;
    const float* E  = hs + (size_t)b * 496 * 64;
    const float* Tm = hs + (size_t)(16 + b) * 496 * 64;
    int tid = threadIdx.x;
    int tx = tid & 15, ty = tid >> 4;

    for (int e = tid; e < 64 * 16; e += 256) {
        int r = e >> 4, c4 = (e & 15) * 4;
        float4 v = (m0 + r < 496) ? *(const float4*)(E + (size_t)(m0 + r) * 64 + c4)
                                  : make_float4(0.f, 0.f, 0.f, 0.f);
        *(float4*)&sE[r * 68 + c4] = v;
    }

    float acc[4][4];
#pragma unroll
    for (int ii = 0; ii < 4; ii++)
#pragma unroll
        for (int dd = 0; dd < 4; dd++) acc[ii][dd] = 0.f;

    for (int n0 = 0; n0 < 496; n0 += 64) {
        for (int e = tid; e < 64 * 16; e += 256) {
            int r = e >> 4, c4 = (e & 15) * 4;
            float4 v = (n0 + r < 496) ? *(const float4*)(Tm + (size_t)(n0 + r) * 64 + c4)
                                      : make_float4(0.f, 0.f, 0.f, 0.f);
            *(float4*)&sTm[r * 68 + c4] = v;
        }
        __syncthreads();

        float s4[4][4];
#pragma unroll
        for (int ii = 0; ii < 4; ii++)
#pragma unroll
            for (int jj = 0; jj < 4; jj++) s4[ii][jj] = 0.f;
#pragma unroll
        for (int k4 = 0; k4 < 16; k4++) {
            float4 a[4], bb[4];
#pragma unroll
            for (int ii = 0; ii < 4; ii++)
                a[ii] = *(float4*)&sE[(ty * 4 + ii) * 68 + k4 * 4];
#pragma unroll
            for (int jj = 0; jj < 4; jj++)
                bb[jj] = *(float4*)&sTm[(tx * 4 + jj) * 68 + k4 * 4];
#pragma unroll
            for (int ii = 0; ii < 4; ii++)
#pragma unroll
                for (int jj = 0; jj < 4; jj++)
                    s4[ii][jj] += a[ii].x * bb[jj].x + a[ii].y * bb[jj].y
                                + a[ii].z * bb[jj].z + a[ii].w * bb[jj].w;
        }
#pragma unroll
        for (int jj = 0; jj < 4; jj++) {
            int nn = n0 + tx * 4 + jj;
            float mxn = (nn < 496) ? mxv[b * 512 + nn] : 0.f;
            float ivn = (nn < 496) ? ivv[b * 512 + nn] : 0.f;
#pragma unroll
            for (int ii = 0; ii < 4; ii++)
                sP[(ty * 4 + ii) * 68 + tx * 4 + jj] =
                    (nn < 496) ? __expf(s4[ii][jj] - mxn) * ivn : 0.f;
        }
        __syncthreads();
#pragma unroll 2
        for (int j = 0; j < 64; j++) {
            float4 bv = *(float4*)&sTm[j * 68 + tx * 4];
            float p0 = sP[(ty * 4 + 0) * 68 + j];
            float p1 = sP[(ty * 4 + 1) * 68 + j];
            float p2 = sP[(ty * 4 + 2) * 68 + j];
            float p3 = sP[(ty * 4 + 3) * 68 + j];
            acc[0][0] += p0 * bv.x; acc[0][1] += p0 * bv.y; acc[0][2] += p0 * bv.z; acc[0][3] += p0 * bv.w;
            acc[1][0] += p1 * bv.x; acc[1][1] += p1 * bv.y; acc[1][2] += p1 * bv.z; acc[1][3] += p1 * bv.w;
            acc[2][0] += p2 * bv.x; acc[2][1] += p2 * bv.y; acc[2][2] += p2 * bv.z; acc[2][3] += p2 * bv.w;
            acc[3][0] += p3 * bv.x; acc[3][1] += p3 * bv.y; acc[3][2] += p3 * bv.z; acc[3][3] += p3 * bv.w;
        }
        __syncthreads();
    }
#pragma unroll
    for (int ii = 0; ii < 4; ii++) {
        int m = m0 + ty * 4 + ii;
        if (m < 496) {
            float4 v; v.x = acc[ii][0]; v.y = acc[ii][1]; v.z = acc[ii][2]; v.w = acc[ii][3];
            *(float4*)&Tp[((size_t)b * 496 + m) * 64 + tx * 4] = v;
        }
    }
}

// ---------------- fused head ----------------
__global__ void final_kernel(const float* __restrict__ hs, const float* __restrict__ Tp,
                             const float* __restrict__ aw, const float* __restrict__ ab,
                             const float* __restrict__ l3w, const float* __restrict__ l3b,
                             const float* __restrict__ cw, const float* __restrict__ cb,
                             float* __restrict__ outp)
{
    int b = blockIdx.x;
    int tid = threadIdx.x; // 256
    const float* E   = hs + (size_t)b * 496 * 64;
    const float* Tpb = Tp + (size_t)b * 496 * 64;
    __shared__ float att[496];
    __shared__ float red[256];
    __shared__ float part[4][64];
    __shared__ float hrep[64];
    __shared__ float h2[128];
    __shared__ float aw_sh[64];
    if (tid < 64) aw_sh[tid] = aw[tid];
    __syncthreads();
    float lmax = -INFINITY;
    for (int s = tid; s < 496; s += 256) {
        const float* er = E + (size_t)s * 64;
        float acc = ab[0];
#pragma unroll
        for (int j = 0; j < 64; j++) acc += er[j] * aw_sh[j];
        att[s] = acc;
        lmax = fmaxf(lmax, acc);
    }
    red[tid] = lmax;
    __syncthreads();
    for (int o = 128; o; o >>= 1) {
        if (tid < o) red[tid] = fmaxf(red[tid], red[tid + o]);
        __syncthreads();
    }
    float mx = red[0];
    __syncthreads();
    float lsum = 0.f;
    for (int s = tid; s < 496; s += 256) {
        float e = __expf(att[s] - mx);
        att[s] = e;
        lsum += e;
    }
    red[tid] = lsum;
    __syncthreads();
    for (int o = 128; o; o >>= 1) {
        if (tid < o) red[tid] += red[tid + o];
        __syncthreads();
    }
    float inv = 1.f / red[0];
    int d = tid & 63, grp = tid >> 6;
    float acc = 0.f;
    for (int s = grp; s < 496; s += 4)
        acc += att[s] * fabsf(Tpb[(size_t)s * 64 + d] - E[(size_t)s * 64 + d]);
    part[grp][d] = acc;
    __syncthreads();
    if (tid < 64) {
        float r = (part[0][tid] + part[1][tid] + part[2][tid] + part[3][tid]) * inv;
        hrep[tid] = fmaxf(r, 0.f);
    }
    __syncthreads();
    if (tid < 128) {
        float a2 = l3b[tid];
#pragma unroll
        for (int j = 0; j < 64; j++) a2 += hrep[j] * l3w[(size_t)tid * 64 + j];
        h2[tid] = fmaxf(a2, 0.f);
    }
    __syncthreads();
    if (tid < 2) {
        float a3 = cb[tid];
#pragma unroll
        for (int j = 0; j < 128; j++) a3 += h2[j] * cw[(size_t)tid * 128 + j];
        outp[b * 2 + tid] = a3;
    }
}

// ---------------- launch ----------------
extern "C" void kernel_launch(void* const* d_in, const int* in_sizes, int n_in,
                              void* d_out, int out_size)
{
    const float* ev    = (const float*)d_in[0];
    const float* tmpl  = (const float*)d_in[1];
    const float* c1w   = (const float*)d_in[2];
    const float* c1b   = (const float*)d_in[3];
    const float* c2w   = (const float*)d_in[4];
    const float* c2b   = (const float*)d_in[5];
    const float* c3w   = (const float*)d_in[6];
    const float* c3b   = (const float*)d_in[7];
    const float* l1w   = (const float*)d_in[8];
    const float* l1b   = (const float*)d_in[9];
    const float* W_ih  = (const float*)d_in[10];
    const float* W_hh  = (const float*)d_in[11];
    const float* b_ih  = (const float*)d_in[12];
    const float* b_hh  = (const float*)d_in[13];
    const float* aw    = (const float*)d_in[14];
    const float* ab    = (const float*)d_in[15];
    const float* l3w   = (const float*)d_in[16];
    const float* l3b   = (const float*)d_in[17];
    const float* cw    = (const float*)d_in[18];
    const float* cb    = (const float*)d_in[19];
    float* outp = (float*)d_out;

    float *p_in, *p_c1, *p_c2, *p_c3, *p_pool, *p_x1, *p_gi, *p_hs, *p_Tp;
    float *p_wt2, *p_wt3, *p_mx, *p_iv;
    cudaGetSymbolAddress((void**)&p_in,   g_in);
    cudaGetSymbolAddress((void**)&p_c1,   g_c1);
    cudaGetSymbolAddress((void**)&p_c2,   g_c2);
    cudaGetSymbolAddress((void**)&p_c3,   g_c3);
    cudaGetSymbolAddress((void**)&p_pool, g_pool);
    cudaGetSymbolAddress((void**)&p_x1,   g_x1);
    cudaGetSymbolAddress((void**)&p_gi,   g_gi);
    cudaGetSymbolAddress((void**)&p_hs,   g_hs);
    cudaGetSymbolAddress((void**)&p_Tp,   g_Tp);
    cudaGetSymbolAddress((void**)&p_wt2,  g_wt2);
    cudaGetSymbolAddress((void**)&p_wt3,  g_wt3);
    cudaGetSymbolAddress((void**)&p_mx,   g_mx);
    cudaGetSymbolAddress((void**)&p_iv,   g_iv);

    const int smem2 = (8 * 2112 + 2 * 2560) * 4;    // 88,064 B
    const int smem3 = (8 * 4224 + 2 * 10240) * 4;   // 217,088 B
    const int smemp = 5 * 58 * 67 * 4;              // 77,720 B
    const int smemt = 3 * 64 * 68 * 4;              // 52,224 B
    cudaFuncSetAttribute(conv_mma2<16, 32, 508, 124>,
                         cudaFuncAttributeMaxDynamicSharedMemorySize, smem2);
    cudaFuncSetAttribute(conv_mma2<32, 64, 504, 120>,
                         cudaFuncAttributeMaxDynamicSharedMemorySize, smem3);
    cudaFuncSetAttribute(pool_ring,
                         cudaFuncAttributeMaxDynamicSharedMemorySize, smemp);
    cudaFuncSetAttribute(tp_fused,
                         cudaFuncAttributeMaxDynamicSharedMemorySize, smemt);

    prep_kernel<<<dim3(4, 16, 33), dim3(32, 8)>>>(ev, tmpl, c2w, c3w, p_in, p_wt2, p_wt3);
    conv1_nhwc<<<dim3(508, 32), 128>>>(p_in, c1w, c1b, p_c1);
    conv_mma2<16, 32, 508, 124><<<dim3(126, 32), 512, smem2>>>(p_c1, p_wt2, c2b, p_c2);
    conv_mma2<32, 64, 504, 120><<<dim3(125, 32), 512, smem3>>>(p_c2, p_wt3, c3b, p_c3);
    pool_ring<<<dim3(8, 32), 256, smemp>>>(p_c3, p_pool);
    lin1_mma<<<124, 256>>>(p_pool, l1w, l1b, p_x1);
    gemm_bias<true><<<dim3(248, 3, 1), 128>>>(p_x1, W_ih, b_ih, p_gi,
                                              15872, 192, 64, 0, 0, 0);
    gru_kernel<<<2, 192>>>(p_gi, W_hh, b_hh, p_hs);
    attn_stats<<<dim3(62, 16), 256>>>(p_hs, p_mx, p_iv);
    tp_fused<<<dim3(8, 16), 256, smemt>>>(p_hs, p_mx, p_iv, p_Tp);
    final_kernel<<<16, 256>>>(p_hs, p_Tp, aw, ab, l3w, l3b, cw, cb, outp);
}

// round 15
// speedup vs baseline: 1.1678x; 1.0140x over previous
#include <cuda_runtime.h>
#include <math.h>
#include <stddef.h>
#include <stdint.h>
#include <string.h>

// ---------------- static scratch (no allocations allowed) ----------------
__device__ float g_in  [(size_t)32*512*128];          // (n, t, c)
__device__ float g_c1  [(size_t)32*508*124*16];       // NHWC
__device__ float g_c2  [(size_t)32*504*120*32];       // NHWC
__device__ float g_c3  [(size_t)32*500*116*64];       // NHWC
__device__ float g_pool[(size_t)32*64*496*58];        // (n, c, s, w) raw reshape layout
__device__ float g_x1  [(size_t)32*496*64];
__device__ float g_gi  [(size_t)32*496*192];
__device__ float g_hs  [(size_t)32*496*64];           // E (n<16) / Tm (n>=16)
__device__ float g_Tp  [(size_t)16*496*64];
__device__ float g_wt2 [(size_t)5*80*32];             // conv2 weights [dy][k8][co][pos]
__device__ float g_wt3 [(size_t)5*160*64];            // conv3 weights [dy][k8][co][pos]
__device__ float g_mx  [16*512];                      // column softmax stats
__device__ float g_iv  [16*512];

__device__ __forceinline__ uint32_t f2tf32(float x)
{
    uint32_t u;
    asm("cvt.rna.tf32.f32 %0, %1;" : "=r"(u) : "f"(x));
    return u;
}

__device__ __forceinline__ unsigned long long fma2(unsigned long long a,
                                                   unsigned long long b,
                                                   unsigned long long c)
{
    unsigned long long d;
    asm("fma.rn.f32x2 %0, %1, %2, %3;" : "=l"(d) : "l"(a), "l"(b), "l"(c));
    return d;
}

__device__ __forceinline__ unsigned long long pack2(float x, float y)
{
    unsigned long long d;
    asm("mov.b64 %0, {%1, %2};" : "=l"(d) : "f"(x), "f"(y));
    return d;
}

__device__ __forceinline__ void unpack2(unsigned long long v, float& x, float& y)
{
    asm("mov.b64 {%0, %1}, %2;" : "=f"(x), "=f"(y) : "l"(v));
}

// ---------------- prep: transpose (z<32) + weight reorders (z==32) ----------------
// B layout (R9): [dy][k>>3][co][pos(k&7)], pos(j) = 2*(j&3) + (j>>2)
__global__ void prep_kernel(const float* __restrict__ ev, const float* __restrict__ tm,
                            const float* __restrict__ c2w, const float* __restrict__ c3w,
                            float* __restrict__ out, float* __restrict__ wt2,
                            float* __restrict__ wt3)
{
    if (blockIdx.z < 32) {
        __shared__ float tile[32][33];
        int n = blockIdx.z;
        const float* src = (n < 16) ? (ev + (size_t)n * 128 * 512)
                                    : (tm + (size_t)(n - 16) * 128 * 512);
        int x0 = blockIdx.x * 32;
        int y0 = blockIdx.y * 32;
        int lx = threadIdx.x, ly = threadIdx.y; // 32 x 8
        for (int r = ly; r < 32; r += 8)
            tile[r][lx] = src[(size_t)(x0 + r) * 512 + y0 + lx];
        __syncthreads();
        float* o = out + (size_t)n * 512 * 128;
        for (int r = ly; r < 32; r += 8)
            o[(size_t)(y0 + r) * 128 + x0 + lx] = tile[lx][r];
    } else {
        int pid = (blockIdx.y * 4 + blockIdx.x) * 256 + threadIdx.y * 32 + threadIdx.x;
        for (int idx = pid; idx < 12800; idx += 16384) {   // conv2: CIN=16, COUT=32
            int dx = idx % 5, dy = (idx / 5) % 5, ci = (idx / 25) % 16, co = idx / 400;
            int k = dx * 16 + ci;
            int j = k & 7;
            int pos = 2 * (j & 3) + (j >> 2);
            wt2[(size_t)dy * (80 * 32) + (k >> 3) * 256 + co * 8 + pos] =
                __uint_as_float(f2tf32(c2w[idx]));
        }
        for (int idx = pid; idx < 51200; idx += 16384) {   // conv3: CIN=32, COUT=64
            int dx = idx % 5, dy = (idx / 5) % 5, ci = (idx / 25) % 32, co = idx / 800;
            int k = dx * 32 + ci;
            int j = k & 7;
            int pos = 2 * (j & 3) + (j >> 2);
            wt3[(size_t)dy * (160 * 64) + (k >> 3) * 512 + co * 8 + pos] =
                __uint_as_float(f2tf32(c3w[idx]));
        }
    }
}

// ---------------- conv1: CIN=1, direct fp32, NHWC out ----------------
__global__ void conv1_nhwc(const float* __restrict__ in, const float* __restrict__ w,
                           const float* __restrict__ bias, float* __restrict__ out)
{
    __shared__ float srow[5][128];
    __shared__ float sw[16][25];
    __shared__ float sb[16];
    int y = blockIdx.x, n = blockIdx.y, tid = threadIdx.x;  // 128 threads
    const float* ip = in + ((size_t)n * 512 + y) * 128;
#pragma unroll
    for (int r = 0; r < 5; r++) srow[r][tid] = ip[(size_t)r * 128 + tid];
    if (tid < 16) sb[tid] = bias[tid];
    for (int e = tid; e < 400; e += 128) sw[e / 25][e % 25] = w[e];
    __syncthreads();
    if (tid >= 124) return;
    float acc[16];
#pragma unroll
    for (int co = 0; co < 16; co++) acc[co] = sb[co];
#pragma unroll
    for (int dy = 0; dy < 5; dy++) {
#pragma unroll
        for (int dx = 0; dx < 5; dx++) {
            float v = srow[dy][tid + dx];
#pragma unroll
            for (int co = 0; co < 16; co++) acc[co] += v * sw[co][dy * 5 + dx];
        }
    }
    float4* op = (float4*)(out + (((size_t)n * 508 + y) * 124 + tid) * 16);
#pragma unroll
    for (int q = 0; q < 4; q++) {
        float4 v; v.x = acc[q*4]; v.y = acc[q*4+1]; v.z = acc[q*4+2]; v.w = acc[q*4+3];
        op[q] = v;
    }
}

// ---------------- implicit-GEMM conv (R9): ldmatrix A-frags, paired-B LDS.64 ---------
template<int CIN, int COUT, int HIN, int WIN>
__global__ __launch_bounds__(512) void conv_mma2(const float* __restrict__ in,
                                                 const float* __restrict__ wt,
                                                 const float* __restrict__ bias,
                                                 float* __restrict__ out)
{
    constexpr int HOUT = HIN - 4, WOUT = WIN - 4;
    constexpr int ROWF = 132 * CIN;
    constexpr int KDY = 5 * CIN;
    constexpr int BSZ = KDY * COUT;
    constexpr int A_SHIFT = (CIN == 32) ? 5 : 4;
    constexpr int MI = (COUT == 64) ? 4 : 2;

    extern __shared__ float smem[];
    float* sA = smem;                 // 8 rows x ROWF
    float* sB = smem + 8 * ROWF;      // 2 x BSZ (double buffer, contiguous layout)
    uint32_t* sAu = (uint32_t*)sA;

    int tid = threadIdx.x;
    int lane = tid & 31, warp = tid >> 5;   // 16 warps
    int y0 = blockIdx.x * 4, n = blockIdx.y;
    int wy = warp >> 2;
    int wsub = warp & 3;
    int mrow, nbase;
    if (COUT == 64) { mrow = (wsub & 1) * 64; nbase = (wsub >> 1) * 32; }
    else            { mrow = wsub * 32;       nbase = 0; }

    int ra = lane >> 2;
    int kfrac = lane & 3;
    int cidx[4];
#pragma unroll
    for (int nj = 0; nj < 4; nj++)
        cidx[nj] = (nbase + nj * 8 + ra) * 4 + kfrac;

    int lrow = lane & 15;
    int lcol = (lane >> 4) * 4;
    int linv[MI];
#pragma unroll
    for (int mi = 0; mi < MI; mi++)
        linv[mi] = (mrow + mi * 16 + lrow) * CIN + lcol;

    uint32_t sA_sh = (uint32_t)__cvta_generic_to_shared(sAu);

    float acc[MI][4][4];
#pragma unroll
    for (int mi = 0; mi < MI; mi++)
#pragma unroll
        for (int nj = 0; nj < 4; nj++)
#pragma unroll
            for (int q = 0; q < 4; q++) acc[mi][nj][q] = 0.f;

    // ---- stage all 8 input rows once (tf32, per-row swizzle) ----
    const int WVALID = WIN * CIN;
    for (int l = tid * 4; l < 8 * ROWF; l += 2048) {
        int rr = l / ROWF, lo = l % ROWF;
        const float* inrow = in + ((size_t)(n * HIN + y0 + rr) * WIN) * CIN;
        float4 v;
        if (lo + 4 <= WVALID) v = *(const float4*)(inrow + lo);
        else { v.x = v.y = v.z = v.w = 0.f; }
        uint4 u;
        u.x = f2tf32(v.x); u.y = f2tf32(v.y); u.z = f2tf32(v.z); u.w = f2tf32(v.w);
        int p = lo ^ (((lo >> A_SHIFT) & 7) << 2);
        *(uint4*)(sAu + rr * ROWF + p) = u;
    }

    // ---- prefetch B[0] via cp.async ----
    for (int l = tid * 4; l < BSZ; l += 2048) {
        uint32_t da = (uint32_t)__cvta_generic_to_shared(sB + l);
        asm volatile("cp.async.ca.shared.global [%0], [%1], 16;\n"
                     :: "r"(da), "l"(wt + l));
    }
    asm volatile("cp.async.commit_group;\n");
    asm volatile("cp.async.wait_group 0;\n");
    __syncthreads();

#pragma unroll 1
    for (int dy = 0; dy < 5; dy++) {
        if (dy < 4) {
            const float* wrow = wt + (size_t)(dy + 1) * BSZ;
            float* dst = sB + ((dy + 1) & 1) * BSZ;
            for (int l = tid * 4; l < BSZ; l += 2048) {
                uint32_t da = (uint32_t)__cvta_generic_to_shared(dst + l);
                asm volatile("cp.async.ca.shared.global [%0], [%1], 16;\n"
                             :: "r"(da), "l"(wrow + l));
            }
            asm volatile("cp.async.commit_group;\n");
        }
        const float2* sB2 = (const float2*)(sB + (dy & 1) * BSZ);

        int abase = (wy + dy) * ROWF;
#pragma unroll
        for (int k8 = 0; k8 < KDY; k8 += 8) {
            uint32_t a[MI][4];
#pragma unroll
            for (int mi = 0; mi < MI; mi++) {
                int l0 = linv[mi] + k8;
                int p = l0 ^ (((l0 >> A_SHIFT) & 7) << 2);
                uint32_t addr = sA_sh + (uint32_t)(abase + p) * 4u;
                asm volatile(
                    "ldmatrix.sync.aligned.m8n8.x4.shared.b16 {%0,%1,%2,%3}, [%4];"
                    : "=r"(a[mi][0]), "=r"(a[mi][1]), "=r"(a[mi][2]), "=r"(a[mi][3])
                    : "r"(addr));
            }
            const float2* pb = sB2 + (k8 >> 3) * (4 * COUT);
#pragma unroll
            for (int nj = 0; nj < 4; nj++) {
                float2 bb = pb[cidx[nj]];
                uint32_t b0 = __float_as_uint(bb.x);
                uint32_t b1 = __float_as_uint(bb.y);
#pragma unroll
                for (int mi = 0; mi < MI; mi++) {
                    asm volatile(
                        "mma.sync.aligned.m16n8k8.row.col.f32.tf32.tf32.f32 "
                        "{%0,%1,%2,%3}, {%4,%5,%6,%7}, {%8,%9}, {%0,%1,%2,%3};"
                        : "+f"(acc[mi][nj][0]), "+f"(acc[mi][nj][1]),
                          "+f"(acc[mi][nj][2]), "+f"(acc[mi][nj][3])
                        : "r"(a[mi][0]), "r"(a[mi][1]), "r"(a[mi][2]), "r"(a[mi][3]),
                          "r"(b0), "r"(b1));
                }
            }
        }
        if (dy < 4) {
            asm volatile("cp.async.wait_group 0;\n");
            __syncthreads();
        }
    }

    int y = y0 + wy;
    size_t obase = ((size_t)(n * HOUT + y) * WOUT) * COUT;
#pragma unroll
    for (int mi = 0; mi < MI; mi++) {
#pragma unroll
        for (int nj = 0; nj < 4; nj++) {
            int x = mrow + mi * 16 + ra;
            int co = nbase + nj * 8 + kfrac * 2;
            float b0 = bias[co], b1 = bias[co + 1];
            if (x < WOUT) {
                float2 v; v.x = acc[mi][nj][0] + b0; v.y = acc[mi][nj][1] + b1;
                *(float2*)(out + obase + (size_t)x * COUT + co) = v;
            }
            if (x + 8 < WOUT) {
                float2 v; v.x = acc[mi][nj][2] + b0; v.y = acc[mi][nj][3] + b1;
                *(float2*)(out + obase + (size_t)(x + 8) * COUT + co) = v;
            }
        }
    }
}

// ---------------- maxpool ring: each conv3 row read once ----------------
__global__ void pool_ring(const float* __restrict__ in, float* __restrict__ out)
{
    extern __shared__ float ring[];   // 5 x (58*67)
    const int RP = 58 * 67;
    int strip = blockIdx.x, n = blockIdx.y, tid = threadIdx.x; // 256 threads
    int s0 = strip * 62;
    float* ob = out + (size_t)n * 64 * 496 * 58;
    for (int y = s0; y < s0 + 66; y++) {
        const float* ip = in + ((size_t)(n * 500 + y) * 116) * 64;
        int rr = (y - s0) % 5;
        for (int idx = tid; idx < 3712; idx += 256) {
            int wp = idx >> 6, c = idx & 63;
            float a = ip[(size_t)(2 * wp) * 64 + c];
            float b = ip[(size_t)(2 * wp) * 64 + 64 + c];
            ring[rr * RP + wp * 67 + c] = fmaxf(a, b);
        }
        __syncthreads();
        if (y - s0 >= 4) {
            int s = y - 4;
            for (int f = tid; f < 3712; f += 256) {
                int c = f / 58, wp = f % 58;
                int o = wp * 67 + c;
                float m = ring[o];
                m = fmaxf(m, ring[RP + o]);
                m = fmaxf(m, ring[2 * RP + o]);
                m = fmaxf(m, ring[3 * RP + o]);
                m = fmaxf(m, ring[4 * RP + o]);
                ob[(size_t)c * 496 * 58 + (size_t)s * 58 + wp] = m;
            }
        }
        __syncthreads();
    }
}

// ---------------- lin1: split-tf32 MMA GEMM, M=15872 K=3712 N=64 (R7) ----------------
__global__ __launch_bounds__(256) void lin1_mma(const float* __restrict__ A,
                                                const float* __restrict__ W,
                                                const float* __restrict__ bias,
                                                float* __restrict__ C)
{
    const int K = 3712;
    __shared__ float sAhi[128 * 20], sAlo[128 * 20];
    __shared__ float sBhi[16 * 72], sBlo[16 * 72];
    int tid = threadIdx.x;
    int lane = tid & 31, warp = tid >> 5;      // 8 warps
    int m0 = blockIdx.x * 128;
    int mrow = (warp & 3) * 32;
    int nbase = (warp >> 2) * 32;

    float acc[2][4][4];
#pragma unroll
    for (int mi = 0; mi < 2; mi++)
#pragma unroll
        for (int nj = 0; nj < 4; nj++)
#pragma unroll
            for (int q = 0; q < 4; q++) acc[mi][nj][q] = 0.f;

    for (int k0 = 0; k0 < K; k0 += 16) {
#pragma unroll
        for (int pass = 0; pass < 2; pass++) {
            int l = tid * 4 + pass * 1024;
            int row = l >> 4, kk = l & 15;
            float4 v = *(const float4*)(A + (size_t)(m0 + row) * K + k0 + kk);
            float hx = __uint_as_float(f2tf32(v.x));
            float hy = __uint_as_float(f2tf32(v.y));
            float hz = __uint_as_float(f2tf32(v.z));
            float hw = __uint_as_float(f2tf32(v.w));
            float* ph = sAhi + row * 20 + kk;
            float* pl = sAlo + row * 20 + kk;
            ph[0] = hx; ph[1] = hy; ph[2] = hz; ph[3] = hw;
            pl[0] = __uint_as_float(f2tf32(v.x - hx));
            pl[1] = __uint_as_float(f2tf32(v.y - hy));
            pl[2] = __uint_as_float(f2tf32(v.z - hz));
            pl[3] = __uint_as_float(f2tf32(v.w - hw));
        }
        {
            int l = tid * 4;
            int jn = l >> 4, kk = l & 15;
            float4 v = *(const float4*)(W + (size_t)jn * K + k0 + kk);
            float h0 = __uint_as_float(f2tf32(v.x));
            float h1 = __uint_as_float(f2tf32(v.y));
            float h2 = __uint_as_float(f2tf32(v.z));
            float h3 = __uint_as_float(f2tf32(v.w));
            sBhi[(kk + 0) * 72 + jn] = h0;
            sBhi[(kk + 1) * 72 + jn] = h1;
            sBhi[(kk + 2) * 72 + jn] = h2;
            sBhi[(kk + 3) * 72 + jn] = h3;
            sBlo[(kk + 0) * 72 + jn] = __uint_as_float(f2tf32(v.x - h0));
            sBlo[(kk + 1) * 72 + jn] = __uint_as_float(f2tf32(v.y - h1));
            sBlo[(kk + 2) * 72 + jn] = __uint_as_float(f2tf32(v.z - h2));
            sBlo[(kk + 3) * 72 + jn] = __uint_as_float(f2tf32(v.w - h3));
        }
        __syncthreads();

#pragma unroll
        for (int k8 = 0; k8 < 16; k8 += 8) {
            int ra = lane >> 2, ca = k8 + (lane & 3);
            uint32_t ah[2][4], al[2][4];
#pragma unroll
            for (int mi = 0; mi < 2; mi++) {
                int r0 = mrow + mi * 16 + ra;
                ah[mi][0] = __float_as_uint(sAhi[r0 * 20 + ca]);
                ah[mi][1] = __float_as_uint(sAhi[(r0 + 8) * 20 + ca]);
                ah[mi][2] = __float_as_uint(sAhi[r0 * 20 + ca + 4]);
                ah[mi][3] = __float_as_uint(sAhi[(r0 + 8) * 20 + ca + 4]);
                al[mi][0] = __float_as_uint(sAlo[r0 * 20 + ca]);
                al[mi][1] = __float_as_uint(sAlo[(r0 + 8) * 20 + ca]);
                al[mi][2] = __float_as_uint(sAlo[r0 * 20 + ca + 4]);
                al[mi][3] = __float_as_uint(sAlo[(r0 + 8) * 20 + ca + 4]);
            }
            int kb = k8 + (lane & 3);
#pragma unroll
            for (int nj = 0; nj < 4; nj++) {
                int cn = nbase + nj * 8 + (lane >> 2);
                uint32_t bh0 = __float_as_uint(sBhi[kb * 72 + cn]);
                uint32_t bh1 = __float_as_uint(sBhi[(kb + 4) * 72 + cn]);
                uint32_t bl0 = __float_as_uint(sBlo[kb * 72 + cn]);
                uint32_t bl1 = __float_as_uint(sBlo[(kb + 4) * 72 + cn]);
#pragma unroll
                for (int mi = 0; mi < 2; mi++) {
#define LIN1_MMA(AV0,AV1,AV2,AV3,BV0,BV1) \
    asm volatile("mma.sync.aligned.m16n8k8.row.col.f32.tf32.tf32.f32 " \
                 "{%0,%1,%2,%3}, {%4,%5,%6,%7}, {%8,%9}, {%0,%1,%2,%3};" \
                 : "+f"(acc[mi][nj][0]), "+f"(acc[mi][nj][1]), \
                   "+f"(acc[mi][nj][2]), "+f"(acc[mi][nj][3]) \
                 : "r"(AV0), "r"(AV1), "r"(AV2), "r"(AV3), "r"(BV0), "r"(BV1))
                    LIN1_MMA(ah[mi][0], ah[mi][1], ah[mi][2], ah[mi][3], bh0, bh1);
                    LIN1_MMA(ah[mi][0], ah[mi][1], ah[mi][2], ah[mi][3], bl0, bl1);
                    LIN1_MMA(al[mi][0], al[mi][1], al[mi][2], al[mi][3], bh0, bh1);
#undef LIN1_MMA
                }
            }
        }
        __syncthreads();
    }

#pragma unroll
    for (int mi = 0; mi < 2; mi++) {
#pragma unroll
        for (int nj = 0; nj < 4; nj++) {
            int x = mrow + mi * 16 + (lane >> 2);
            int co = nbase + nj * 8 + (lane & 3) * 2;
            float b0 = bias[co], b1 = bias[co + 1];
            float2 v0; v0.x = acc[mi][nj][0] + b0; v0.y = acc[mi][nj][1] + b1;
            *(float2*)(C + (size_t)(m0 + x) * 64 + co) = v0;
            float2 v1; v1.x = acc[mi][nj][2] + b0; v1.y = acc[mi][nj][3] + b1;
            *(float2*)(C + (size_t)(m0 + x + 8) * 64 + co) = v1;
        }
    }
}

// ---------------- tiled SIMT GEMM (gi): pack-at-use f32x2 (R7) ----------------
template<bool WT>
__global__ void gemm_bias(const float* __restrict__ A, const float* __restrict__ Bm,
                          const float* __restrict__ bias, float* __restrict__ C,
                          int M, int N, int K, long sA, long sB, long sC)
{
    A  += (long)blockIdx.z * sA;
    Bm += (long)blockIdx.z * sB;
    C  += (long)blockIdx.z * sC;
    __shared__ __align__(16) float sAi[64][17];
    __shared__ __align__(16) float sBi[16][68];
    int tid = threadIdx.x;          // 128
    int ttx = tid & 15, tty = tid >> 4;
    int m0 = blockIdx.x * 64, n0 = blockIdx.y * 64;
    unsigned long long acc2[8][2];
#pragma unroll
    for (int i = 0; i < 8; i++) { acc2[i][0] = 0ull; acc2[i][1] = 0ull; }

    for (int k0 = 0; k0 < K; k0 += 16) {
#pragma unroll
        for (int l = 0; l < 8; l++) {
            int e = tid + l * 128;
            int mm = e >> 4, kk = e & 15;
            int m = m0 + mm;
            sAi[mm][kk] = (m < M) ? A[(long)m * K + k0 + kk] : 0.f;
        }
#pragma unroll
        for (int l = 0; l < 8; l++) {
            int e = tid + l * 128;
            if (WT) {
                int j = e >> 4, kk = e & 15;
                int jn = n0 + j;
                sBi[kk][j] = (jn < N) ? Bm[(long)jn * K + k0 + kk] : 0.f;
            } else {
                int kk = e >> 6, j = e & 63;
                int jn = n0 + j;
                sBi[kk][j] = (jn < N) ? Bm[(long)(k0 + kk) * N + jn] : 0.f;
            }
        }
        __syncthreads();
#pragma unroll
        for (int kk = 0; kk < 16; kk++) {
            unsigned long long b0 = *(const unsigned long long*)&sBi[kk][ttx * 4];
            unsigned long long b1 = *(const unsigned long long*)&sBi[kk][ttx * 4 + 2];
#pragma unroll
            for (int i = 0; i < 8; i++) {
                float as = sAi[tty * 8 + i][kk];
                unsigned long long ap = pack2(as, as);
                acc2[i][0] = fma2(ap, b0, acc2[i][0]);
                acc2[i][1] = fma2(ap, b1, acc2[i][1]);
            }
        }
        __syncthreads();
    }
#pragma unroll
    for (int i = 0; i < 8; i++) {
        int m = m0 + tty * 8 + i;
        if (m < M) {
            int j0 = n0 + ttx * 4;
            float4 v;
            unpack2(acc2[i][0], v.x, v.y);
            unpack2(acc2[i][1], v.z, v.w);
            v.x += bias ? bias[j0 + 0] : 0.f;
            v.y += bias ? bias[j0 + 1] : 0.f;
            v.z += bias ? bias[j0 + 2] : 0.f;
            v.w += bias ? bias[j0 + 3] : 0.f;
            *(float4*)&C[(long)m * N + j0] = v;
        }
    }
}

// ------- GRU (R7): 192 thr, scalar stride-4 dot, fast activations, 2 barriers --------
__global__ void gru_kernel(const float* __restrict__ gi, const float* __restrict__ W_hh,
                           const float* __restrict__ b_hh, float* __restrict__ hs)
{
    int branch = blockIdx.x;
    int i = threadIdx.x; // 0..191
    const float* g = gi + (size_t)branch * (16 * 496 * 192);
    float* out = hs + (size_t)branch * (16 * 496 * 64);
    float w[64];
#pragma unroll
    for (int j = 0; j < 64; j++) w[j] = W_hh[(size_t)i * 64 + j];
    float bh = b_hh[i];
    __shared__ float h_sh[64], r_sh[64], z_sh[64];
    if (i < 64) h_sh[i] = 0.f;
    __syncthreads();
    const int L = 16 * 496;
    float gcur = g[i];
    for (int t = 0; t < L; t++) {
        float gnext = (t + 1 < L) ? g[(size_t)(t + 1) * 192 + i] : 0.f;
        float s0 = 0.f, s1 = 0.f, s2 = 0.f, s3 = 0.f;
#pragma unroll
        for (int j = 0; j < 64; j += 4) {
            s0 += w[j + 0] * h_sh[j + 0];
            s1 += w[j + 1] * h_sh[j + 1];
            s2 += w[j + 2] * h_sh[j + 2];
            s3 += w[j + 3] * h_sh[j + 3];
        }
        float s = bh + ((s0 + s1) + (s2 + s3));
        if (i < 64) {
            r_sh[i] = __fdividef(1.f, 1.f + __expf(-(gcur + s)));
        } else if (i < 128) {
            z_sh[i - 64] = __fdividef(1.f, 1.f + __expf(-(gcur + s)));
        }
        __syncthreads();
        if (i >= 128) {
            int j = i - 128;
            float x = gcur + r_sh[j] * s;
            float e = __expf(-2.f * fabsf(x));
            float nt = __fdividef(1.f - e, 1.f + e);
            nt = copysignf(nt, x);
            float z = z_sh[j];
            float hn = (1.f - z) * nt + z * h_sh[j];
            h_sh[j] = hn;
            out[(size_t)t * 64 + j] = hn;
        }
        __syncthreads();
        gcur = gnext;
    }
}

// ---------------- attention stats: column max & inv-sum of exp ----------------
__global__ void attn_stats(const float* __restrict__ hs, float* __restrict__ mxo,
                           float* __restrict__ ivo)
{
    int b = blockIdx.y;
    int n0 = blockIdx.x * 8;
    const float* E  = hs + (size_t)b * 496 * 64;
    const float* Tm = hs + (size_t)(16 + b) * 496 * 64;
    __shared__ float tm_sh[8][64];
    __shared__ float lg[496][9];
    int tid = threadIdx.x; // 256
    for (int e = tid; e < 8 * 64; e += 256)
        tm_sh[e >> 6][e & 63] = Tm[(size_t)(n0 + (e >> 6)) * 64 + (e & 63)];
    __syncthreads();
    for (int m = tid; m < 496; m += 256) {
        const float4* Er = (const float4*)(E + (size_t)m * 64);
        float acc[8];
#pragma unroll
        for (int nn = 0; nn < 8; nn++) acc[nn] = 0.f;
#pragma unroll
        for (int j4 = 0; j4 < 16; j4++) {
            float4 v = Er[j4];
#pragma unroll
            for (int nn = 0; nn < 8; nn++) {
                acc[nn] += v.x * tm_sh[nn][j4 * 4 + 0];
                acc[nn] += v.y * tm_sh[nn][j4 * 4 + 1];
                acc[nn] += v.z * tm_sh[nn][j4 * 4 + 2];
                acc[nn] += v.w * tm_sh[nn][j4 * 4 + 3];
            }
        }
#pragma unroll
        for (int nn = 0; nn < 8; nn++) lg[m][nn] = acc[nn];
    }
    __syncthreads();
    int wg = tid >> 5, lane = tid & 31;
    float mx = -INFINITY;
    for (int m = lane; m < 496; m += 32) mx = fmaxf(mx, lg[m][wg]);
#pragma unroll
    for (int o = 16; o; o >>= 1) mx = fmaxf(mx, __shfl_xor_sync(0xffffffffu, mx, o));
    float sum = 0.f;
    for (int m = lane; m < 496; m += 32) sum += __expf(lg[m][wg] - mx);
#pragma unroll
    for (int o = 16; o; o >>= 1) sum += __shfl_xor_sync(0xffffffffu, sum, o);
    if (lane == 0) {
        mxo[b * 512 + n0 + wg] = mx;
        ivo[b * 512 + n0 + wg] = 1.f / sum;
    }
}

// ---------------- fused Tp: recompute logits, exp, contract with Tm ----------------
__global__ __launch_bounds__(256) void tp_fused(const float* __restrict__ hs,
                                                const float* __restrict__ mxv,
                                                const float* __restrict__ ivv,
                                                float* __restrict__ Tp)
{
    extern __shared__ float sm[];
    float* sE  = sm;               // 64 x 68
    float* sTm = sm + 64 * 68;     // 64 x 68
    float* sP  = sm + 2 * 64 * 68; // 64 x 68
    int b = blockIdx.y;
    int m0 = blockIdx.x * 64;
    const float* E  = hs + (size_t)b * 496 * 64;
    const float* Tm = hs + (size_t)(16 + b) * 496 * 64;
    int tid = threadIdx.x;
    int tx = tid & 15, ty = tid >> 4;

    for (int e = tid; e < 64 * 16; e += 256) {
        int r = e >> 4, c4 = (e & 15) * 4;
        float4 v = (m0 + r < 496) ? *(const float4*)(E + (size_t)(m0 + r) * 64 + c4)
                                  : make_float4(0.f, 0.f, 0.f, 0.f);
        *(float4*)&sE[r * 68 + c4] = v;
    }

    float acc[4][4];
#pragma unroll
    for (int ii = 0; ii < 4; ii++)
#pragma unroll
        for (int dd = 0; dd < 4; dd++) acc[ii][dd] = 0.f;

    for (int n0 = 0; n0 < 496; n0 += 64) {
        for (int e = tid; e < 64 * 16; e += 256) {
            int r = e >> 4, c4 = (e & 15) * 4;
            float4 v = (n0 + r < 496) ? *(const float4*)(Tm + (size_t)(n0 + r) * 64 + c4)
                                      : make_float4(0.f, 0.f, 0.f, 0.f);
            *(float4*)&sTm[r * 68 + c4] = v;
        }
        __syncthreads();

        float s4[4][4];
#pragma unroll
        for (int ii = 0; ii < 4; ii++)
#pragma unroll
            for (int jj = 0; jj < 4; jj++) s4[ii][jj] = 0.f;
#pragma unroll
        for (int k4 = 0; k4 < 16; k4++) {
            float4 a[4], bb[4];
#pragma unroll
            for (int ii = 0; ii < 4; ii++)
                a[ii] = *(float4*)&sE[(ty * 4 + ii) * 68 + k4 * 4];
#pragma unroll
            for (int jj = 0; jj < 4; jj++)
                bb[jj] = *(float4*)&sTm[(tx * 4 + jj) * 68 + k4 * 4];
#pragma unroll
            for (int ii = 0; ii < 4; ii++)
#pragma unroll
                for (int jj = 0; jj < 4; jj++)
                    s4[ii][jj] += a[ii].x * bb[jj].x + a[ii].y * bb[jj].y
                                + a[ii].z * bb[jj].z + a[ii].w * bb[jj].w;
        }
#pragma unroll
        for (int jj = 0; jj < 4; jj++) {
            int nn = n0 + tx * 4 + jj;
            float mxn = (nn < 496) ? mxv[b * 512 + nn] : 0.f;
            float ivn = (nn < 496) ? ivv[b * 512 + nn] : 0.f;
#pragma unroll
            for (int ii = 0; ii < 4; ii++)
                sP[(ty * 4 + ii) * 68 + tx * 4 + jj] =
                    (nn < 496) ? __expf(s4[ii][jj] - mxn) * ivn : 0.f;
        }
        __syncthreads();
#pragma unroll 2
        for (int j = 0; j < 64; j++) {
            float4 bv = *(float4*)&sTm[j * 68 + tx * 4];
            float p0 = sP[(ty * 4 + 0) * 68 + j];
            float p1 = sP[(ty * 4 + 1) * 68 + j];
            float p2 = sP[(ty * 4 + 2) * 68 + j];
            float p3 = sP[(ty * 4 + 3) * 68 + j];
            acc[0][0] += p0 * bv.x; acc[0][1] += p0 * bv.y; acc[0][2] += p0 * bv.z; acc[0][3] += p0 * bv.w;
            acc[1][0] += p1 * bv.x; acc[1][1] += p1 * bv.y; acc[1][2] += p1 * bv.z; acc[1][3] += p1 * bv.w;
            acc[2][0] += p2 * bv.x; acc[2][1] += p2 * bv.y; acc[2][2] += p2 * bv.z; acc[2][3] += p2 * bv.w;
            acc[3][0] += p3 * bv.x; acc[3][1] += p3 * bv.y; acc[3][2] += p3 * bv.z; acc[3][3] += p3 * bv.w;
        }
        __syncthreads();
    }
#pragma unroll
    for (int ii = 0; ii < 4; ii++) {
        int m = m0 + ty * 4 + ii;
        if (m < 496) {
            float4 v; v.x = acc[ii][0]; v.y = acc[ii][1]; v.z = acc[ii][2]; v.w = acc[ii][3];
            *(float4*)&Tp[((size_t)b * 496 + m) * 64 + tx * 4] = v;
        }
    }
}

// ---------------- fused head ----------------
__global__ void final_kernel(const float* __restrict__ hs, const float* __restrict__ Tp,
                             const float* __restrict__ aw, const float* __restrict__ ab,
                             const float* __restrict__ l3w, const float* __restrict__ l3b,
                             const float* __restrict__ cw, const float* __restrict__ cb,
                             float* __restrict__ outp)
{
    int b = blockIdx.x;
    int tid = threadIdx.x; // 256
    const float* E   = hs + (size_t)b * 496 * 64;
    const float* Tpb = Tp + (size_t)b * 496 * 64;
    __shared__ float att[496];
    __shared__ float red[256];
    __shared__ float part[4][64];
    __shared__ float hrep[64];
    __shared__ float h2[128];
    __shared__ float aw_sh[64];
    if (tid < 64) aw_sh[tid] = aw[tid];
    __syncthreads();
    float lmax = -INFINITY;
    for (int s = tid; s < 496; s += 256) {
        const float* er = E + (size_t)s * 64;
        float acc = ab[0];
#pragma unroll
        for (int j = 0; j < 64; j++) acc += er[j] * aw_sh[j];
        att[s] = acc;
        lmax = fmaxf(lmax, acc);
    }
    red[tid] = lmax;
    __syncthreads();
    for (int o = 128; o; o >>= 1) {
        if (tid < o) red[tid] = fmaxf(red[tid], red[tid + o]);
        __syncthreads();
    }
    float mx = red[0];
    __syncthreads();
    float lsum = 0.f;
    for (int s = tid; s < 496; s += 256) {
        float e = __expf(att[s] - mx);
        att[s] = e;
        lsum += e;
    }
    red[tid] = lsum;
    __syncthreads();
    for (int o = 128; o; o >>= 1) {
        if (tid < o) red[tid] += red[tid + o];
        __syncthreads();
    }
    float inv = 1.f / red[0];
    int d = tid & 63, grp = tid >> 6;
    float acc = 0.f;
    for (int s = grp; s < 496; s += 4)
        acc += att[s] * fabsf(Tpb[(size_t)s * 64 + d] - E[(size_t)s * 64 + d]);
    part[grp][d] = acc;
    __syncthreads();
    if (tid < 64) {
        float r = (part[0][tid] + part[1][tid] + part[2][tid] + part[3][tid]) * inv;
        hrep[tid] = fmaxf(r, 0.f);
    }
    __syncthreads();
    if (tid < 128) {
        float a2 = l3b[tid];
#pragma unroll
        for (int j = 0; j < 64; j++) a2 += hrep[j] * l3w[(size_t)tid * 64 + j];
        h2[tid] = fmaxf(a2, 0.f);
    }
    __syncthreads();
    if (tid < 2) {
        float a3 = cb[tid];
#pragma unroll
        for (int j = 0; j < 128; j++) a3 += h2[j] * cw[(size_t)tid * 128 + j];
        outp[b * 2 + tid] = a3;
    }
}

// ---------------- launch ----------------
extern "C" void kernel_launch(void* const* d_in, const int* in_sizes, int n_in,
                              void* d_out, int out_size)
{
    const float* ev    = (const float*)d_in[0];
    const float* tmpl  = (const float*)d_in[1];
    const float* c1w   = (const float*)d_in[2];
    const float* c1b   = (const float*)d_in[3];
    const float* c2w   = (const float*)d_in[4];
    const float* c2b   = (const float*)d_in[5];
    const float* c3w   = (const float*)d_in[6];
    const float* c3b   = (const float*)d_in[7];
    const float* l1w   = (const float*)d_in[8];
    const float* l1b   = (const float*)d_in[9];
    const float* W_ih  = (const float*)d_in[10];
    const float* W_hh  = (const float*)d_in[11];
    const float* b_ih  = (const float*)d_in[12];
    const float* b_hh  = (const float*)d_in[13];
    const float* aw    = (const float*)d_in[14];
    const float* ab    = (const float*)d_in[15];
    const float* l3w   = (const float*)d_in[16];
    const float* l3b   = (const float*)d_in[17];
    const float* cw    = (const float*)d_in[18];
    const float* cb    = (const float*)d_in[19];
    float* outp = (float*)d_out;

    float *p_in, *p_c1, *p_c2, *p_c3, *p_pool, *p_x1, *p_gi, *p_hs, *p_Tp;
    float *p_wt2, *p_wt3, *p_mx, *p_iv;
    cudaGetSymbolAddress((void**)&p_in,   g_in);
    cudaGetSymbolAddress((void**)&p_c1,   g_c1);
    cudaGetSymbolAddress((void**)&p_c2,   g_c2);
    cudaGetSymbolAddress((void**)&p_c3,   g_c3);
    cudaGetSymbolAddress((void**)&p_pool, g_pool);
    cudaGetSymbolAddress((void**)&p_x1,   g_x1);
    cudaGetSymbolAddress((void**)&p_gi,   g_gi);
    cudaGetSymbolAddress((void**)&p_hs,   g_hs);
    cudaGetSymbolAddress((void**)&p_Tp,   g_Tp);
    cudaGetSymbolAddress((void**)&p_wt2,  g_wt2);
    cudaGetSymbolAddress((void**)&p_wt3,  g_wt3);
    cudaGetSymbolAddress((void**)&p_mx,   g_mx);
    cudaGetSymbolAddress((void**)&p_iv,   g_iv);

    const int smem2 = (8 * 2112 + 2 * 2560) * 4;    // 88,064 B
    const int smem3 = (8 * 4224 + 2 * 10240) * 4;   // 217,088 B
    const int smemp = 5 * 58 * 67 * 4;              // 77,720 B
    const int smemt = 3 * 64 * 68 * 4;              // 52,224 B
    cudaFuncSetAttribute(conv_mma2<16, 32, 508, 124>,
                         cudaFuncAttributeMaxDynamicSharedMemorySize, smem2);
    cudaFuncSetAttribute(conv_mma2<32, 64, 504, 120>,
                         cudaFuncAttributeMaxDynamicSharedMemorySize, smem3);
    cudaFuncSetAttribute(pool_ring,
                         cudaFuncAttributeMaxDynamicSharedMemorySize, smemp);
    cudaFuncSetAttribute(tp_fused,
                         cudaFuncAttributeMaxDynamicSharedMemorySize, smemt);

    prep_kernel<<<dim3(4, 16, 33), dim3(32, 8)>>>(ev, tmpl, c2w, c3w, p_in, p_wt2, p_wt3);
    conv1_nhwc<<<dim3(508, 32), 128>>>(p_in, c1w, c1b, p_c1);
    conv_mma2<16, 32, 508, 124><<<dim3(126, 32), 512, smem2>>>(p_c1, p_wt2, c2b, p_c2);
    conv_mma2<32, 64, 504, 120><<<dim3(125, 32), 512, smem3>>>(p_c2, p_wt3, c3b, p_c3);
    pool_ring<<<dim3(8, 32), 256, smemp>>>(p_c3, p_pool);
    lin1_mma<<<124, 256>>>(p_pool, l1w, l1b, p_x1);
    gemm_bias<true><<<dim3(248, 3, 1), 128>>>(p_x1, W_ih, b_ih, p_gi,
                                              15872, 192, 64, 0, 0, 0);
    gru_kernel<<<2, 192>>>(p_gi, W_hh, b_hh, p_hs);
    attn_stats<<<dim3(62, 16), 256>>>(p_hs, p_mx, p_iv);
    tp_fused<<<dim3(8, 16), 256, smemt>>>(p_hs, p_mx, p_iv, p_Tp);
    final_kernel<<<16, 256>>>(p_hs, p_Tp, aw, ab, l3w, l3b, cw, cb, outp);
}

// round 16
// speedup vs baseline: 1.2062x; 1.0329x over previous
#include <cuda_runtime.h>
#include <math.h>
#include <stddef.h>
#include <stdint.h>
#include <string.h>

// ---------------- static scratch (no allocations allowed) ----------------
__device__ float g_in  [(size_t)32*512*128];          // (n, t, c)
__device__ float g_c1  [(size_t)32*508*124*16];       // NHWC
__device__ float g_c2  [(size_t)32*504*120*32];       // NHWC
__device__ float g_c3  [(size_t)32*500*116*64];       // NHWC
__device__ float g_pool[(size_t)32*64*496*58];        // (n, c, s, w) raw reshape layout
__device__ float g_x1  [(size_t)32*496*64];
__device__ float g_gi  [(size_t)32*496*192];
__device__ float g_hs  [(size_t)32*496*64];           // E (n<16) / Tm (n>=16)
__device__ float g_Tp  [(size_t)16*496*64];
__device__ float g_wt2 [(size_t)5*80*32];             // conv2 weights [dy][k8][co][pos]
__device__ float g_wt3 [(size_t)5*160*64];            // conv3 weights [dy][k8][co][pos]
__device__ float g_mx  [16*512];                      // column softmax stats
__device__ float g_iv  [16*512];

__device__ __forceinline__ uint32_t f2tf32(float x)
{
    uint32_t u;
    asm("cvt.rna.tf32.f32 %0, %1;" : "=r"(u) : "f"(x));
    return u;
}

__device__ __forceinline__ unsigned long long fma2(unsigned long long a,
                                                   unsigned long long b,
                                                   unsigned long long c)
{
    unsigned long long d;
    asm("fma.rn.f32x2 %0, %1, %2, %3;" : "=l"(d) : "l"(a), "l"(b), "l"(c));
    return d;
}

__device__ __forceinline__ unsigned long long pack2(float x, float y)
{
    unsigned long long d;
    asm("mov.b64 %0, {%1, %2};" : "=l"(d) : "f"(x), "f"(y));
    return d;
}

__device__ __forceinline__ void unpack2(unsigned long long v, float& x, float& y)
{
    asm("mov.b64 {%0, %1}, %2;" : "=f"(x), "=f"(y) : "l"(v));
}

// ---------------- prep: transpose (z<32) + weight reorders (z==32) ----------------
// B layout (R9): [dy][k>>3][co][pos(k&7)], pos(j) = 2*(j&3) + (j>>2)
__global__ void prep_kernel(const float* __restrict__ ev, const float* __restrict__ tm,
                            const float* __restrict__ c2w, const float* __restrict__ c3w,
                            float* __restrict__ out, float* __restrict__ wt2,
                            float* __restrict__ wt3)
{
    if (blockIdx.z < 32) {
        __shared__ float tile[32][33];
        int n = blockIdx.z;
        const float* src = (n < 16) ? (ev + (size_t)n * 128 * 512)
                                    : (tm + (size_t)(n - 16) * 128 * 512);
        int x0 = blockIdx.x * 32;
        int y0 = blockIdx.y * 32;
        int lx = threadIdx.x, ly = threadIdx.y; // 32 x 8
        for (int r = ly; r < 32; r += 8)
            tile[r][lx] = src[(size_t)(x0 + r) * 512 + y0 + lx];
        __syncthreads();
        float* o = out + (size_t)n * 512 * 128;
        for (int r = ly; r < 32; r += 8)
            o[(size_t)(y0 + r) * 128 + x0 + lx] = tile[lx][r];
    } else {
        int pid = (blockIdx.y * 4 + blockIdx.x) * 256 + threadIdx.y * 32 + threadIdx.x;
        for (int idx = pid; idx < 12800; idx += 16384) {   // conv2: CIN=16, COUT=32
            int dx = idx % 5, dy = (idx / 5) % 5, ci = (idx / 25) % 16, co = idx / 400;
            int k = dx * 16 + ci;
            int j = k & 7;
            int pos = 2 * (j & 3) + (j >> 2);
            wt2[(size_t)dy * (80 * 32) + (k >> 3) * 256 + co * 8 + pos] =
                __uint_as_float(f2tf32(c2w[idx]));
        }
        for (int idx = pid; idx < 51200; idx += 16384) {   // conv3: CIN=32, COUT=64
            int dx = idx % 5, dy = (idx / 5) % 5, ci = (idx / 25) % 32, co = idx / 800;
            int k = dx * 32 + ci;
            int j = k & 7;
            int pos = 2 * (j & 3) + (j >> 2);
            wt3[(size_t)dy * (160 * 64) + (k >> 3) * 512 + co * 8 + pos] =
                __uint_as_float(f2tf32(c3w[idx]));
        }
    }
}

// ---------------- conv1: CIN=1, direct fp32, NHWC out ----------------
__global__ void conv1_nhwc(const float* __restrict__ in, const float* __restrict__ w,
                           const float* __restrict__ bias, float* __restrict__ out)
{
    __shared__ float srow[5][128];
    __shared__ float sw[16][25];
    __shared__ float sb[16];
    int y = blockIdx.x, n = blockIdx.y, tid = threadIdx.x;  // 128 threads
    const float* ip = in + ((size_t)n * 512 + y) * 128;
#pragma unroll
    for (int r = 0; r < 5; r++) srow[r][tid] = ip[(size_t)r * 128 + tid];
    if (tid < 16) sb[tid] = bias[tid];
    for (int e = tid; e < 400; e += 128) sw[e / 25][e % 25] = w[e];
    __syncthreads();
    if (tid >= 124) return;
    float acc[16];
#pragma unroll
    for (int co = 0; co < 16; co++) acc[co] = sb[co];
#pragma unroll
    for (int dy = 0; dy < 5; dy++) {
#pragma unroll
        for (int dx = 0; dx < 5; dx++) {
            float v = srow[dy][tid + dx];
#pragma unroll
            for (int co = 0; co < 16; co++) acc[co] += v * sw[co][dy * 5 + dx];
        }
    }
    float4* op = (float4*)(out + (((size_t)n * 508 + y) * 124 + tid) * 16);
#pragma unroll
    for (int q = 0; q < 4; q++) {
        float4 v; v.x = acc[q*4]; v.y = acc[q*4+1]; v.z = acc[q*4+2]; v.w = acc[q*4+3];
        op[q] = v;
    }
}

// ---------------- conv2 (R9): ldmatrix A-frags, paired-B LDS.64, 512 thr -------------
template<int CIN, int COUT, int HIN, int WIN>
__global__ __launch_bounds__(512) void conv_mma2(const float* __restrict__ in,
                                                 const float* __restrict__ wt,
                                                 const float* __restrict__ bias,
                                                 float* __restrict__ out)
{
    constexpr int HOUT = HIN - 4, WOUT = WIN - 4;
    constexpr int ROWF = 132 * CIN;
    constexpr int KDY = 5 * CIN;
    constexpr int BSZ = KDY * COUT;
    constexpr int A_SHIFT = (CIN == 32) ? 5 : 4;
    constexpr int MI = (COUT == 64) ? 4 : 2;

    extern __shared__ float smem[];
    float* sA = smem;                 // 8 rows x ROWF
    float* sB = smem + 8 * ROWF;      // 2 x BSZ (double buffer)
    uint32_t* sAu = (uint32_t*)sA;

    int tid = threadIdx.x;
    int lane = tid & 31, warp = tid >> 5;   // 16 warps
    int y0 = blockIdx.x * 4, n = blockIdx.y;
    int wy = warp >> 2;
    int wsub = warp & 3;
    int mrow, nbase;
    if (COUT == 64) { mrow = (wsub & 1) * 64; nbase = (wsub >> 1) * 32; }
    else            { mrow = wsub * 32;       nbase = 0; }

    int ra = lane >> 2;
    int kfrac = lane & 3;
    int cidx[4];
#pragma unroll
    for (int nj = 0; nj < 4; nj++)
        cidx[nj] = (nbase + nj * 8 + ra) * 4 + kfrac;

    int lrow = lane & 15;
    int lcol = (lane >> 4) * 4;
    int linv[MI];
#pragma unroll
    for (int mi = 0; mi < MI; mi++)
        linv[mi] = (mrow + mi * 16 + lrow) * CIN + lcol;

    uint32_t sA_sh = (uint32_t)__cvta_generic_to_shared(sAu);

    float acc[MI][4][4];
#pragma unroll
    for (int mi = 0; mi < MI; mi++)
#pragma unroll
        for (int nj = 0; nj < 4; nj++)
#pragma unroll
            for (int q = 0; q < 4; q++) acc[mi][nj][q] = 0.f;

    const int WVALID = WIN * CIN;
    for (int l = tid * 4; l < 8 * ROWF; l += 2048) {
        int rr = l / ROWF, lo = l % ROWF;
        const float* inrow = in + ((size_t)(n * HIN + y0 + rr) * WIN) * CIN;
        float4 v;
        if (lo + 4 <= WVALID) v = *(const float4*)(inrow + lo);
        else { v.x = v.y = v.z = v.w = 0.f; }
        uint4 u;
        u.x = f2tf32(v.x); u.y = f2tf32(v.y); u.z = f2tf32(v.z); u.w = f2tf32(v.w);
        int p = lo ^ (((lo >> A_SHIFT) & 7) << 2);
        *(uint4*)(sAu + rr * ROWF + p) = u;
    }

    for (int l = tid * 4; l < BSZ; l += 2048) {
        uint32_t da = (uint32_t)__cvta_generic_to_shared(sB + l);
        asm volatile("cp.async.ca.shared.global [%0], [%1], 16;\n"
                     :: "r"(da), "l"(wt + l));
    }
    asm volatile("cp.async.commit_group;\n");
    asm volatile("cp.async.wait_group 0;\n");
    __syncthreads();

#pragma unroll 1
    for (int dy = 0; dy < 5; dy++) {
        if (dy < 4) {
            const float* wrow = wt + (size_t)(dy + 1) * BSZ;
            float* dst = sB + ((dy + 1) & 1) * BSZ;
            for (int l = tid * 4; l < BSZ; l += 2048) {
                uint32_t da = (uint32_t)__cvta_generic_to_shared(dst + l);
                asm volatile("cp.async.ca.shared.global [%0], [%1], 16;\n"
                             :: "r"(da), "l"(wrow + l));
            }
            asm volatile("cp.async.commit_group;\n");
        }
        const float2* sB2 = (const float2*)(sB + (dy & 1) * BSZ);

        int abase = (wy + dy) * ROWF;
#pragma unroll
        for (int k8 = 0; k8 < KDY; k8 += 8) {
            uint32_t a[MI][4];
#pragma unroll
            for (int mi = 0; mi < MI; mi++) {
                int l0 = linv[mi] + k8;
                int p = l0 ^ (((l0 >> A_SHIFT) & 7) << 2);
                uint32_t addr = sA_sh + (uint32_t)(abase + p) * 4u;
                asm volatile(
                    "ldmatrix.sync.aligned.m8n8.x4.shared.b16 {%0,%1,%2,%3}, [%4];"
                    : "=r"(a[mi][0]), "=r"(a[mi][1]), "=r"(a[mi][2]), "=r"(a[mi][3])
                    : "r"(addr));
            }
            const float2* pb = sB2 + (k8 >> 3) * (4 * COUT);
#pragma unroll
            for (int nj = 0; nj < 4; nj++) {
                float2 bb = pb[cidx[nj]];
                uint32_t b0 = __float_as_uint(bb.x);
                uint32_t b1 = __float_as_uint(bb.y);
#pragma unroll
                for (int mi = 0; mi < MI; mi++) {
                    asm volatile(
                        "mma.sync.aligned.m16n8k8.row.col.f32.tf32.tf32.f32 "
                        "{%0,%1,%2,%3}, {%4,%5,%6,%7}, {%8,%9}, {%0,%1,%2,%3};"
                        : "+f"(acc[mi][nj][0]), "+f"(acc[mi][nj][1]),
                          "+f"(acc[mi][nj][2]), "+f"(acc[mi][nj][3])
                        : "r"(a[mi][0]), "r"(a[mi][1]), "r"(a[mi][2]), "r"(a[mi][3]),
                          "r"(b0), "r"(b1));
                }
            }
        }
        if (dy < 4) {
            asm volatile("cp.async.wait_group 0;\n");
            __syncthreads();
        }
    }

    int y = y0 + wy;
    size_t obase = ((size_t)(n * HOUT + y) * WOUT) * COUT;
#pragma unroll
    for (int mi = 0; mi < MI; mi++) {
#pragma unroll
        for (int nj = 0; nj < 4; nj++) {
            int x = mrow + mi * 16 + ra;
            int co = nbase + nj * 8 + kfrac * 2;
            float b0 = bias[co], b1 = bias[co + 1];
            if (x < WOUT) {
                float2 v; v.x = acc[mi][nj][0] + b0; v.y = acc[mi][nj][1] + b1;
                *(float2*)(out + obase + (size_t)x * COUT + co) = v;
            }
            if (x + 8 < WOUT) {
                float2 v; v.x = acc[mi][nj][2] + b0; v.y = acc[mi][nj][3] + b1;
                *(float2*)(out + obase + (size_t)(x + 8) * COUT + co) = v;
            }
        }
    }
}

// ----- conv3 v2: 256 thr, 2 y-rows, ring-A(3x128cols) + single-B, 2 blocks/SM --------
__global__ __launch_bounds__(256, 2) void conv_mma3(const float* __restrict__ in,
                                                    const float* __restrict__ wt,
                                                    const float* __restrict__ bias,
                                                    float* __restrict__ out)
{
    constexpr int CIN = 32, COUT = 64, HIN = 504, WIN = 120;
    constexpr int HOUT = 500, WOUT = 116;
    constexpr int ROWF = 128 * CIN;       // 4096 words per staged row
    constexpr int KDY = 5 * CIN;          // 160
    constexpr int BSZ = KDY * COUT;       // 10240
    constexpr int MI = 4;

    extern __shared__ float smem[];
    float* sA = smem;                     // 3 slots x ROWF
    float* sB = smem + 3 * ROWF;          // BSZ (single buffer)
    uint32_t* sAu = (uint32_t*)sA;

    int tid = threadIdx.x;
    int lane = tid & 31, warp = tid >> 5; // 8 warps
    int y0 = blockIdx.x * 2, n = blockIdx.y;
    int wy = warp >> 2;                   // 0..1
    int wsub = warp & 3;
    int mrow = (wsub & 1) * 64;
    int nbase = (wsub >> 1) * 32;

    int ra = lane >> 2;
    int kfrac = lane & 3;
    int cidx[4];
#pragma unroll
    for (int nj = 0; nj < 4; nj++)
        cidx[nj] = (nbase + nj * 8 + ra) * 4 + kfrac;

    int lrow = lane & 15;
    int lcol = (lane >> 4) * 4;
    int linv[MI];
#pragma unroll
    for (int mi = 0; mi < MI; mi++)
        linv[mi] = (mrow + mi * 16 + lrow) * CIN + lcol;

    uint32_t sA_sh = (uint32_t)__cvta_generic_to_shared(sAu);

    float acc[MI][4][4];
#pragma unroll
    for (int mi = 0; mi < MI; mi++)
#pragma unroll
        for (int nj = 0; nj < 4; nj++)
#pragma unroll
            for (int q = 0; q < 4; q++) acc[mi][nj][q] = 0.f;

    const int WVALID = WIN * CIN;   // 3840

    // stage relative row rr (0..5) into slot rr%3 (tf32 + swizzle)
#define STAGE_ROW(RR)                                                           \
    {                                                                           \
        int slot_ = (RR) % 3;                                                   \
        const float* inrow_ = in + ((size_t)(n * HIN + y0 + (RR)) * WIN) * CIN; \
        for (int l = tid * 4; l < ROWF; l += 1024) {                            \
            float4 v;                                                           \
            if (l + 4 <= WVALID) v = *(const float4*)(inrow_ + l);              \
            else { v.x = v.y = v.z = v.w = 0.f; }                               \
            uint4 u;                                                            \
            u.x = f2tf32(v.x); u.y = f2tf32(v.y);                               \
            u.z = f2tf32(v.z); u.w = f2tf32(v.w);                               \
            int p = l ^ (((l >> 5) & 7) << 2);                                  \
            *(uint4*)(sAu + slot_ * ROWF + p) = u;                              \
        }                                                                       \
    }

    STAGE_ROW(0)
    STAGE_ROW(1)
    for (int l = tid * 4; l < BSZ; l += 1024) {
        uint32_t da = (uint32_t)__cvta_generic_to_shared(sB + l);
        asm volatile("cp.async.ca.shared.global [%0], [%1], 16;\n"
                     :: "r"(da), "l"(wt + l));
    }
    asm volatile("cp.async.commit_group;\n");
    asm volatile("cp.async.wait_group 0;\n");
    __syncthreads();

#pragma unroll 1
    for (int dy = 0; dy < 5; dy++) {
        int abase = ((wy + dy) % 3) * ROWF;
        const float2* sB2 = (const float2*)sB;
#pragma unroll
        for (int k8 = 0; k8 < KDY; k8 += 8) {
            uint32_t a[MI][4];
#pragma unroll
            for (int mi = 0; mi < MI; mi++) {
                int l0 = linv[mi] + k8;
                int p = l0 ^ (((l0 >> 5) & 7) << 2);
                uint32_t addr = sA_sh + (uint32_t)(abase + p) * 4u;
                asm volatile(
                    "ldmatrix.sync.aligned.m8n8.x4.shared.b16 {%0,%1,%2,%3}, [%4];"
                    : "=r"(a[mi][0]), "=r"(a[mi][1]), "=r"(a[mi][2]), "=r"(a[mi][3])
                    : "r"(addr));
            }
            const float2* pb = sB2 + (k8 >> 3) * (4 * COUT);
#pragma unroll
            for (int nj = 0; nj < 4; nj++) {
                float2 bb = pb[cidx[nj]];
                uint32_t b0 = __float_as_uint(bb.x);
                uint32_t b1 = __float_as_uint(bb.y);
#pragma unroll
                for (int mi = 0; mi < MI; mi++) {
                    asm volatile(
                        "mma.sync.aligned.m16n8k8.row.col.f32.tf32.tf32.f32 "
                        "{%0,%1,%2,%3}, {%4,%5,%6,%7}, {%8,%9}, {%0,%1,%2,%3};"
                        : "+f"(acc[mi][nj][0]), "+f"(acc[mi][nj][1]),
                          "+f"(acc[mi][nj][2]), "+f"(acc[mi][nj][3])
                        : "r"(a[mi][0]), "r"(a[mi][1]), "r"(a[mi][2]), "r"(a[mi][3]),
                          "r"(b0), "r"(b1));
                }
            }
        }
        if (dy < 4) {
            __syncthreads();               // everyone done with sB + old A slot
            STAGE_ROW(dy + 2)
            const float* wrow = wt + (size_t)(dy + 1) * BSZ;
            for (int l = tid * 4; l < BSZ; l += 1024) {
                uint32_t da = (uint32_t)__cvta_generic_to_shared(sB + l);
                asm volatile("cp.async.ca.shared.global [%0], [%1], 16;\n"
                             :: "r"(da), "l"(wrow + l));
            }
            asm volatile("cp.async.commit_group;\n");
            asm volatile("cp.async.wait_group 0;\n");
            __syncthreads();
        }
    }
#undef STAGE_ROW

    int y = y0 + wy;
    size_t obase = ((size_t)(n * HOUT + y) * WOUT) * COUT;
#pragma unroll
    for (int mi = 0; mi < MI; mi++) {
#pragma unroll
        for (int nj = 0; nj < 4; nj++) {
            int x = mrow + mi * 16 + ra;
            int co = nbase + nj * 8 + kfrac * 2;
            float b0 = bias[co], b1 = bias[co + 1];
            if (x < WOUT) {
                float2 v; v.x = acc[mi][nj][0] + b0; v.y = acc[mi][nj][1] + b1;
                *(float2*)(out + obase + (size_t)x * COUT + co) = v;
            }
            if (x + 8 < WOUT) {
                float2 v; v.x = acc[mi][nj][2] + b0; v.y = acc[mi][nj][3] + b1;
                *(float2*)(out + obase + (size_t)(x + 8) * COUT + co) = v;
            }
        }
    }
}

// ---------------- maxpool ring: each conv3 row read once ----------------
__global__ void pool_ring(const float* __restrict__ in, float* __restrict__ out)
{
    extern __shared__ float ring[];   // 5 x (58*67)
    const int RP = 58 * 67;
    int strip = blockIdx.x, n = blockIdx.y, tid = threadIdx.x; // 256 threads
    int s0 = strip * 62;
    float* ob = out + (size_t)n * 64 * 496 * 58;
    for (int y = s0; y < s0 + 66; y++) {
        const float* ip = in + ((size_t)(n * 500 + y) * 116) * 64;
        int rr = (y - s0) % 5;
        for (int idx = tid; idx < 3712; idx += 256) {
            int wp = idx >> 6, c = idx & 63;
            float a = ip[(size_t)(2 * wp) * 64 + c];
            float b = ip[(size_t)(2 * wp) * 64 + 64 + c];
            ring[rr * RP + wp * 67 + c] = fmaxf(a, b);
        }
        __syncthreads();
        if (y - s0 >= 4) {
            int s = y - 4;
            for (int f = tid; f < 3712; f += 256) {
                int c = f / 58, wp = f % 58;
                int o = wp * 67 + c;
                float m = ring[o];
                m = fmaxf(m, ring[RP + o]);
                m = fmaxf(m, ring[2 * RP + o]);
                m = fmaxf(m, ring[3 * RP + o]);
                m = fmaxf(m, ring[4 * RP + o]);
                ob[(size_t)c * 496 * 58 + (size_t)s * 58 + wp] = m;
            }
        }
        __syncthreads();
    }
}

// ---------------- lin1: split-tf32 MMA GEMM, M=15872 K=3712 N=64 (R7) ----------------
__global__ __launch_bounds__(256) void lin1_mma(const float* __restrict__ A,
                                                const float* __restrict__ W,
                                                const float* __restrict__ bias,
                                                float* __restrict__ C)
{
    const int K = 3712;
    __shared__ float sAhi[128 * 20], sAlo[128 * 20];
    __shared__ float sBhi[16 * 72], sBlo[16 * 72];
    int tid = threadIdx.x;
    int lane = tid & 31, warp = tid >> 5;      // 8 warps
    int m0 = blockIdx.x * 128;
    int mrow = (warp & 3) * 32;
    int nbase = (warp >> 2) * 32;

    float acc[2][4][4];
#pragma unroll
    for (int mi = 0; mi < 2; mi++)
#pragma unroll
        for (int nj = 0; nj < 4; nj++)
#pragma unroll
            for (int q = 0; q < 4; q++) acc[mi][nj][q] = 0.f;

    for (int k0 = 0; k0 < K; k0 += 16) {
#pragma unroll
        for (int pass = 0; pass < 2; pass++) {
            int l = tid * 4 + pass * 1024;
            int row = l >> 4, kk = l & 15;
            float4 v = *(const float4*)(A + (size_t)(m0 + row) * K + k0 + kk);
            float hx = __uint_as_float(f2tf32(v.x));
            float hy = __uint_as_float(f2tf32(v.y));
            float hz = __uint_as_float(f2tf32(v.z));
            float hw = __uint_as_float(f2tf32(v.w));
            float* ph = sAhi + row * 20 + kk;
            float* pl = sAlo + row * 20 + kk;
            ph[0] = hx; ph[1] = hy; ph[2] = hz; ph[3] = hw;
            pl[0] = __uint_as_float(f2tf32(v.x - hx));
            pl[1] = __uint_as_float(f2tf32(v.y - hy));
            pl[2] = __uint_as_float(f2tf32(v.z - hz));
            pl[3] = __uint_as_float(f2tf32(v.w - hw));
        }
        {
            int l = tid * 4;
            int jn = l >> 4, kk = l & 15;
            float4 v = *(const float4*)(W + (size_t)jn * K + k0 + kk);
            float h0 = __uint_as_float(f2tf32(v.x));
            float h1 = __uint_as_float(f2tf32(v.y));
            float h2 = __uint_as_float(f2tf32(v.z));
            float h3 = __uint_as_float(f2tf32(v.w));
            sBhi[(kk + 0) * 72 + jn] = h0;
            sBhi[(kk + 1) * 72 + jn] = h1;
            sBhi[(kk + 2) * 72 + jn] = h2;
            sBhi[(kk + 3) * 72 + jn] = h3;
            sBlo[(kk + 0) * 72 + jn] = __uint_as_float(f2tf32(v.x - h0));
            sBlo[(kk + 1) * 72 + jn] = __uint_as_float(f2tf32(v.y - h1));
            sBlo[(kk + 2) * 72 + jn] = __uint_as_float(f2tf32(v.z - h2));
            sBlo[(kk + 3) * 72 + jn] = __uint_as_float(f2tf32(v.w - h3));
        }
        __syncthreads();

#pragma unroll
        for (int k8 = 0; k8 < 16; k8 += 8) {
            int ra = lane >> 2, ca = k8 + (lane & 3);
            uint32_t ah[2][4], al[2][4];
#pragma unroll
            for (int mi = 0; mi < 2; mi++) {
                int r0 = mrow + mi * 16 + ra;
                ah[mi][0] = __float_as_uint(sAhi[r0 * 20 + ca]);
                ah[mi][1] = __float_as_uint(sAhi[(r0 + 8) * 20 + ca]);
                ah[mi][2] = __float_as_uint(sAhi[r0 * 20 + ca + 4]);
                ah[mi][3] = __float_as_uint(sAhi[(r0 + 8) * 20 + ca + 4]);
                al[mi][0] = __float_as_uint(sAlo[r0 * 20 + ca]);
                al[mi][1] = __float_as_uint(sAlo[(r0 + 8) * 20 + ca]);
                al[mi][2] = __float_as_uint(sAlo[r0 * 20 + ca + 4]);
                al[mi][3] = __float_as_uint(sAlo[(r0 + 8) * 20 + ca + 4]);
            }
            int kb = k8 + (lane & 3);
#pragma unroll
            for (int nj = 0; nj < 4; nj++) {
                int cn = nbase + nj * 8 + (lane >> 2);
                uint32_t bh0 = __float_as_uint(sBhi[kb * 72 + cn]);
                uint32_t bh1 = __float_as_uint(sBhi[(kb + 4) * 72 + cn]);
                uint32_t bl0 = __float_as_uint(sBlo[kb * 72 + cn]);
                uint32_t bl1 = __float_as_uint(sBlo[(kb + 4) * 72 + cn]);
#pragma unroll
                for (int mi = 0; mi < 2; mi++) {
#define LIN1_MMA(AV0,AV1,AV2,AV3,BV0,BV1) \
    asm volatile("mma.sync.aligned.m16n8k8.row.col.f32.tf32.tf32.f32 " \
                 "{%0,%1,%2,%3}, {%4,%5,%6,%7}, {%8,%9}, {%0,%1,%2,%3};" \
                 : "+f"(acc[mi][nj][0]), "+f"(acc[mi][nj][1]), \
                   "+f"(acc[mi][nj][2]), "+f"(acc[mi][nj][3]) \
                 : "r"(AV0), "r"(AV1), "r"(AV2), "r"(AV3), "r"(BV0), "r"(BV1))
                    LIN1_MMA(ah[mi][0], ah[mi][1], ah[mi][2], ah[mi][3], bh0, bh1);
                    LIN1_MMA(ah[mi][0], ah[mi][1], ah[mi][2], ah[mi][3], bl0, bl1);
                    LIN1_MMA(al[mi][0], al[mi][1], al[mi][2], al[mi][3], bh0, bh1);
#undef LIN1_MMA
                }
            }
        }
        __syncthreads();
    }

#pragma unroll
    for (int mi = 0; mi < 2; mi++) {
#pragma unroll
        for (int nj = 0; nj < 4; nj++) {
            int x = mrow + mi * 16 + (lane >> 2);
            int co = nbase + nj * 8 + (lane & 3) * 2;
            float b0 = bias[co], b1 = bias[co + 1];
            float2 v0; v0.x = acc[mi][nj][0] + b0; v0.y = acc[mi][nj][1] + b1;
            *(float2*)(C + (size_t)(m0 + x) * 64 + co) = v0;
            float2 v1; v1.x = acc[mi][nj][2] + b0; v1.y = acc[mi][nj][3] + b1;
            *(float2*)(C + (size_t)(m0 + x + 8) * 64 + co) = v1;
        }
    }
}

// ---------------- tiled SIMT GEMM (gi): pack-at-use f32x2 (R7) ----------------
template<bool WT>
__global__ void gemm_bias(const float* __restrict__ A, const float* __restrict__ Bm,
                          const float* __restrict__ bias, float* __restrict__ C,
                          int M, int N, int K, long sA, long sB, long sC)
{
    A  += (long)blockIdx.z * sA;
    Bm += (long)blockIdx.z * sB;
    C  += (long)blockIdx.z * sC;
    __shared__ __align__(16) float sAi[64][17];
    __shared__ __align__(16) float sBi[16][68];
    int tid = threadIdx.x;          // 128
    int ttx = tid & 15, tty = tid >> 4;
    int m0 = blockIdx.x * 64, n0 = blockIdx.y * 64;
    unsigned long long acc2[8][2];
#pragma unroll
    for (int i = 0; i < 8; i++) { acc2[i][0] = 0ull; acc2[i][1] = 0ull; }

    for (int k0 = 0; k0 < K; k0 += 16) {
#pragma unroll
        for (int l = 0; l < 8; l++) {
            int e = tid + l * 128;
            int mm = e >> 4, kk = e & 15;
            int m = m0 + mm;
            sAi[mm][kk] = (m < M) ? A[(long)m * K + k0 + kk] : 0.f;
        }
#pragma unroll
        for (int l = 0; l < 8; l++) {
            int e = tid + l * 128;
            if (WT) {
                int j = e >> 4, kk = e & 15;
                int jn = n0 + j;
                sBi[kk][j] = (jn < N) ? Bm[(long)jn * K + k0 + kk] : 0.f;
            } else {
                int kk = e >> 6, j = e & 63;
                int jn = n0 + j;
                sBi[kk][j] = (jn < N) ? Bm[(long)(k0 + kk) * N + jn] : 0.f;
            }
        }
        __syncthreads();
#pragma unroll
        for (int kk = 0; kk < 16; kk++) {
            unsigned long long b0 = *(const unsigned long long*)&sBi[kk][ttx * 4];
            unsigned long long b1 = *(const unsigned long long*)&sBi[kk][ttx * 4 + 2];
#pragma unroll
            for (int i = 0; i < 8; i++) {
                float as = sAi[tty * 8 + i][kk];
                unsigned long long ap = pack2(as, as);
                acc2[i][0] = fma2(ap, b0, acc2[i][0]);
                acc2[i][1] = fma2(ap, b1, acc2[i][1]);
            }
        }
        __syncthreads();
    }
#pragma unroll
    for (int i = 0; i < 8; i++) {
        int m = m0 + tty * 8 + i;
        if (m < M) {
            int j0 = n0 + ttx * 4;
            float4 v;
            unpack2(acc2[i][0], v.x, v.y);
            unpack2(acc2[i][1], v.z, v.w);
            v.x += bias ? bias[j0 + 0] : 0.f;
            v.y += bias ? bias[j0 + 1] : 0.f;
            v.z += bias ? bias[j0 + 2] : 0.f;
            v.w += bias ? bias[j0 + 3] : 0.f;
            *(float4*)&C[(long)m * N + j0] = v;
        }
    }
}

// ------- GRU (R7): 192 thr, scalar stride-4 dot, fast activations, 2 barriers --------
__global__ void gru_kernel(const float* __restrict__ gi, const float* __restrict__ W_hh,
                           const float* __restrict__ b_hh, float* __restrict__ hs)
{
    int branch = blockIdx.x;
    int i = threadIdx.x; // 0..191
    const float* g = gi + (size_t)branch * (16 * 496 * 192);
    float* out = hs + (size_t)branch * (16 * 496 * 64);
    float w[64];
#pragma unroll
    for (int j = 0; j < 64; j++) w[j] = W_hh[(size_t)i * 64 + j];
    float bh = b_hh[i];
    __shared__ float h_sh[64], r_sh[64], z_sh[64];
    if (i < 64) h_sh[i] = 0.f;
    __syncthreads();
    const int L = 16 * 496;
    float gcur = g[i];
    for (int t = 0; t < L; t++) {
        float gnext = (t + 1 < L) ? g[(size_t)(t + 1) * 192 + i] : 0.f;
        float s0 = 0.f, s1 = 0.f, s2 = 0.f, s3 = 0.f;
#pragma unroll
        for (int j = 0; j < 64; j += 4) {
            s0 += w[j + 0] * h_sh[j + 0];
            s1 += w[j + 1] * h_sh[j + 1];
            s2 += w[j + 2] * h_sh[j + 2];
            s3 += w[j + 3] * h_sh[j + 3];
        }
        float s = bh + ((s0 + s1) + (s2 + s3));
        if (i < 64) {
            r_sh[i] = __fdividef(1.f, 1.f + __expf(-(gcur + s)));
        } else if (i < 128) {
            z_sh[i - 64] = __fdividef(1.f, 1.f + __expf(-(gcur + s)));
        }
        __syncthreads();
        if (i >= 128) {
            int j = i - 128;
            float x = gcur + r_sh[j] * s;
            float e = __expf(-2.f * fabsf(x));
            float nt = __fdividef(1.f - e, 1.f + e);
            nt = copysignf(nt, x);
            float z = z_sh[j];
            float hn = (1.f - z) * nt + z * h_sh[j];
            h_sh[j] = hn;
            out[(size_t)t * 64 + j] = hn;
        }
        __syncthreads();
        gcur = gnext;
    }
}

// ---------------- attention stats: column max & inv-sum of exp ----------------
__global__ void attn_stats(const float* __restrict__ hs, float* __restrict__ mxo,
                           float* __restrict__ ivo)
{
    int b = blockIdx.y;
    int n0 = blockIdx.x * 8;
    const float* E  = hs + (size_t)b * 496 * 64;
    const float* Tm = hs + (size_t)(16 + b) * 496 * 64;
    __shared__ float tm_sh[8][64];
    __shared__ float lg[496][9];
    int tid = threadIdx.x; // 256
    for (int e = tid; e < 8 * 64; e += 256)
        tm_sh[e >> 6][e & 63] = Tm[(size_t)(n0 + (e >> 6)) * 64 + (e & 63)];
    __syncthreads();
    for (int m = tid; m < 496; m += 256) {
        const float4* Er = (const float4*)(E + (size_t)m * 64);
        float acc[8];
#pragma unroll
        for (int nn = 0; nn < 8; nn++) acc[nn] = 0.f;
#pragma unroll
        for (int j4 = 0; j4 < 16; j4++) {
            float4 v = Er[j4];
#pragma unroll
            for (int nn = 0; nn < 8; nn++) {
                acc[nn] += v.x * tm_sh[nn][j4 * 4 + 0];
                acc[nn] += v.y * tm_sh[nn][j4 * 4 + 1];
                acc[nn] += v.z * tm_sh[nn][j4 * 4 + 2];
                acc[nn] += v.w * tm_sh[nn][j4 * 4 + 3];
            }
        }
#pragma unroll
        for (int nn = 0; nn < 8; nn++) lg[m][nn] = acc[nn];
    }
    __syncthreads();
    int wg = tid >> 5, lane = tid & 31;
    float mx = -INFINITY;
    for (int m = lane; m < 496; m += 32) mx = fmaxf(mx, lg[m][wg]);
#pragma unroll
    for (int o = 16; o; o >>= 1) mx = fmaxf(mx, __shfl_xor_sync(0xffffffffu, mx, o));
    float sum = 0.f;
    for (int m = lane; m < 496; m += 32) sum += __expf(lg[m][wg] - mx);
#pragma unroll
    for (int o = 16; o; o >>= 1) sum += __shfl_xor_sync(0xffffffffu, sum, o);
    if (lane == 0) {
        mxo[b * 512 + n0 + wg] = mx;
        ivo[b * 512 + n0 + wg] = 1.f / sum;
    }
}

// ---------------- fused Tp: recompute logits, exp, contract with Tm ----------------
__global__ __launch_bounds__(256) void tp_fused(const float* __restrict__ hs,
                                                const float* __restrict__ mxv,
                                                const float* __restrict__ ivv,
                                                float* __restrict__ Tp)
{
    extern __shared__ float sm[];
    float* sE  = sm;               // 64 x 68
    float* sTm = sm + 64 * 68;     // 64 x 68
    float* sP  = sm + 2 * 64 * 68; // 64 x 68
    int b = blockIdx.y;
    int m0 = blockIdx.x * 64;
    const float* E  = hs + (size_t)b * 496 * 64;
    const float* Tm = hs + (size_t)(16 + b) * 496 * 64;
    int tid = threadIdx.x;
    int tx = tid & 15, ty = tid >> 4;

    for (int e = tid; e < 64 * 16; e += 256) {
        int r = e >> 4, c4 = (e & 15) * 4;
        float4 v = (m0 + r < 496) ? *(const float4*)(E + (size_t)(m0 + r) * 64 + c4)
                                  : make_float4(0.f, 0.f, 0.f, 0.f);
        *(float4*)&sE[r * 68 + c4] = v;
    }

    float acc[4][4];
#pragma unroll
    for (int ii = 0; ii < 4; ii++)
#pragma unroll
        for (int dd = 0; dd < 4; dd++) acc[ii][dd] = 0.f;

    for (int n0 = 0; n0 < 496; n0 += 64) {
        for (int e = tid; e < 64 * 16; e += 256) {
            int r = e >> 4, c4 = (e & 15) * 4;
            float4 v = (n0 + r < 496) ? *(const float4*)(Tm + (size_t)(n0 + r) * 64 + c4)
                                      : make_float4(0.f, 0.f, 0.f, 0.f);
            *(float4*)&sTm[r * 68 + c4] = v;
        }
        __syncthreads();

        float s4[4][4];
#pragma unroll
        for (int ii = 0; ii < 4; ii++)
#pragma unroll
            for (int jj = 0; jj < 4; jj++) s4[ii][jj] = 0.f;
#pragma unroll
        for (int k4 = 0; k4 < 16; k4++) {
            float4 a[4], bb[4];
#pragma unroll
            for (int ii = 0; ii < 4; ii++)
                a[ii] = *(float4*)&sE[(ty * 4 + ii) * 68 + k4 * 4];
#pragma unroll
            for (int jj = 0; jj < 4; jj++)
                bb[jj] = *(float4*)&sTm[(tx * 4 + jj) * 68 + k4 * 4];
#pragma unroll
            for (int ii = 0; ii < 4; ii++)
#pragma unroll
                for (int jj = 0; jj < 4; jj++)
                    s4[ii][jj] += a[ii].x * bb[jj].x + a[ii].y * bb[jj].y
                                + a[ii].z * bb[jj].z + a[ii].w * bb[jj].w;
        }
#pragma unroll
        for (int jj = 0; jj < 4; jj++) {
            int nn = n0 + tx * 4 + jj;
            float mxn = (nn < 496) ? mxv[b * 512 + nn] : 0.f;
            float ivn = (nn < 496) ? ivv[b * 512 + nn] : 0.f;
#pragma unroll
            for (int ii = 0; ii < 4; ii++)
                sP[(ty * 4 + ii) * 68 + tx * 4 + jj] =
                    (nn < 496) ? __expf(s4[ii][jj] - mxn) * ivn : 0.f;
        }
        __syncthreads();
#pragma unroll 2
        for (int j = 0; j < 64; j++) {
            float4 bv = *(float4*)&sTm[j * 68 + tx * 4];
            float p0 = sP[(ty * 4 + 0) * 68 + j];
            float p1 = sP[(ty * 4 + 1) * 68 + j];
            float p2 = sP[(ty * 4 + 2) * 68 + j];
            float p3 = sP[(ty * 4 + 3) * 68 + j];
            acc[0][0] += p0 * bv.x; acc[0][1] += p0 * bv.y; acc[0][2] += p0 * bv.z; acc[0][3] += p0 * bv.w;
            acc[1][0] += p1 * bv.x; acc[1][1] += p1 * bv.y; acc[1][2] += p1 * bv.z; acc[1][3] += p1 * bv.w;
            acc[2][0] += p2 * bv.x; acc[2][1] += p2 * bv.y; acc[2][2] += p2 * bv.z; acc[2][3] += p2 * bv.w;
            acc[3][0] += p3 * bv.x; acc[3][1] += p3 * bv.y; acc[3][2] += p3 * bv.z; acc[3][3] += p3 * bv.w;
        }
        __syncthreads();
    }
#pragma unroll
    for (int ii = 0; ii < 4; ii++) {
        int m = m0 + ty * 4 + ii;
        if (m < 496) {
            float4 v; v.x = acc[ii][0]; v.y = acc[ii][1]; v.z = acc[ii][2]; v.w = acc[ii][3];
            *(float4*)&Tp[((size_t)b * 496 + m) * 64 + tx * 4] = v;
        }
    }
}

// ---------------- fused head ----------------
__global__ void final_kernel(const float* __restrict__ hs, const float* __restrict__ Tp,
                             const float* __restrict__ aw, const float* __restrict__ ab,
                             const float* __restrict__ l3w, const float* __restrict__ l3b,
                             const float* __restrict__ cw, const float* __restrict__ cb,
                             float* __restrict__ outp)
{
    int b = blockIdx.x;
    int tid = threadIdx.x; // 256
    const float* E   = hs + (size_t)b * 496 * 64;
    const float* Tpb = Tp + (size_t)b * 496 * 64;
    __shared__ float att[496];
    __shared__ float red[256];
    __shared__ float part[4][64];
    __shared__ float hrep[64];
    __shared__ float h2[128];
    __shared__ float aw_sh[64];
    if (tid < 64) aw_sh[tid] = aw[tid];
    __syncthreads();
    float lmax = -INFINITY;
    for (int s = tid; s < 496; s += 256) {
        const float* er = E + (size_t)s * 64;
        float acc = ab[0];
#pragma unroll
        for (int j = 0; j < 64; j++) acc += er[j] * aw_sh[j];
        att[s] = acc;
        lmax = fmaxf(lmax, acc);
    }
    red[tid] = lmax;
    __syncthreads();
    for (int o = 128; o; o >>= 1) {
        if (tid < o) red[tid] = fmaxf(red[tid], red[tid + o]);
        __syncthreads();
    }
    float mx = red[0];
    __syncthreads();
    float lsum = 0.f;
    for (int s = tid; s < 496; s += 256) {
        float e = __expf(att[s] - mx);
        att[s] = e;
        lsum += e;
    }
    red[tid] = lsum;
    __syncthreads();
    for (int o = 128; o; o >>= 1) {
        if (tid < o) red[tid] += red[tid + o];
        __syncthreads();
    }
    float inv = 1.f / red[0];
    int d = tid & 63, grp = tid >> 6;
    float acc = 0.f;
    for (int s = grp; s < 496; s += 4)
        acc += att[s] * fabsf(Tpb[(size_t)s * 64 + d] - E[(size_t)s * 64 + d]);
    part[grp][d] = acc;
    __syncthreads();
    if (tid < 64) {
        float r = (part[0][tid] + part[1][tid] + part[2][tid] + part[3][tid]) * inv;
        hrep[tid] = fmaxf(r, 0.f);
    }
    __syncthreads();
    if (tid < 128) {
        float a2 = l3b[tid];
#pragma unroll
        for (int j = 0; j < 64; j++) a2 += hrep[j] * l3w[(size_t)tid * 64 + j];
        h2[tid] = fmaxf(a2, 0.f);
    }
    __syncthreads();
    if (tid < 2) {
        float a3 = cb[tid];
#pragma unroll
        for (int j = 0; j < 128; j++) a3 += h2[j] * cw[(size_t)tid * 128 + j];
        outp[b * 2 + tid] = a3;
    }
}

// ---------------- launch ----------------
extern "C" void kernel_launch(void* const* d_in, const int* in_sizes, int n_in,
                              void* d_out, int out_size)
{
    const float* ev    = (const float*)d_in[0];
    const float* tmpl  = (const float*)d_in[1];
    const float* c1w   = (const float*)d_in[2];
    const float* c1b   = (const float*)d_in[3];
    const float* c2w   = (const float*)d_in[4];
    const float* c2b   = (const float*)d_in[5];
    const float* c3w   = (const float*)d_in[6];
    const float* c3b   = (const float*)d_in[7];
    const float* l1w   = (const float*)d_in[8];
    const float* l1b   = (const float*)d_in[9];
    const float* W_ih  = (const float*)d_in[10];
    const float* W_hh  = (const float*)d_in[11];
    const float* b_ih  = (const float*)d_in[12];
    const float* b_hh  = (const float*)d_in[13];
    const float* aw    = (const float*)d_in[14];
    const float* ab    = (const float*)d_in[15];
    const float* l3w   = (const float*)d_in[16];
    const float* l3b   = (const float*)d_in[17];
    const float* cw    = (const float*)d_in[18];
    const float* cb    = (const float*)d_in[19];
    float* outp = (float*)d_out;

    float *p_in, *p_c1, *p_c2, *p_c3, *p_pool, *p_x1, *p_gi, *p_hs, *p_Tp;
    float *p_wt2, *p_wt3, *p_mx, *p_iv;
    cudaGetSymbolAddress((void**)&p_in,   g_in);
    cudaGetSymbolAddress((void**)&p_c1,   g_c1);
    cudaGetSymbolAddress((void**)&p_c2,   g_c2);
    cudaGetSymbolAddress((void**)&p_c3,   g_c3);
    cudaGetSymbolAddress((void**)&p_pool, g_pool);
    cudaGetSymbolAddress((void**)&p_x1,   g_x1);
    cudaGetSymbolAddress((void**)&p_gi,   g_gi);
    cudaGetSymbolAddress((void**)&p_hs,   g_hs);
    cudaGetSymbolAddress((void**)&p_Tp,   g_Tp);
    cudaGetSymbolAddress((void**)&p_wt2,  g_wt2);
    cudaGetSymbolAddress((void**)&p_wt3,  g_wt3);
    cudaGetSymbolAddress((void**)&p_mx,   g_mx);
    cudaGetSymbolAddress((void**)&p_iv,   g_iv);

    const int smem2 = (8 * 2112 + 2 * 2560) * 4;    // 88,064 B
    const int smem3 = (3 * 4096 + 10240) * 4;       // 90,112 B (2 blocks/SM)
    const int smemp = 5 * 58 * 67 * 4;              // 77,720 B
    const int smemt = 3 * 64 * 68 * 4;              // 52,224 B
    cudaFuncSetAttribute(conv_mma2<16, 32, 508, 124>,
                         cudaFuncAttributeMaxDynamicSharedMemorySize, smem2);
    cudaFuncSetAttribute(conv_mma3,
                         cudaFuncAttributeMaxDynamicSharedMemorySize, smem3);
    cudaFuncSetAttribute(pool_ring,
                         cudaFuncAttributeMaxDynamicSharedMemorySize, smemp);
    cudaFuncSetAttribute(tp_fused,
                         cudaFuncAttributeMaxDynamicSharedMemorySize, smemt);

    prep_kernel<<<dim3(4, 16, 33), dim3(32, 8)>>>(ev, tmpl, c2w, c3w, p_in, p_wt2, p_wt3);
    conv1_nhwc<<<dim3(508, 32), 128>>>(p_in, c1w, c1b, p_c1);
    conv_mma2<16, 32, 508, 124><<<dim3(126, 32), 512, smem2>>>(p_c1, p_wt2, c2b, p_c2);
    conv_mma3<<<dim3(250, 32), 256, smem3>>>(p_c2, p_wt3, c3b, p_c3);
    pool_ring<<<dim3(8, 32), 256, smemp>>>(p_c3, p_pool);
    lin1_mma<<<124, 256>>>(p_pool, l1w, l1b, p_x1);
    gemm_bias<true><<<dim3(248, 3, 1), 128>>>(p_x1, W_ih, b_ih, p_gi,
                                              15872, 192, 64, 0, 0, 0);
    gru_kernel<<<2, 192>>>(p_gi, W_hh, b_hh, p_hs);
    attn_stats<<<dim3(62, 16), 256>>>(p_hs, p_mx, p_iv);
    tp_fused<<<dim3(8, 16), 256, smemt>>>(p_hs, p_mx, p_iv, p_Tp);
    final_kernel<<<16, 256>>>(p_hs, p_Tp, aw, ab, l3w, l3b, cw, cb, outp);
}

// round 17
// speedup vs baseline: 1.2264x; 1.0167x over previous
#include <cuda_runtime.h>
#include <math.h>
#include <stddef.h>
#include <stdint.h>
#include <string.h>

// ---------------- static scratch (no allocations allowed) ----------------
__device__ float g_in  [(size_t)32*512*128];          // (n, t, c)
__device__ float g_c1  [(size_t)32*508*124*16];       // NHWC
__device__ float g_c2  [(size_t)32*504*120*32];       // NHWC
__device__ float g_c3  [(size_t)32*500*116*64];       // NHWC
__device__ float g_pool[(size_t)32*64*496*58];        // (n, c, s, w) raw reshape layout
__device__ float g_x1  [(size_t)32*496*64];
__device__ float g_gi  [(size_t)32*496*192];
__device__ float g_hs  [(size_t)32*496*64];           // E (n<16) / Tm (n>=16)
__device__ float g_Tp  [(size_t)16*496*64];
__device__ float g_wt2 [(size_t)5*80*32];             // conv2 weights [dy][k8][co][pos]
__device__ float g_wt3 [(size_t)5*160*64];            // conv3 weights [dy][k8][co][pos]
__device__ float g_mx  [16*512];                      // column softmax stats
__device__ float g_iv  [16*512];

__device__ __forceinline__ uint32_t f2tf32(float x)
{
    uint32_t u;
    asm("cvt.rna.tf32.f32 %0, %1;" : "=r"(u) : "f"(x));
    return u;
}

__device__ __forceinline__ unsigned long long fma2(unsigned long long a,
                                                   unsigned long long b,
                                                   unsigned long long c)
{
    unsigned long long d;
    asm("fma.rn.f32x2 %0, %1, %2, %3;" : "=l"(d) : "l"(a), "l"(b), "l"(c));
    return d;
}

__device__ __forceinline__ unsigned long long pack2(float x, float y)
{
    unsigned long long d;
    asm("mov.b64 %0, {%1, %2};" : "=l"(d) : "f"(x), "f"(y));
    return d;
}

__device__ __forceinline__ void unpack2(unsigned long long v, float& x, float& y)
{
    asm("mov.b64 {%0, %1}, %2;" : "=f"(x), "=f"(y) : "l"(v));
}

// ---------------- prep: transpose (z<32) + weight reorders (z==32) ----------------
// B layout: [dy][k>>3][co][pos(k&7)], pos(j) = 2*(j&3) + (j>>2)
__global__ void prep_kernel(const float* __restrict__ ev, const float* __restrict__ tm,
                            const float* __restrict__ c2w, const float* __restrict__ c3w,
                            float* __restrict__ out, float* __restrict__ wt2,
                            float* __restrict__ wt3)
{
    if (blockIdx.z < 32) {
        __shared__ float tile[32][33];
        int n = blockIdx.z;
        const float* src = (n < 16) ? (ev + (size_t)n * 128 * 512)
                                    : (tm + (size_t)(n - 16) * 128 * 512);
        int x0 = blockIdx.x * 32;
        int y0 = blockIdx.y * 32;
        int lx = threadIdx.x, ly = threadIdx.y; // 32 x 8
        for (int r = ly; r < 32; r += 8)
            tile[r][lx] = src[(size_t)(x0 + r) * 512 + y0 + lx];
        __syncthreads();
        float* o = out + (size_t)n * 512 * 128;
        for (int r = ly; r < 32; r += 8)
            o[(size_t)(y0 + r) * 128 + x0 + lx] = tile[lx][r];
    } else {
        int pid = (blockIdx.y * 4 + blockIdx.x) * 256 + threadIdx.y * 32 + threadIdx.x;
        for (int idx = pid; idx < 12800; idx += 16384) {   // conv2: CIN=16, COUT=32
            int dx = idx % 5, dy = (idx / 5) % 5, ci = (idx / 25) % 16, co = idx / 400;
            int k = dx * 16 + ci;
            int j = k & 7;
            int pos = 2 * (j & 3) + (j >> 2);
            wt2[(size_t)dy * (80 * 32) + (k >> 3) * 256 + co * 8 + pos] =
                __uint_as_float(f2tf32(c2w[idx]));
        }
        for (int idx = pid; idx < 51200; idx += 16384) {   // conv3: CIN=32, COUT=64
            int dx = idx % 5, dy = (idx / 5) % 5, ci = (idx / 25) % 32, co = idx / 800;
            int k = dx * 32 + ci;
            int j = k & 7;
            int pos = 2 * (j & 3) + (j >> 2);
            wt3[(size_t)dy * (160 * 64) + (k >> 3) * 512 + co * 8 + pos] =
                __uint_as_float(f2tf32(c3w[idx]));
        }
    }
}

// ---------------- conv1: CIN=1, direct fp32, NHWC out ----------------
__global__ void conv1_nhwc(const float* __restrict__ in, const float* __restrict__ w,
                           const float* __restrict__ bias, float* __restrict__ out)
{
    __shared__ float srow[5][128];
    __shared__ float sw[16][25];
    __shared__ float sb[16];
    int y = blockIdx.x, n = blockIdx.y, tid = threadIdx.x;  // 128 threads
    const float* ip = in + ((size_t)n * 512 + y) * 128;
#pragma unroll
    for (int r = 0; r < 5; r++) srow[r][tid] = ip[(size_t)r * 128 + tid];
    if (tid < 16) sb[tid] = bias[tid];
    for (int e = tid; e < 400; e += 128) sw[e / 25][e % 25] = w[e];
    __syncthreads();
    if (tid >= 124) return;
    float acc[16];
#pragma unroll
    for (int co = 0; co < 16; co++) acc[co] = sb[co];
#pragma unroll
    for (int dy = 0; dy < 5; dy++) {
#pragma unroll
        for (int dx = 0; dx < 5; dx++) {
            float v = srow[dy][tid + dx];
#pragma unroll
            for (int co = 0; co < 16; co++) acc[co] += v * sw[co][dy * 5 + dx];
        }
    }
    float4* op = (float4*)(out + (((size_t)n * 508 + y) * 124 + tid) * 16);
#pragma unroll
    for (int q = 0; q < 4; q++) {
        float4 v; v.x = acc[q*4]; v.y = acc[q*4+1]; v.z = acc[q*4+2]; v.w = acc[q*4+3];
        op[q] = v;
    }
}

// ----- ring implicit-GEMM conv: 256 thr, 2 y-rows, ring-A(3 slots) + single-B --------
// MNB = minBlocksPerMultiprocessor target for launch_bounds.
template<int CIN, int COUT, int HIN, int WIN, int MNB>
__global__ __launch_bounds__(256, MNB) void conv_ring(const float* __restrict__ in,
                                                      const float* __restrict__ wt,
                                                      const float* __restrict__ bias,
                                                      float* __restrict__ out)
{
    constexpr int HOUT = HIN - 4, WOUT = WIN - 4;
    constexpr int ROWF = 128 * CIN;       // staged words per row slot
    constexpr int KDY = 5 * CIN;
    constexpr int BSZ = KDY * COUT;
    constexpr int A_SHIFT = (CIN == 32) ? 5 : 4;
    constexpr int MI = (COUT == 64) ? 4 : 2;

    extern __shared__ float smem[];
    float* sA = smem;                     // 3 slots x ROWF
    float* sB = smem + 3 * ROWF;          // BSZ (single buffer)
    uint32_t* sAu = (uint32_t*)sA;

    int tid = threadIdx.x;
    int lane = tid & 31, warp = tid >> 5; // 8 warps
    int y0 = blockIdx.x * 2, n = blockIdx.y;
    int wy = warp >> 2;                   // 0..1
    int wsub = warp & 3;
    int mrow, nbase;
    if (COUT == 64) { mrow = (wsub & 1) * 64; nbase = (wsub >> 1) * 32; }
    else            { mrow = wsub * 32;       nbase = 0; }

    int ra = lane >> 2;
    int kfrac = lane & 3;
    int cidx[4];
#pragma unroll
    for (int nj = 0; nj < 4; nj++)
        cidx[nj] = (nbase + nj * 8 + ra) * 4 + kfrac;

    int lrow = lane & 15;
    int lcol = (lane >> 4) * 4;
    int linv[MI];
#pragma unroll
    for (int mi = 0; mi < MI; mi++)
        linv[mi] = (mrow + mi * 16 + lrow) * CIN + lcol;

    uint32_t sA_sh = (uint32_t)__cvta_generic_to_shared(sAu);

    float acc[MI][4][4];
#pragma unroll
    for (int mi = 0; mi < MI; mi++)
#pragma unroll
        for (int nj = 0; nj < 4; nj++)
#pragma unroll
            for (int q = 0; q < 4; q++) acc[mi][nj][q] = 0.f;

    const int WVALID = WIN * CIN;

    // stage relative row rr (0..5) into slot rr%3 (tf32 + swizzle)
#define STAGE_ROW(RR)                                                           \
    {                                                                           \
        int slot_ = (RR) % 3;                                                   \
        const float* inrow_ = in + ((size_t)(n * HIN + y0 + (RR)) * WIN) * CIN; \
        for (int l = tid * 4; l < ROWF; l += 1024) {                            \
            float4 v;                                                           \
            if (l + 4 <= WVALID) v = *(const float4*)(inrow_ + l);              \
            else { v.x = v.y = v.z = v.w = 0.f; }                               \
            uint4 u;                                                            \
            u.x = f2tf32(v.x); u.y = f2tf32(v.y);                               \
            u.z = f2tf32(v.z); u.w = f2tf32(v.w);                               \
            int p = l ^ (((l >> A_SHIFT) & 7) << 2);                            \
            *(uint4*)(sAu + slot_ * ROWF + p) = u;                              \
        }                                                                       \
    }

    STAGE_ROW(0)
    STAGE_ROW(1)
    for (int l = tid * 4; l < BSZ; l += 1024) {
        uint32_t da = (uint32_t)__cvta_generic_to_shared(sB + l);
        asm volatile("cp.async.ca.shared.global [%0], [%1], 16;\n"
                     :: "r"(da), "l"(wt + l));
    }
    asm volatile("cp.async.commit_group;\n");
    asm volatile("cp.async.wait_group 0;\n");
    __syncthreads();

#pragma unroll 1
    for (int dy = 0; dy < 5; dy++) {
        int abase = ((wy + dy) % 3) * ROWF;
        const float2* sB2 = (const float2*)sB;
#pragma unroll
        for (int k8 = 0; k8 < KDY; k8 += 8) {
            uint32_t a[MI][4];
#pragma unroll
            for (int mi = 0; mi < MI; mi++) {
                int l0 = linv[mi] + k8;
                int p = l0 ^ (((l0 >> A_SHIFT) & 7) << 2);
                uint32_t addr = sA_sh + (uint32_t)(abase + p) * 4u;
                asm volatile(
                    "ldmatrix.sync.aligned.m8n8.x4.shared.b16 {%0,%1,%2,%3}, [%4];"
                    : "=r"(a[mi][0]), "=r"(a[mi][1]), "=r"(a[mi][2]), "=r"(a[mi][3])
                    : "r"(addr));
            }
            const float2* pb = sB2 + (k8 >> 3) * (4 * COUT);
#pragma unroll
            for (int nj = 0; nj < 4; nj++) {
                float2 bb = pb[cidx[nj]];
                uint32_t b0 = __float_as_uint(bb.x);
                uint32_t b1 = __float_as_uint(bb.y);
#pragma unroll
                for (int mi = 0; mi < MI; mi++) {
                    asm volatile(
                        "mma.sync.aligned.m16n8k8.row.col.f32.tf32.tf32.f32 "
                        "{%0,%1,%2,%3}, {%4,%5,%6,%7}, {%8,%9}, {%0,%1,%2,%3};"
                        : "+f"(acc[mi][nj][0]), "+f"(acc[mi][nj][1]),
                          "+f"(acc[mi][nj][2]), "+f"(acc[mi][nj][3])
                        : "r"(a[mi][0]), "r"(a[mi][1]), "r"(a[mi][2]), "r"(a[mi][3]),
                          "r"(b0), "r"(b1));
                }
            }
        }
        if (dy < 4) {
            __syncthreads();               // everyone done with sB + old A slot
            STAGE_ROW(dy + 2)
            const float* wrow = wt + (size_t)(dy + 1) * BSZ;
            for (int l = tid * 4; l < BSZ; l += 1024) {
                uint32_t da = (uint32_t)__cvta_generic_to_shared(sB + l);
                asm volatile("cp.async.ca.shared.global [%0], [%1], 16;\n"
                             :: "r"(da), "l"(wrow + l));
            }
            asm volatile("cp.async.commit_group;\n");
            asm volatile("cp.async.wait_group 0;\n");
            __syncthreads();
        }
    }
#undef STAGE_ROW

    int y = y0 + wy;
    size_t obase = ((size_t)(n * HOUT + y) * WOUT) * COUT;
#pragma unroll
    for (int mi = 0; mi < MI; mi++) {
#pragma unroll
        for (int nj = 0; nj < 4; nj++) {
            int x = mrow + mi * 16 + ra;
            int co = nbase + nj * 8 + kfrac * 2;
            float b0 = bias[co], b1 = bias[co + 1];
            if (x < WOUT) {
                float2 v; v.x = acc[mi][nj][0] + b0; v.y = acc[mi][nj][1] + b1;
                *(float2*)(out + obase + (size_t)x * COUT + co) = v;
            }
            if (x + 8 < WOUT) {
                float2 v; v.x = acc[mi][nj][2] + b0; v.y = acc[mi][nj][3] + b1;
                *(float2*)(out + obase + (size_t)(x + 8) * COUT + co) = v;
            }
        }
    }
}

// ---------------- maxpool ring: each conv3 row read once ----------------
__global__ void pool_ring(const float* __restrict__ in, float* __restrict__ out)
{
    extern __shared__ float ring[];   // 5 x (58*67)
    const int RP = 58 * 67;
    int strip = blockIdx.x, n = blockIdx.y, tid = threadIdx.x; // 256 threads
    int s0 = strip * 62;
    float* ob = out + (size_t)n * 64 * 496 * 58;
    for (int y = s0; y < s0 + 66; y++) {
        const float* ip = in + ((size_t)(n * 500 + y) * 116) * 64;
        int rr = (y - s0) % 5;
        for (int idx = tid; idx < 3712; idx += 256) {
            int wp = idx >> 6, c = idx & 63;
            float a = ip[(size_t)(2 * wp) * 64 + c];
            float b = ip[(size_t)(2 * wp) * 64 + 64 + c];
            ring[rr * RP + wp * 67 + c] = fmaxf(a, b);
        }
        __syncthreads();
        if (y - s0 >= 4) {
            int s = y - 4;
            for (int f = tid; f < 3712; f += 256) {
                int c = f / 58, wp = f % 58;
                int o = wp * 67 + c;
                float m = ring[o];
                m = fmaxf(m, ring[RP + o]);
                m = fmaxf(m, ring[2 * RP + o]);
                m = fmaxf(m, ring[3 * RP + o]);
                m = fmaxf(m, ring[4 * RP + o]);
                ob[(size_t)c * 496 * 58 + (size_t)s * 58 + wp] = m;
            }
        }
        __syncthreads();
    }
}

// ---------------- lin1: split-tf32 MMA GEMM, M=15872 K=3712 N=64 (R7) ----------------
__global__ __launch_bounds__(256) void lin1_mma(const float* __restrict__ A,
                                                const float* __restrict__ W,
                                                const float* __restrict__ bias,
                                                float* __restrict__ C)
{
    const int K = 3712;
    __shared__ float sAhi[128 * 20], sAlo[128 * 20];
    __shared__ float sBhi[16 * 72], sBlo[16 * 72];
    int tid = threadIdx.x;
    int lane = tid & 31, warp = tid >> 5;      // 8 warps
    int m0 = blockIdx.x * 128;
    int mrow = (warp & 3) * 32;
    int nbase = (warp >> 2) * 32;

    float acc[2][4][4];
#pragma unroll
    for (int mi = 0; mi < 2; mi++)
#pragma unroll
        for (int nj = 0; nj < 4; nj++)
#pragma unroll
            for (int q = 0; q < 4; q++) acc[mi][nj][q] = 0.f;

    for (int k0 = 0; k0 < K; k0 += 16) {
#pragma unroll
        for (int pass = 0; pass < 2; pass++) {
            int l = tid * 4 + pass * 1024;
            int row = l >> 4, kk = l & 15;
            float4 v = *(const float4*)(A + (size_t)(m0 + row) * K + k0 + kk);
            float hx = __uint_as_float(f2tf32(v.x));
            float hy = __uint_as_float(f2tf32(v.y));
            float hz = __uint_as_float(f2tf32(v.z));
            float hw = __uint_as_float(f2tf32(v.w));
            float* ph = sAhi + row * 20 + kk;
            float* pl = sAlo + row * 20 + kk;
            ph[0] = hx; ph[1] = hy; ph[2] = hz; ph[3] = hw;
            pl[0] = __uint_as_float(f2tf32(v.x - hx));
            pl[1] = __uint_as_float(f2tf32(v.y - hy));
            pl[2] = __uint_as_float(f2tf32(v.z - hz));
            pl[3] = __uint_as_float(f2tf32(v.w - hw));
        }
        {
            int l = tid * 4;
            int jn = l >> 4, kk = l & 15;
            float4 v = *(const float4*)(W + (size_t)jn * K + k0 + kk);
            float h0 = __uint_as_float(f2tf32(v.x));
            float h1 = __uint_as_float(f2tf32(v.y));
            float h2 = __uint_as_float(f2tf32(v.z));
            float h3 = __uint_as_float(f2tf32(v.w));
            sBhi[(kk + 0) * 72 + jn] = h0;
            sBhi[(kk + 1) * 72 + jn] = h1;
            sBhi[(kk + 2) * 72 + jn] = h2;
            sBhi[(kk + 3) * 72 + jn] = h3;
            sBlo[(kk + 0) * 72 + jn] = __uint_as_float(f2tf32(v.x - h0));
            sBlo[(kk + 1) * 72 + jn] = __uint_as_float(f2tf32(v.y - h1));
            sBlo[(kk + 2) * 72 + jn] = __uint_as_float(f2tf32(v.z - h2));
            sBlo[(kk + 3) * 72 + jn] = __uint_as_float(f2tf32(v.w - h3));
        }
        __syncthreads();

#pragma unroll
        for (int k8 = 0; k8 < 16; k8 += 8) {
            int ra = lane >> 2, ca = k8 + (lane & 3);
            uint32_t ah[2][4], al[2][4];
#pragma unroll
            for (int mi = 0; mi < 2; mi++) {
                int r0 = mrow + mi * 16 + ra;
                ah[mi][0] = __float_as_uint(sAhi[r0 * 20 + ca]);
                ah[mi][1] = __float_as_uint(sAhi[(r0 + 8) * 20 + ca]);
                ah[mi][2] = __float_as_uint(sAhi[r0 * 20 + ca + 4]);
                ah[mi][3] = __float_as_uint(sAhi[(r0 + 8) * 20 + ca + 4]);
                al[mi][0] = __float_as_uint(sAlo[r0 * 20 + ca]);
                al[mi][1] = __float_as_uint(sAlo[(r0 + 8) * 20 + ca]);
                al[mi][2] = __float_as_uint(sAlo[r0 * 20 + ca + 4]);
                al[mi][3] = __float_as_uint(sAlo[(r0 + 8) * 20 + ca + 4]);
            }
            int kb = k8 + (lane & 3);
#pragma unroll
            for (int nj = 0; nj < 4; nj++) {
                int cn = nbase + nj * 8 + (lane >> 2);
                uint32_t bh0 = __float_as_uint(sBhi[kb * 72 + cn]);
                uint32_t bh1 = __float_as_uint(sBhi[(kb + 4) * 72 + cn]);
                uint32_t bl0 = __float_as_uint(sBlo[kb * 72 + cn]);
                uint32_t bl1 = __float_as_uint(sBlo[(kb + 4) * 72 + cn]);
#pragma unroll
                for (int mi = 0; mi < 2; mi++) {
#define LIN1_MMA(AV0,AV1,AV2,AV3,BV0,BV1) \
    asm volatile("mma.sync.aligned.m16n8k8.row.col.f32.tf32.tf32.f32 " \
                 "{%0,%1,%2,%3}, {%4,%5,%6,%7}, {%8,%9}, {%0,%1,%2,%3};" \
                 : "+f"(acc[mi][nj][0]), "+f"(acc[mi][nj][1]), \
                   "+f"(acc[mi][nj][2]), "+f"(acc[mi][nj][3]) \
                 : "r"(AV0), "r"(AV1), "r"(AV2), "r"(AV3), "r"(BV0), "r"(BV1))
                    LIN1_MMA(ah[mi][0], ah[mi][1], ah[mi][2], ah[mi][3], bh0, bh1);
                    LIN1_MMA(ah[mi][0], ah[mi][1], ah[mi][2], ah[mi][3], bl0, bl1);
                    LIN1_MMA(al[mi][0], al[mi][1], al[mi][2], al[mi][3], bh0, bh1);
#undef LIN1_MMA
                }
            }
        }
        __syncthreads();
    }

#pragma unroll
    for (int mi = 0; mi < 2; mi++) {
#pragma unroll
        for (int nj = 0; nj < 4; nj++) {
            int x = mrow + mi * 16 + (lane >> 2);
            int co = nbase + nj * 8 + (lane & 3) * 2;
            float b0 = bias[co], b1 = bias[co + 1];
            float2 v0; v0.x = acc[mi][nj][0] + b0; v0.y = acc[mi][nj][1] + b1;
            *(float2*)(C + (size_t)(m0 + x) * 64 + co) = v0;
            float2 v1; v1.x = acc[mi][nj][2] + b0; v1.y = acc[mi][nj][3] + b1;
            *(float2*)(C + (size_t)(m0 + x + 8) * 64 + co) = v1;
        }
    }
}

// ---------------- tiled SIMT GEMM (gi): pack-at-use f32x2 (R7) ----------------
template<bool WT>
__global__ void gemm_bias(const float* __restrict__ A, const float* __restrict__ Bm,
                          const float* __restrict__ bias, float* __restrict__ C,
                          int M, int N, int K, long sA, long sB, long sC)
{
    A  += (long)blockIdx.z * sA;
    Bm += (long)blockIdx.z * sB;
    C  += (long)blockIdx.z * sC;
    __shared__ __align__(16) float sAi[64][17];
    __shared__ __align__(16) float sBi[16][68];
    int tid = threadIdx.x;          // 128
    int ttx = tid & 15, tty = tid >> 4;
    int m0 = blockIdx.x * 64, n0 = blockIdx.y * 64;
    unsigned long long acc2[8][2];
#pragma unroll
    for (int i = 0; i < 8; i++) { acc2[i][0] = 0ull; acc2[i][1] = 0ull; }

    for (int k0 = 0; k0 < K; k0 += 16) {
#pragma unroll
        for (int l = 0; l < 8; l++) {
            int e = tid + l * 128;
            int mm = e >> 4, kk = e & 15;
            int m = m0 + mm;
            sAi[mm][kk] = (m < M) ? A[(long)m * K + k0 + kk] : 0.f;
        }
#pragma unroll
        for (int l = 0; l < 8; l++) {
            int e = tid + l * 128;
            if (WT) {
                int j = e >> 4, kk = e & 15;
                int jn = n0 + j;
                sBi[kk][j] = (jn < N) ? Bm[(long)jn * K + k0 + kk] : 0.f;
            } else {
                int kk = e >> 6, j = e & 63;
                int jn = n0 + j;
                sBi[kk][j] = (jn < N) ? Bm[(long)(k0 + kk) * N + jn] : 0.f;
            }
        }
        __syncthreads();
#pragma unroll
        for (int kk = 0; kk < 16; kk++) {
            unsigned long long b0 = *(const unsigned long long*)&sBi[kk][ttx * 4];
            unsigned long long b1 = *(const unsigned long long*)&sBi[kk][ttx * 4 + 2];
#pragma unroll
            for (int i = 0; i < 8; i++) {
                float as = sAi[tty * 8 + i][kk];
                unsigned long long ap = pack2(as, as);
                acc2[i][0] = fma2(ap, b0, acc2[i][0]);
                acc2[i][1] = fma2(ap, b1, acc2[i][1]);
            }
        }
        __syncthreads();
    }
#pragma unroll
    for (int i = 0; i < 8; i++) {
        int m = m0 + tty * 8 + i;
        if (m < M) {
            int j0 = n0 + ttx * 4;
            float4 v;
            unpack2(acc2[i][0], v.x, v.y);
            unpack2(acc2[i][1], v.z, v.w);
            v.x += bias ? bias[j0 + 0] : 0.f;
            v.y += bias ? bias[j0 + 1] : 0.f;
            v.z += bias ? bias[j0 + 2] : 0.f;
            v.w += bias ? bias[j0 + 3] : 0.f;
            *(float4*)&C[(long)m * N + j0] = v;
        }
    }
}

// ------- GRU (R7): 192 thr, scalar stride-4 dot, fast activations, 2 barriers --------
__global__ void gru_kernel(const float* __restrict__ gi, const float* __restrict__ W_hh,
                           const float* __restrict__ b_hh, float* __restrict__ hs)
{
    int branch = blockIdx.x;
    int i = threadIdx.x; // 0..191
    const float* g = gi + (size_t)branch * (16 * 496 * 192);
    float* out = hs + (size_t)branch * (16 * 496 * 64);
    float w[64];
#pragma unroll
    for (int j = 0; j < 64; j++) w[j] = W_hh[(size_t)i * 64 + j];
    float bh = b_hh[i];
    __shared__ float h_sh[64], r_sh[64], z_sh[64];
    if (i < 64) h_sh[i] = 0.f;
    __syncthreads();
    const int L = 16 * 496;
    float gcur = g[i];
    for (int t = 0; t < L; t++) {
        float gnext = (t + 1 < L) ? g[(size_t)(t + 1) * 192 + i] : 0.f;
        float s0 = 0.f, s1 = 0.f, s2 = 0.f, s3 = 0.f;
#pragma unroll
        for (int j = 0; j < 64; j += 4) {
            s0 += w[j + 0] * h_sh[j + 0];
            s1 += w[j + 1] * h_sh[j + 1];
            s2 += w[j + 2] * h_sh[j + 2];
            s3 += w[j + 3] * h_sh[j + 3];
        }
        float s = bh + ((s0 + s1) + (s2 + s3));
        if (i < 64) {
            r_sh[i] = __fdividef(1.f, 1.f + __expf(-(gcur + s)));
        } else if (i < 128) {
            z_sh[i - 64] = __fdividef(1.f, 1.f + __expf(-(gcur + s)));
        }
        __syncthreads();
        if (i >= 128) {
            int j = i - 128;
            float x = gcur + r_sh[j] * s;
            float e = __expf(-2.f * fabsf(x));
            float nt = __fdividef(1.f - e, 1.f + e);
            nt = copysignf(nt, x);
            float z = z_sh[j];
            float hn = (1.f - z) * nt + z * h_sh[j];
            h_sh[j] = hn;
            out[(size_t)t * 64 + j] = hn;
        }
        __syncthreads();
        gcur = gnext;
    }
}

// ---------------- attention stats: column max & inv-sum of exp ----------------
__global__ void attn_stats(const float* __restrict__ hs, float* __restrict__ mxo,
                           float* __restrict__ ivo)
{
    int b = blockIdx.y;
    int n0 = blockIdx.x * 8;
    const float* E  = hs + (size_t)b * 496 * 64;
    const float* Tm = hs + (size_t)(16 + b) * 496 * 64;
    __shared__ float tm_sh[8][64];
    __shared__ float lg[496][9];
    int tid = threadIdx.x; // 256
    for (int e = tid; e < 8 * 64; e += 256)
        tm_sh[e >> 6][e & 63] = Tm[(size_t)(n0 + (e >> 6)) * 64 + (e & 63)];
    __syncthreads();
    for (int m = tid; m < 496; m += 256) {
        const float4* Er = (const float4*)(E + (size_t)m * 64);
        float acc[8];
#pragma unroll
        for (int nn = 0; nn < 8; nn++) acc[nn] = 0.f;
#pragma unroll
        for (int j4 = 0; j4 < 16; j4++) {
            float4 v = Er[j4];
#pragma unroll
            for (int nn = 0; nn < 8; nn++) {
                acc[nn] += v.x * tm_sh[nn][j4 * 4 + 0];
                acc[nn] += v.y * tm_sh[nn][j4 * 4 + 1];
                acc[nn] += v.z * tm_sh[nn][j4 * 4 + 2];
                acc[nn] += v.w * tm_sh[nn][j4 * 4 + 3];
            }
        }
#pragma unroll
        for (int nn = 0; nn < 8; nn++) lg[m][nn] = acc[nn];
    }
    __syncthreads();
    int wg = tid >> 5, lane = tid & 31;
    float mx = -INFINITY;
    for (int m = lane; m < 496; m += 32) mx = fmaxf(mx, lg[m][wg]);
#pragma unroll
    for (int o = 16; o; o >>= 1) mx = fmaxf(mx, __shfl_xor_sync(0xffffffffu, mx, o));
    float sum = 0.f;
    for (int m = lane; m < 496; m += 32) sum += __expf(lg[m][wg] - mx);
#pragma unroll
    for (int o = 16; o; o >>= 1) sum += __shfl_xor_sync(0xffffffffu, sum, o);
    if (lane == 0) {
        mxo[b * 512 + n0 + wg] = mx;
        ivo[b * 512 + n0 + wg] = 1.f / sum;
    }
}

// ---------------- fused Tp: recompute logits, exp, contract with Tm ----------------
__global__ __launch_bounds__(256) void tp_fused(const float* __restrict__ hs,
                                                const float* __restrict__ mxv,
                                                const float* __restrict__ ivv,
                                                float* __restrict__ Tp)
{
    extern __shared__ float sm[];
    float* sE  = sm;               // 64 x 68
    float* sTm = sm + 64 * 68;     // 64 x 68
    float* sP  = sm + 2 * 64 * 68; // 64 x 68
    int b = blockIdx.y;
    int m0 = blockIdx.x * 64;
    const float* E  = hs + (size_t)b * 496 * 64;
    const float* Tm = hs + (size_t)(16 + b) * 496 * 64;
    int tid = threadIdx.x;
    int tx = tid & 15, ty = tid >> 4;

    for (int e = tid; e < 64 * 16; e += 256) {
        int r = e >> 4, c4 = (e & 15) * 4;
        float4 v = (m0 + r < 496) ? *(const float4*)(E + (size_t)(m0 + r) * 64 + c4)
                                  : make_float4(0.f, 0.f, 0.f, 0.f);
        *(float4*)&sE[r * 68 + c4] = v;
    }

    float acc[4][4];
#pragma unroll
    for (int ii = 0; ii < 4; ii++)
#pragma unroll
        for (int dd = 0; dd < 4; dd++) acc[ii][dd] = 0.f;

    for (int n0 = 0; n0 < 496; n0 += 64) {
        for (int e = tid; e < 64 * 16; e += 256) {
            int r = e >> 4, c4 = (e & 15) * 4;
            float4 v = (n0 + r < 496) ? *(const float4*)(Tm + (size_t)(n0 + r) * 64 + c4)
                                      : make_float4(0.f, 0.f, 0.f, 0.f);
            *(float4*)&sTm[r * 68 + c4] = v;
        }
        __syncthreads();

        float s4[4][4];
#pragma unroll
        for (int ii = 0; ii < 4; ii++)
#pragma unroll
            for (int jj = 0; jj < 4; jj++) s4[ii][jj] = 0.f;
#pragma unroll
        for (int k4 = 0; k4 < 16; k4++) {
            float4 a[4], bb[4];
#pragma unroll
            for (int ii = 0; ii < 4; ii++)
                a[ii] = *(float4*)&sE[(ty * 4 + ii) * 68 + k4 * 4];
#pragma unroll
            for (int jj = 0; jj < 4; jj++)
                bb[jj] = *(float4*)&sTm[(tx * 4 + jj) * 68 + k4 * 4];
#pragma unroll
            for (int ii = 0; ii < 4; ii++)
#pragma unroll
                for (int jj = 0; jj < 4; jj++)
                    s4[ii][jj] += a[ii].x * bb[jj].x + a[ii].y * bb[jj].y
                                + a[ii].z * bb[jj].z + a[ii].w * bb[jj].w;
        }
#pragma unroll
        for (int jj = 0; jj < 4; jj++) {
            int nn = n0 + tx * 4 + jj;
            float mxn = (nn < 496) ? mxv[b * 512 + nn] : 0.f;
            float ivn = (nn < 496) ? ivv[b * 512 + nn] : 0.f;
#pragma unroll
            for (int ii = 0; ii < 4; ii++)
                sP[(ty * 4 + ii) * 68 + tx * 4 + jj] =
                    (nn < 496) ? __expf(s4[ii][jj] - mxn) * ivn : 0.f;
        }
        __syncthreads();
#pragma unroll 2
        for (int j = 0; j < 64; j++) {
            float4 bv = *(float4*)&sTm[j * 68 + tx * 4];
            float p0 = sP[(ty * 4 + 0) * 68 + j];
            float p1 = sP[(ty * 4 + 1) * 68 + j];
            float p2 = sP[(ty * 4 + 2) * 68 + j];
            float p3 = sP[(ty * 4 + 3) * 68 + j];
            acc[0][0] += p0 * bv.x; acc[0][1] += p0 * bv.y; acc[0][2] += p0 * bv.z; acc[0][3] += p0 * bv.w;
            acc[1][0] += p1 * bv.x; acc[1][1] += p1 * bv.y; acc[1][2] += p1 * bv.z; acc[1][3] += p1 * bv.w;
            acc[2][0] += p2 * bv.x; acc[2][1] += p2 * bv.y; acc[2][2] += p2 * bv.z; acc[2][3] += p2 * bv.w;
            acc[3][0] += p3 * bv.x; acc[3][1] += p3 * bv.y; acc[3][2] += p3 * bv.z; acc[3][3] += p3 * bv.w;
        }
        __syncthreads();
    }
#pragma unroll
    for (int ii = 0; ii < 4; ii++) {
        int m = m0 + ty * 4 + ii;
        if (m < 496) {
            float4 v; v.x = acc[ii][0]; v.y = acc[ii][1]; v.z = acc[ii][2]; v.w = acc[ii][3];
            *(float4*)&Tp[((size_t)b * 496 + m) * 64 + tx * 4] = v;
        }
    }
}

// ---------------- fused head ----------------
__global__ void final_kernel(const float* __restrict__ hs, const float* __restrict__ Tp,
                             const float* __restrict__ aw, const float* __restrict__ ab,
                             const float* __restrict__ l3w, const float* __restrict__ l3b,
                             const float* __restrict__ cw, const float* __restrict__ cb,
                             float* __restrict__ outp)
{
    int b = blockIdx.x;
    int tid = threadIdx.x; // 256
    const float* E   = hs + (size_t)b * 496 * 64;
    const float* Tpb = Tp + (size_t)b * 496 * 64;
    __shared__ float att[496];
    __shared__ float red[256];
    __shared__ float part[4][64];
    __shared__ float hrep[64];
    __shared__ float h2[128];
    __shared__ float aw_sh[64];
    if (tid < 64) aw_sh[tid] = aw[tid];
    __syncthreads();
    float lmax = -INFINITY;
    for (int s = tid; s < 496; s += 256) {
        const float* er = E + (size_t)s * 64;
        float acc = ab[0];
#pragma unroll
        for (int j = 0; j < 64; j++) acc += er[j] * aw_sh[j];
        att[s] = acc;
        lmax = fmaxf(lmax, acc);
    }
    red[tid] = lmax;
    __syncthreads();
    for (int o = 128; o; o >>= 1) {
        if (tid < o) red[tid] = fmaxf(red[tid], red[tid + o]);
        __syncthreads();
    }
    float mx = red[0];
    __syncthreads();
    float lsum = 0.f;
    for (int s = tid; s < 496; s += 256) {
        float e = __expf(att[s] - mx);
        att[s] = e;
        lsum += e;
    }
    red[tid] = lsum;
    __syncthreads();
    for (int o = 128; o; o >>= 1) {
        if (tid < o) red[tid] += red[tid + o];
        __syncthreads();
    }
    float inv = 1.f / red[0];
    int d = tid & 63, grp = tid >> 6;
    float acc = 0.f;
    for (int s = grp; s < 496; s += 4)
        acc += att[s] * fabsf(Tpb[(size_t)s * 64 + d] - E[(size_t)s * 64 + d]);
    part[grp][d] = acc;
    __syncthreads();
    if (tid < 64) {
        float r = (part[0][tid] + part[1][tid] + part[2][tid] + part[3][tid]) * inv;
        hrep[tid] = fmaxf(r, 0.f);
    }
    __syncthreads();
    if (tid < 128) {
        float a2 = l3b[tid];
#pragma unroll
        for (int j = 0; j < 64; j++) a2 += hrep[j] * l3w[(size_t)tid * 64 + j];
        h2[tid] = fmaxf(a2, 0.f);
    }
    __syncthreads();
    if (tid < 2) {
        float a3 = cb[tid];
#pragma unroll
        for (int j = 0; j < 128; j++) a3 += h2[j] * cw[(size_t)tid * 128 + j];
        outp[b * 2 + tid] = a3;
    }
}

// ---------------- launch ----------------
extern "C" void kernel_launch(void* const* d_in, const int* in_sizes, int n_in,
                              void* d_out, int out_size)
{
    const float* ev    = (const float*)d_in[0];
    const float* tmpl  = (const float*)d_in[1];
    const float* c1w   = (const float*)d_in[2];
    const float* c1b   = (const float*)d_in[3];
    const float* c2w   = (const float*)d_in[4];
    const float* c2b   = (const float*)d_in[5];
    const float* c3w   = (const float*)d_in[6];
    const float* c3b   = (const float*)d_in[7];
    const float* l1w   = (const float*)d_in[8];
    const float* l1b   = (const float*)d_in[9];
    const float* W_ih  = (const float*)d_in[10];
    const float* W_hh  = (const float*)d_in[11];
    const float* b_ih  = (const float*)d_in[12];
    const float* b_hh  = (const float*)d_in[13];
    const float* aw    = (const float*)d_in[14];
    const float* ab    = (const float*)d_in[15];
    const float* l3w   = (const float*)d_in[16];
    const float* l3b   = (const float*)d_in[17];
    const float* cw    = (const float*)d_in[18];
    const float* cb    = (const float*)d_in[19];
    float* outp = (float*)d_out;

    float *p_in, *p_c1, *p_c2, *p_c3, *p_pool, *p_x1, *p_gi, *p_hs, *p_Tp;
    float *p_wt2, *p_wt3, *p_mx, *p_iv;
    cudaGetSymbolAddress((void**)&p_in,   g_in);
    cudaGetSymbolAddress((void**)&p_c1,   g_c1);
    cudaGetSymbolAddress((void**)&p_c2,   g_c2);
    cudaGetSymbolAddress((void**)&p_c3,   g_c3);
    cudaGetSymbolAddress((void**)&p_pool, g_pool);
    cudaGetSymbolAddress((void**)&p_x1,   g_x1);
    cudaGetSymbolAddress((void**)&p_gi,   g_gi);
    cudaGetSymbolAddress((void**)&p_hs,   g_hs);
    cudaGetSymbolAddress((void**)&p_Tp,   g_Tp);
    cudaGetSymbolAddress((void**)&p_wt2,  g_wt2);
    cudaGetSymbolAddress((void**)&p_wt3,  g_wt3);
    cudaGetSymbolAddress((void**)&p_mx,   g_mx);
    cudaGetSymbolAddress((void**)&p_iv,   g_iv);

    const int smem2 = (3 * 2048 + 2560) * 4;        // 34,816 B (3 blocks/SM target)
    const int smem3 = (3 * 4096 + 10240) * 4;       // 90,112 B (2 blocks/SM)
    const int smemp = 5 * 58 * 67 * 4;              // 77,720 B
    const int smemt = 3 * 64 * 68 * 4;              // 52,224 B
    cudaFuncSetAttribute((const void*)conv_ring<16, 32, 508, 124, 3>,
                         cudaFuncAttributeMaxDynamicSharedMemorySize, smem2);
    cudaFuncSetAttribute((const void*)conv_ring<32, 64, 504, 120, 2>,
                         cudaFuncAttributeMaxDynamicSharedMemorySize, smem3);
    cudaFuncSetAttribute(pool_ring,
                         cudaFuncAttributeMaxDynamicSharedMemorySize, smemp);
    cudaFuncSetAttribute(tp_fused,
                         cudaFuncAttributeMaxDynamicSharedMemorySize, smemt);

    prep_kernel<<<dim3(4, 16, 33), dim3(32, 8)>>>(ev, tmpl, c2w, c3w, p_in, p_wt2, p_wt3);
    conv1_nhwc<<<dim3(508, 32), 128>>>(p_in, c1w, c1b, p_c1);
    conv_ring<16, 32, 508, 124, 3><<<dim3(252, 32), 256, smem2>>>(p_c1, p_wt2, c2b, p_c2);
    conv_ring<32, 64, 504, 120, 2><<<dim3(250, 32), 256, smem3>>>(p_c2, p_wt3, c3b, p_c3);
    pool_ring<<<dim3(8, 32), 256, smemp>>>(p_c3, p_pool);
    lin1_mma<<<124, 256>>>(p_pool, l1w, l1b, p_x1);
    gemm_bias<true><<<dim3(248, 3, 1), 128>>>(p_x1, W_ih, b_ih, p_gi,
                                              15872, 192, 64, 0, 0, 0);
    gru_kernel<<<2, 192>>>(p_gi, W_hh, b_hh, p_hs);
    attn_stats<<<dim3(62, 16), 256>>>(p_hs, p_mx, p_iv);
    tp_fused<<<dim3(8, 16), 256, smemt>>>(p_hs, p_mx, p_iv, p_Tp);
    final_kernel<<<16, 256>>>(p_hs, p_Tp, aw, ab, l3w, l3b, cw, cb, outp);
}